// round 5
// baseline (speedup 1.0000x reference)
#include <cuda_runtime.h>
#include <cstdint>

typedef unsigned long long u64;

// ---------------- scratch (device globals; no allocations allowed) ----------
__device__ float g_b1[(size_t)64*128*128*32];   // enc1 out  NHWC [64,128,128,32]
__device__ float g_b2[(size_t)64*64*64*64];     // enc2 out  NHWC [64,64,64,64]
__device__ float g_q [(size_t)64*64*64*16];     // quantized NHWC [64,64,64,16]
__device__ float g_d1[(size_t)64*128*128*64];   // dec1 out  NHWC [64,128,128,64]
__device__ float g_d2[(size_t)64*256*256*32];   // dec2 out  NHWC [64,256,256,32]

__device__ float g_wr1 [864];     // enc1 w  [kh][kw][ci=3][co=32]
__device__ float g_wr2 [18432];   // enc2 w  [kh][kw][ci=32][co=64]
__device__ float g_wrd1[9216];    // dec1 w  [kh][kw][ci=16][co=64]
__device__ float g_wrd2[18432];   // dec2 w  [kh][kw][ci=64][co=32]
__device__ float g_wrd3[864];     // dec3 w  [kh][kw][ci=32][co=3] (pre-flipped)
__device__ double g_acc[2];       // [0]=vq sq-sum, [1]=recon sq-sum

// ---------------- f32x2 helpers ---------------------------------------------
__device__ __forceinline__ u64 pack2(float lo, float hi){
  u64 r; asm("mov.b64 %0, {%1, %2};" : "=l"(r)
             : "r"(__float_as_uint(lo)), "r"(__float_as_uint(hi)));
  return r;
}
__device__ __forceinline__ u64 bcast2(float v){
  u64 r; asm("mov.b64 %0, {%1, %1};" : "=l"(r) : "r"(__float_as_uint(v)));
  return r;
}
__device__ __forceinline__ float2 unpack2(u64 p){
  unsigned lo, hi;
  asm("mov.b64 {%0, %1}, %2;" : "=r"(lo), "=r"(hi) : "l"(p));
  return make_float2(__uint_as_float(lo), __uint_as_float(hi));
}
__device__ __forceinline__ void ffma2(u64 &acc, u64 a, u64 b){
  asm("fma.rn.f32x2 %0, %1, %2, %0;" : "+l"(acc) : "l"(a), "l"(b));
}
__device__ __forceinline__ float4 zero4(){ float4 z; z.x=z.y=z.z=z.w=0.f; return z; }

__device__ __forceinline__ float blockReduceSum(float v){
  __shared__ float red[32];
  #pragma unroll
  for (int o=16;o;o>>=1) v += __shfl_down_sync(0xffffffffu, v, o);
  int lane = threadIdx.x & 31, w = threadIdx.x >> 5;
  if (lane==0) red[w]=v;
  __syncthreads();
  if (w==0){
    v = (lane < ((int)blockDim.x>>5)) ? red[lane] : 0.f;
    #pragma unroll
    for (int o=16;o;o>>=1) v += __shfl_down_sync(0xffffffffu, v, o);
  }
  return v;
}

// ---------------- weight repack + accumulator reset -------------------------
__global__ void repack_k(const float* __restrict__ ew1, const float* __restrict__ ew2,
                         const float* __restrict__ dw1, const float* __restrict__ dw2,
                         const float* __restrict__ dw3){
  int t = blockIdx.x*blockDim.x + threadIdx.x;
  int nt = gridDim.x*blockDim.x;
  if (blockIdx.x==0 && threadIdx.x<2) g_acc[threadIdx.x]=0.0;
  for (int i=t;i<864;i+=nt){ int co=i%32; int r=i/32; int ci=r%3; r/=3; int kw=r%3, kh=r/3;
    g_wr1[i] = ew1[((co*3+ci)*3+kh)*3+kw]; }
  for (int i=t;i<18432;i+=nt){ int co=i&63; int r=i>>6; int ci=r%32; r/=32; int kw=r%3, kh=r/3;
    g_wr2[i] = ew2[((co*32+ci)*3+kh)*3+kw]; }
  for (int i=t;i<9216;i+=nt){ int co=i&63; int r=i>>6; int ci=r%16; r/=16; int kw=r%3, kh=r/3;
    g_wrd1[i] = dw1[((ci*64+co)*3+kh)*3+kw]; }
  for (int i=t;i<18432;i+=nt){ int co=i&31; int r=i>>5; int ci=r%64; r/=64; int kw=r%3, kh=r/3;
    g_wrd2[i] = dw2[((ci*32+co)*3+kh)*3+kw]; }
  for (int i=t;i<864;i+=nt){ int co=i%3; int r=i/3; int ci=r%32; r/=32; int kw=r%3, kh=r/3;
    g_wrd3[i] = dw3[((ci*3+co)*3+(2-kh))*3+(2-kw)]; }
}

// ---------------- enc1: 3->32, k3 s2 p1, relu; 2 pixels/thread (R3 form) ----
__global__ __launch_bounds__(256) void enc1_k(const float* __restrict__ x,
                                              const float* __restrict__ bias){
  __shared__ __align__(16) float ws[864];
  __shared__ float bs[32];
  int tid = threadIdx.x;
  for (int i=tid;i<864;i+=256) ws[i]=g_wr1[i];
  if (tid<32) bs[tid]=bias[tid];
  __syncthreads();
  int idx = blockIdx.x*256 + tid;                 // [0, 524288)
  int tw = idx & 63, ho = (idx>>6)&127, b = idx>>13;
  u64 acc[2][16];
  #pragma unroll
  for (int c=0;c<16;c++){ acc[0][c]=pack2(bs[2*c],bs[2*c+1]); acc[1][c]=acc[0][c]; }
  const float* xb = x + (size_t)b*3*65536;
  for (int kh=0;kh<3;kh++){
    int hi = 2*ho-1+kh; bool inh = (unsigned)hi<256u;
    for (int kw=0;kw<3;kw++){
      int wi0 = 4*tw-1+kw, wi1 = wi0+2;
      bool in0 = inh && (unsigned)wi0<256u;
      bool in1 = inh && (unsigned)wi1<256u;
      #pragma unroll
      for (int ci=0;ci<3;ci++){
        float f0 = in0 ? xb[(size_t)ci*65536 + hi*256 + wi0] : 0.f;
        float f1 = in1 ? xb[(size_t)ci*65536 + hi*256 + wi1] : 0.f;
        u64 v0=bcast2(f0), v1=bcast2(f1);
        const ulonglong2* wp = (const ulonglong2*)&ws[((kh*3+kw)*3+ci)*32];
        #pragma unroll
        for (int q=0;q<8;q++){
          ulonglong2 t=wp[q];
          ffma2(acc[0][2*q],v0,t.x); ffma2(acc[0][2*q+1],v0,t.y);
          ffma2(acc[1][2*q],v1,t.x); ffma2(acc[1][2*q+1],v1,t.y);
        }
      }
    }
  }
  float4* op = (float4*)(g_b1 + (size_t)(2*idx)*32);
  #pragma unroll
  for (int p=0;p<2;p++)
  #pragma unroll
  for (int c4=0;c4<8;c4++){
    float2 a=unpack2(acc[p][2*c4]), b2=unpack2(acc[p][2*c4+1]);
    float4 o; o.x=fmaxf(a.x,0.f); o.y=fmaxf(a.y,0.f); o.z=fmaxf(b2.x,0.f); o.w=fmaxf(b2.y,0.f);
    op[p*8+c4]=o;
  }
}

// -------- enc2: 32->64, k3 s2 p1, relu; 2 px/thread, co halves(grid) + 16-chunks(thread)
__global__ __launch_bounds__(256) void enc2_k(const float* __restrict__ bias){
  __shared__ __align__(16) float ws[9216];   // [tap][ci=32][co_local=32]
  __shared__ float bs[32];
  int half = blockIdx.y;
  int tid = threadIdx.x;
  for (int i=tid;i<9216;i+=256){
    int c = i & 31; int r = i >> 5;
    ws[i] = g_wr2[r*64 + half*32 + c];
  }
  if (tid<32) bs[tid]=bias[half*32+tid];
  __syncthreads();
  int idx = blockIdx.x*256 + tid;                 // [0, 131072)
  int tw = idx & 31, ho = (idx>>5)&63, b = idx>>11;
  #pragma unroll
  for (int s=0;s<2;s++){                          // 16-co chunk within the 32-co half
    u64 acc[2][8];
    #pragma unroll
    for (int c=0;c<8;c++){ acc[0][c]=pack2(bs[s*16+2*c],bs[s*16+2*c+1]); acc[1][c]=acc[0][c]; }
    for (int kh=0;kh<3;kh++){
      int hi = 2*ho-1+kh; bool inh = (unsigned)hi<128u;
      for (int kw=0;kw<3;kw++){
        int wi0 = 4*tw-1+kw, wi1 = wi0+2;
        bool in0 = inh && (unsigned)wi0<128u;
        bool in1 = inh && (unsigned)wi1<128u;
        const float4* ip0 = (const float4*)(g_b1 + ((size_t)((b*128+hi)*128+wi0))*32);
        const float4* ip1 = ip0 + 16;   // wi1 = wi0+2 -> +64 floats
        const float* wt = &ws[(kh*3+kw)*1024 + s*16];
        #pragma unroll 4
        for (int ci4=0;ci4<8;ci4++){
          float4 v0 = in0 ? ip0[ci4] : zero4();
          float4 v1 = in1 ? ip1[ci4] : zero4();
          float A0[4]={v0.x,v0.y,v0.z,v0.w}, A1[4]={v1.x,v1.y,v1.z,v1.w};
          #pragma unroll
          for (int j=0;j<4;j++){
            u64 p0=bcast2(A0[j]), p1=bcast2(A1[j]);
            const ulonglong2* wp = (const ulonglong2*)(wt + (ci4*4+j)*32);
            #pragma unroll
            for (int q=0;q<4;q++){
              ulonglong2 t=wp[q];
              ffma2(acc[0][2*q],p0,t.x); ffma2(acc[0][2*q+1],p0,t.y);
              ffma2(acc[1][2*q],p1,t.x); ffma2(acc[1][2*q+1],p1,t.y);
            }
          }
        }
      }
    }
    #pragma unroll
    for (int p=0;p<2;p++){
      float4* op = (float4*)(g_b2 + (size_t)(2*idx+p)*64 + half*32 + s*16);
      #pragma unroll
      for (int c4=0;c4<4;c4++){
        float2 a=unpack2(acc[p][2*c4]), b2=unpack2(acc[p][2*c4+1]);
        float4 o; o.x=fmaxf(a.x,0.f); o.y=fmaxf(a.y,0.f); o.z=fmaxf(b2.x,0.f); o.w=fmaxf(b2.y,0.f);
        op[c4]=o;
      }
    }
  }
}

// ------------- enc3 (1x1 64->16) + VQ + quantize + VQ loss; 2 px/thread -----
__global__ __launch_bounds__(256) void vq_k(const float* __restrict__ cb,
                                            const float* __restrict__ w3,
                                            const float* __restrict__ b3){
  __shared__ __align__(16) float cbs[8192];   // [512][16]
  __shared__ float nrm[512];                   // 0.5*||e||^2
  __shared__ __align__(16) float w3s[1024];    // [ci=64][d=16]
  __shared__ float b3s[16];
  int tid = threadIdx.x;
  for (int i=tid;i<8192;i+=256) cbs[i]=cb[i];
  for (int i=tid;i<1024;i+=256){ int ci=i>>4, d=i&15; w3s[i]=w3[d*64+ci]; }
  if (tid<16) b3s[tid]=b3[tid];
  __syncthreads();
  for (int k=tid;k<512;k+=256){
    float s=0.f;
    #pragma unroll
    for (int d=0;d<16;d++){ float e=cbs[k*16+d]; s=fmaf(e,e,s); }
    nrm[k]=0.5f*s;
  }
  __syncthreads();
  int idx = blockIdx.x*256 + tid;                 // [0, 131072)
  u64 z2[2][8];
  #pragma unroll
  for (int q=0;q<8;q++){ z2[0][q]=pack2(b3s[2*q],b3s[2*q+1]); z2[1][q]=z2[0][q]; }
  const float4* ip0 = (const float4*)(g_b2 + (size_t)(2*idx)*64);
  const float4* ip1 = ip0 + 16;
  #pragma unroll 4
  for (int ci4=0;ci4<16;ci4++){
    float4 v0 = ip0[ci4], v1 = ip1[ci4];
    float a[4]={v0.x,v0.y,v0.z,v0.w}, bb[4]={v1.x,v1.y,v1.z,v1.w};
    #pragma unroll
    for (int j=0;j<4;j++){
      u64 vb0 = bcast2(a[j]), vb1 = bcast2(bb[j]);
      const ulonglong2* wp = (const ulonglong2*)&w3s[(ci4*4+j)*16];
      #pragma unroll
      for (int q=0;q<4;q++){ ulonglong2 t=wp[q];
        ffma2(z2[0][2*q],vb0,t.x); ffma2(z2[0][2*q+1],vb0,t.y);
        ffma2(z2[1][2*q],vb1,t.x); ffma2(z2[1][2*q+1],vb1,t.y); }
    }
  }
  int best0=0, best1=0; float bs0=-3.4e38f, bs1=-3.4e38f;
  for (int k=0;k<512;k++){
    const ulonglong2* e2 = (const ulonglong2*)&cbs[k*16];
    ulonglong2 t0=e2[0], t1=e2[1], t2=e2[2], t3=e2[3];
    u64 sa0=0ull, sb0=0ull, sa1=0ull, sb1=0ull;   // 4 independent chains
    ffma2(sa0,z2[0][0],t0.x); ffma2(sb0,z2[0][4],t2.x);
    ffma2(sa1,z2[1][0],t0.x); ffma2(sb1,z2[1][4],t2.x);
    ffma2(sa0,z2[0][1],t0.y); ffma2(sb0,z2[0][5],t2.y);
    ffma2(sa1,z2[1][1],t0.y); ffma2(sb1,z2[1][5],t2.y);
    ffma2(sa0,z2[0][2],t1.x); ffma2(sb0,z2[0][6],t3.x);
    ffma2(sa1,z2[1][2],t1.x); ffma2(sb1,z2[1][6],t3.x);
    ffma2(sa0,z2[0][3],t1.y); ffma2(sb0,z2[0][7],t3.y);
    ffma2(sa1,z2[1][3],t1.y); ffma2(sb1,z2[1][7],t3.y);
    float2 pa0=unpack2(sa0), pb0=unpack2(sb0);
    float2 pa1=unpack2(sa1), pb1=unpack2(sb1);
    float nk = nrm[k];
    float s0 = (pa0.x + pa0.y) + (pb0.x + pb0.y) - nk;
    float s1 = (pa1.x + pa1.y) + (pb1.x + pb1.y) - nk;
    if (s0>bs0){ bs0=s0; best0=k; }
    if (s1>bs1){ bs1=s1; best1=k; }
  }
  float ls=0.f;
  int bests[2]={best0,best1};
  #pragma unroll
  for (int p=0;p<2;p++){
    const float* e = &cbs[bests[p]*16];
    float4* qo = (float4*)(g_q + (size_t)(2*idx+p)*16);
    #pragma unroll
    for (int d4=0;d4<4;d4++){
      float4 o; o.x=e[d4*4+0]; o.y=e[d4*4+1]; o.z=e[d4*4+2]; o.w=e[d4*4+3];
      qo[d4]=o;
      float2 za=unpack2(z2[p][d4*2]), zb=unpack2(z2[p][d4*2+1]);
      float d0=o.x-za.x, d1=o.y-za.y, d2=o.z-zb.x, d3=o.w-zb.y;
      ls = fmaf(d0,d0, fmaf(d1,d1, fmaf(d2,d2, fmaf(d3,d3, ls))));
    }
  }
  float s = blockReduceSum(ls);
  if (tid==0) atomicAdd(&g_acc[0], (double)s);
}

// --- dec1: convT 16->64 k3 s2 p1 op1, relu; parity + co halves(grid) + 16-chunks(thread)
template<int PH,int PW>
__global__ __launch_bounds__(256) void dec1_k(const float* __restrict__ bias){
  constexpr int NKH = PH?2:1, NKW = PW?2:1;
  __shared__ __align__(16) float ws[NKH*NKW*512];  // [tap][ci=16][co_half=32]
  __shared__ float bs[32];
  int half = blockIdx.y;
  int tid = threadIdx.x;
  for (int i=tid;i<NKH*NKW*512;i+=256){
    int j = i & 511; int t = i >> 9;
    int a = t / NKW, c = t % NKW;
    int kh = PH ? a*2 : 1;
    int kw = PW ? c*2 : 1;
    ws[i] = g_wrd1[(kh*3+kw)*1024 + (j>>5)*64 + half*32 + (j&31)];
  }
  if (tid<32) bs[tid]=bias[half*32+tid];
  __syncthreads();
  int idx = blockIdx.x*256 + tid;                 // [0, 131072)
  int tw = idx & 31, hb = (idx>>5)&63, b = idx>>11;
  int wb0 = 2*tw;
  int ho = 2*hb+PH, wo0 = 2*wb0+PW;
  #pragma unroll
  for (int s=0;s<2;s++){                          // 16-co chunk within the half
    u64 acc[2][8];
    #pragma unroll
    for (int c=0;c<8;c++){ acc[0][c]=pack2(bs[s*16+2*c],bs[s*16+2*c+1]); acc[1][c]=acc[0][c]; }
    #pragma unroll
    for (int a=0;a<NKH;a++){
      int hi = PH ? (a==0 ? hb+1 : hb) : hb;
      bool inh = PH ? (hi<64) : true;
      #pragma unroll
      for (int cc=0;cc<NKW;cc++){
        int wi0 = PW ? (cc==0 ? wb0+1 : wb0) : wb0;
        int wi1 = wi0+1;
        bool in0 = inh;
        bool in1 = inh && (wi1<64);
        const float4* ip0 = (const float4*)(g_q + ((size_t)((b*64+hi)*64+wi0))*16);
        const float4* ip1 = ip0 + 4;
        const float* wt = &ws[(a*NKW+cc)*512 + s*16];
        #pragma unroll
        for (int ci4=0;ci4<4;ci4++){
          float4 v0 = in0 ? ip0[ci4] : zero4();
          float4 v1 = in1 ? ip1[ci4] : zero4();
          float A0[4]={v0.x,v0.y,v0.z,v0.w}, A1[4]={v1.x,v1.y,v1.z,v1.w};
          #pragma unroll
          for (int j=0;j<4;j++){
            u64 p0 = bcast2(A0[j]), p1 = bcast2(A1[j]);
            const ulonglong2* wp = (const ulonglong2*)(wt + (ci4*4+j)*32);
            #pragma unroll
            for (int q=0;q<4;q++){
              ulonglong2 t3=wp[q];
              ffma2(acc[0][2*q],p0,t3.x); ffma2(acc[0][2*q+1],p0,t3.y);
              ffma2(acc[1][2*q],p1,t3.x); ffma2(acc[1][2*q+1],p1,t3.y);
            }
          }
        }
      }
    }
    #pragma unroll
    for (int p=0;p<2;p++){
      int wo = wo0 + 2*p;
      float4* op = (float4*)(g_d1 + ((size_t)((b*128+ho)*128+wo))*64 + half*32 + s*16);
      #pragma unroll
      for (int c4=0;c4<4;c4++){
        float2 a2=unpack2(acc[p][2*c4]), b2=unpack2(acc[p][2*c4+1]);
        float4 o; o.x=fmaxf(a2.x,0.f); o.y=fmaxf(a2.y,0.f); o.z=fmaxf(b2.x,0.f); o.w=fmaxf(b2.y,0.f);
        op[c4]=o;
      }
    }
  }
}

// --- dec2: convT 64->32 k3 s2 p1 op1, relu; parity + 2px + 16-co chunks(thread)
template<int PH,int PW>
__global__ __launch_bounds__(256) void dec2_k(const float* __restrict__ bias){
  constexpr int NKH = PH?2:1, NKW = PW?2:1;
  __shared__ __align__(16) float ws[NKH*NKW*2048];   // [tap][ci=64][co=32]
  __shared__ float bs[32];
  int tid = threadIdx.x;
  for (int i=tid;i<NKH*NKW*2048;i+=256){
    int j = i & 2047; int t = i >> 11;
    int a = t / NKW, c = t % NKW;
    int kh = PH ? a*2 : 1;
    int kw = PW ? c*2 : 1;
    ws[i] = g_wrd2[(kh*3+kw)*2048 + j];
  }
  if (tid<32) bs[tid]=bias[tid];
  __syncthreads();
  int idx = blockIdx.x*256 + tid;                 // [0, 524288)
  int tw = idx & 63, hb = (idx>>6)&127, b = idx>>13;
  int wb0 = 2*tw;
  int ho = 2*hb+PH, wo0 = 2*wb0+PW;
  #pragma unroll
  for (int s=0;s<2;s++){                          // 16-co chunk of the 32 co
    u64 acc[2][8];
    #pragma unroll
    for (int c=0;c<8;c++){ acc[0][c]=pack2(bs[s*16+2*c],bs[s*16+2*c+1]); acc[1][c]=acc[0][c]; }
    #pragma unroll
    for (int a=0;a<NKH;a++){
      int hi = PH ? (a==0 ? hb+1 : hb) : hb;
      bool inh = PH ? (hi<128) : true;
      #pragma unroll
      for (int cc=0;cc<NKW;cc++){
        int wi0 = PW ? (cc==0 ? wb0+1 : wb0) : wb0;
        int wi1 = wi0+1;
        bool in0 = inh;
        bool in1 = inh && (wi1<128);
        const float4* ip0 = (const float4*)(g_d1 + ((size_t)((b*128+hi)*128+wi0))*64);
        const float4* ip1 = ip0 + 16;
        const float* wt = &ws[(a*NKW+cc)*2048 + s*16];
        #pragma unroll 4
        for (int ci4=0;ci4<16;ci4++){
          float4 v0 = in0 ? ip0[ci4] : zero4();
          float4 v1 = in1 ? ip1[ci4] : zero4();
          float A0[4]={v0.x,v0.y,v0.z,v0.w}, A1[4]={v1.x,v1.y,v1.z,v1.w};
          #pragma unroll
          for (int j=0;j<4;j++){
            u64 p0=bcast2(A0[j]), p1=bcast2(A1[j]);
            const ulonglong2* wp = (const ulonglong2*)(wt + (ci4*4+j)*32);
            #pragma unroll
            for (int q=0;q<4;q++){
              ulonglong2 t=wp[q];
              ffma2(acc[0][2*q],p0,t.x); ffma2(acc[0][2*q+1],p0,t.y);
              ffma2(acc[1][2*q],p1,t.x); ffma2(acc[1][2*q+1],p1,t.y);
            }
          }
        }
      }
    }
    #pragma unroll
    for (int p=0;p<2;p++){
      int wo = wo0 + 2*p;
      float4* op = (float4*)(g_d2 + ((size_t)((b*256+ho)*256+wo))*32 + s*16);
      #pragma unroll
      for (int c4=0;c4<4;c4++){
        float2 a2=unpack2(acc[p][2*c4]), b2=unpack2(acc[p][2*c4+1]);
        float4 o; o.x=fmaxf(a2.x,0.f); o.y=fmaxf(a2.y,0.f); o.z=fmaxf(b2.x,0.f); o.w=fmaxf(b2.y,0.f);
        op[c4]=o;
      }
    }
  }
}

// ------------- dec3: convT 32->3 k3 s1 p1 + recon MSE (fused, no store) -----
#define COMPSEL(v,c) ((c)==0 ? (v).x : (c)==1 ? (v).y : (c)==2 ? (v).z : (v).w)
__global__ __launch_bounds__(256) void dec3_k(const float* __restrict__ x,
                                              const float* __restrict__ bias){
  __shared__ __align__(16) u64 ws2[864];    // [kh][kw][ci=32][co=3], dup-pair {w,w}
  __shared__ float bs[3];
  int tid = threadIdx.x;
  for (int i=tid;i<864;i+=256){ float w=g_wrd3[i]; ws2[i]=pack2(w,w); }
  if (tid<3) bs[tid]=bias[tid];
  __syncthreads();
  int idx = blockIdx.x*256 + tid;                 // 64*256*64 (4 pixels/thread in w)
  int tw = idx & 63, ho = (idx>>6)&255, b = idx>>14;
  int wo0 = tw*4;
  u64 accp[3][2];   // [co][pixel-pair]
  #pragma unroll
  for (int co=0;co<3;co++){ accp[co][0]=pack2(bs[co],bs[co]); accp[co][1]=accp[co][0]; }
  for (int kh=0;kh<3;kh++){
    int hi = ho-1+kh; if ((unsigned)hi>=256u) continue;
    const float* rowp = g_d2 + ((size_t)(b*256+hi))*256*32;
    #pragma unroll 2
    for (int ci4=0;ci4<8;ci4++){
      float4 v[6];
      #pragma unroll
      for (int j=0;j<6;j++){
        int wi = wo0-1+j;
        if ((unsigned)wi<256u) v[j] = ((const float4*)(rowp + (size_t)wi*32))[ci4];
        else v[j] = zero4();
      }
      #pragma unroll
      for (int kw=0;kw<3;kw++){
        #pragma unroll
        for (int c=0;c<4;c++){
          float f0=COMPSEL(v[kw+0],c), f1=COMPSEL(v[kw+1],c);
          float f2=COMPSEL(v[kw+2],c), f3=COMPSEL(v[kw+3],c);
          u64 a0=pack2(f0,f1), a1=pack2(f2,f3);
          const u64* wd = &ws2[((kh*3+kw)*32 + ci4*4 + c)*3];
          u64 w0=wd[0], w1=wd[1], w2=wd[2];
          ffma2(accp[0][0],a0,w0); ffma2(accp[0][1],a1,w0);
          ffma2(accp[1][0],a0,w1); ffma2(accp[1][1],a1,w1);
          ffma2(accp[2][0],a0,w2); ffma2(accp[2][1],a1,w2);
        }
      }
    }
  }
  float acc[4][3];
  #pragma unroll
  for (int co=0;co<3;co++){
    float2 p0=unpack2(accp[co][0]), p1=unpack2(accp[co][1]);
    acc[0][co]=p0.x; acc[1][co]=p0.y; acc[2][co]=p1.x; acc[3][co]=p1.y;
  }
  float ls=0.f;
  const float* xb = x + (size_t)b*3*65536;
  #pragma unroll
  for (int o=0;o<4;o++){
    #pragma unroll
    for (int c=0;c<3;c++){
      float d = acc[o][c] - xb[(size_t)c*65536 + ho*256 + wo0+o];
      ls = fmaf(d,d,ls);
    }
  }
  float s = blockReduceSum(ls);
  if (tid==0) atomicAdd(&g_acc[1], (double)s);
}

// ------------- finalize -----------------------------------------------------
__global__ void final_k(float* __restrict__ out){
  double vq  = g_acc[0];
  double rec = g_acc[1];
  float e_q  = (float)(1.25 * vq / 4194304.0);
  float mse  = (float)(rec / 12582912.0);
  out[0] = e_q;
  out[1] = mse;
  out[2] = mse;
}

// ---------------- launch ----------------------------------------------------
extern "C" void kernel_launch(void* const* d_in, const int* in_sizes, int n_in,
                              void* d_out, int out_size){
  const float* x   = (const float*)d_in[0];
  const float* ew1 = (const float*)d_in[1];
  const float* eb1 = (const float*)d_in[2];
  const float* ew2 = (const float*)d_in[3];
  const float* eb2 = (const float*)d_in[4];
  const float* ew3 = (const float*)d_in[5];
  const float* eb3 = (const float*)d_in[6];
  const float* cb  = (const float*)d_in[7];
  const float* dw1 = (const float*)d_in[8];
  const float* db1 = (const float*)d_in[9];
  const float* dw2 = (const float*)d_in[10];
  const float* db2 = (const float*)d_in[11];
  const float* dw3 = (const float*)d_in[12];
  const float* db3 = (const float*)d_in[13];
  float* out = (float*)d_out;

  repack_k<<<64,256>>>(ew1, ew2, dw1, dw2, dw3);
  enc1_k<<<2048,256>>>(x, eb1);
  enc2_k<<<dim3(512,2),256>>>(eb2);
  vq_k<<<512,256>>>(cb, ew3, eb3);
  dec1_k<0,0><<<dim3(512,2),256>>>(db1);
  dec1_k<0,1><<<dim3(512,2),256>>>(db1);
  dec1_k<1,0><<<dim3(512,2),256>>>(db1);
  dec1_k<1,1><<<dim3(512,2),256>>>(db1);
  dec2_k<0,0><<<2048,256>>>(db2);
  dec2_k<0,1><<<2048,256>>>(db2);
  dec2_k<1,0><<<2048,256>>>(db2);
  dec2_k<1,1><<<2048,256>>>(db2);
  dec3_k<<<4096,256>>>(x, db3);
  final_k<<<1,1>>>(out);
}

// round 6
// speedup vs baseline: 1.8750x; 1.8750x over previous
#include <cuda_runtime.h>
#include <cuda_bf16.h>
#include <cstdint>

typedef unsigned long long u64;
typedef unsigned int u32;

// ---------------- scratch (device globals; no allocations allowed) ----------
__device__ float g_b1[(size_t)64*128*128*32];       // enc1 out  NHWC
__device__ float g_b2[(size_t)64*64*64*64];         // enc2 out  NHWC
__device__ float g_q [(size_t)64*64*64*16];         // quantized NHWC
__device__ unsigned short g_d1h[(size_t)64*128*128*64]; // dec1 out NHWC bf16
__device__ float g_d2[(size_t)64*256*256*32];       // dec2 out  NHWC fp32

__device__ float g_wr1 [864];     // enc1 w  [kh][kw][ci=3][co=32]
__device__ float g_wr2 [18432];   // enc2 w  [kh][kw][ci=32][co=64]
__device__ float g_wrd1[9216];    // dec1 w  [kh][kw][ci=16][co=64]
__device__ u32   g_wfrag[9216];   // dec2 w  B-fragments [tap9][kt4][nt4][lane32][reg2] bf16x2
__device__ float g_wrd3[864];     // dec3 w  [kh][kw][ci=32][co=3] (pre-flipped)
__device__ double g_acc[2];       // [0]=vq sq-sum, [1]=recon sq-sum

// ---------------- helpers ----------------------------------------------------
__device__ __forceinline__ u64 pack2(float lo, float hi){
  u64 r; asm("mov.b64 %0, {%1, %2};" : "=l"(r)
             : "r"(__float_as_uint(lo)), "r"(__float_as_uint(hi)));
  return r;
}
__device__ __forceinline__ u64 bcast2(float v){
  u64 r; asm("mov.b64 %0, {%1, %1};" : "=l"(r) : "r"(__float_as_uint(v)));
  return r;
}
__device__ __forceinline__ float2 unpack2(u64 p){
  unsigned lo, hi;
  asm("mov.b64 {%0, %1}, %2;" : "=r"(lo), "=r"(hi) : "l"(p));
  return make_float2(__uint_as_float(lo), __uint_as_float(hi));
}
__device__ __forceinline__ void ffma2(u64 &acc, u64 a, u64 b){
  asm("fma.rn.f32x2 %0, %1, %2, %0;" : "+l"(acc) : "l"(a), "l"(b));
}
__device__ __forceinline__ float4 zero4(){ float4 z; z.x=z.y=z.z=z.w=0.f; return z; }
// pack {lo,hi} floats -> bf16x2 (lo in bits[15:0])
__device__ __forceinline__ u32 bfpack(float lo, float hi){
  u32 r; asm("cvt.rn.bf16x2.f32 %0, %1, %2;" : "=r"(r) : "f"(hi), "f"(lo));
  return r;
}
__device__ __forceinline__ u32 smem_u32(const void* p){
  u32 a; asm("{ .reg .u64 t; cvta.to.shared.u64 t, %1; cvt.u32.u64 %0, t; }"
             : "=r"(a) : "l"(p));
  return a;
}

__device__ __forceinline__ float blockReduceSum(float v){
  __shared__ float red[32];
  #pragma unroll
  for (int o=16;o;o>>=1) v += __shfl_down_sync(0xffffffffu, v, o);
  int lane = threadIdx.x & 31, w = threadIdx.x >> 5;
  if (lane==0) red[w]=v;
  __syncthreads();
  if (w==0){
    v = (lane < ((int)blockDim.x>>5)) ? red[lane] : 0.f;
    #pragma unroll
    for (int o=16;o;o>>=1) v += __shfl_down_sync(0xffffffffu, v, o);
  }
  return v;
}

// ---------------- weight repack + accumulator reset -------------------------
__global__ void repack_k(const float* __restrict__ ew1, const float* __restrict__ ew2,
                         const float* __restrict__ dw1, const float* __restrict__ dw2,
                         const float* __restrict__ dw3){
  int t = blockIdx.x*blockDim.x + threadIdx.x;
  int nt = gridDim.x*blockDim.x;
  if (blockIdx.x==0 && threadIdx.x<2) g_acc[threadIdx.x]=0.0;
  for (int i=t;i<864;i+=nt){ int co=i%32; int r=i/32; int ci=r%3; r/=3; int kw=r%3, kh=r/3;
    g_wr1[i] = ew1[((co*3+ci)*3+kh)*3+kw]; }
  for (int i=t;i<18432;i+=nt){ int co=i&63; int r=i>>6; int ci=r%32; r/=32; int kw=r%3, kh=r/3;
    g_wr2[i] = ew2[((co*32+ci)*3+kh)*3+kw]; }
  for (int i=t;i<9216;i+=nt){ int co=i&63; int r=i>>6; int ci=r%16; r/=16; int kw=r%3, kh=r/3;
    g_wrd1[i] = dw1[((ci*64+co)*3+kh)*3+kw]; }
  // dec2 bf16 B-fragments: flat = tap*1024 + kt*256 + ntile*64 + lane*2 + reg
  for (int i=t;i<9216;i+=nt){
    int tap = i>>10; int w_ = i & 1023;
    int reg = w_ & 1; int lane = (w_>>1)&31; int ntv = (w_>>6)&3; int kt = (w_>>8)&3;
    int kh = tap/3, kw = tap%3;
    int gg = lane>>2, tg = lane&3;
    int co = ntv*8+gg;
    int ci0 = kt*16 + 2*tg + (reg?8:0);
    float w0 = dw2[((ci0*32+co)*3+kh)*3+kw];
    float w1 = dw2[(((ci0+1)*32+co)*3+kh)*3+kw];
    unsigned short h0 = __bfloat16_as_ushort(__float2bfloat16(w0));
    unsigned short h1 = __bfloat16_as_ushort(__float2bfloat16(w1));
    g_wfrag[i] = (u32)h0 | ((u32)h1<<16);
  }
  for (int i=t;i<864;i+=nt){ int co=i%3; int r=i/3; int ci=r%32; r/=32; int kw=r%3, kh=r/3;
    g_wrd3[i] = dw3[((ci*3+co)*3+(2-kh))*3+(2-kw)]; }
}

// ---------------- enc1: 3->32, k3 s2 p1, relu; 2 pixels/thread (R3) ---------
__global__ __launch_bounds__(256) void enc1_k(const float* __restrict__ x,
                                              const float* __restrict__ bias){
  __shared__ __align__(16) float ws[864];
  __shared__ float bs[32];
  int tid = threadIdx.x;
  for (int i=tid;i<864;i+=256) ws[i]=g_wr1[i];
  if (tid<32) bs[tid]=bias[tid];
  __syncthreads();
  int idx = blockIdx.x*256 + tid;
  int tw = idx & 63, ho = (idx>>6)&127, b = idx>>13;
  u64 acc[2][16];
  #pragma unroll
  for (int c=0;c<16;c++){ acc[0][c]=pack2(bs[2*c],bs[2*c+1]); acc[1][c]=acc[0][c]; }
  const float* xb = x + (size_t)b*3*65536;
  for (int kh=0;kh<3;kh++){
    int hi = 2*ho-1+kh; bool inh = (unsigned)hi<256u;
    for (int kw=0;kw<3;kw++){
      int wi0 = 4*tw-1+kw, wi1 = wi0+2;
      bool in0 = inh && (unsigned)wi0<256u;
      bool in1 = inh && (unsigned)wi1<256u;
      #pragma unroll
      for (int ci=0;ci<3;ci++){
        float f0 = in0 ? xb[(size_t)ci*65536 + hi*256 + wi0] : 0.f;
        float f1 = in1 ? xb[(size_t)ci*65536 + hi*256 + wi1] : 0.f;
        u64 v0=bcast2(f0), v1=bcast2(f1);
        const ulonglong2* wp = (const ulonglong2*)&ws[((kh*3+kw)*3+ci)*32];
        #pragma unroll
        for (int q=0;q<8;q++){
          ulonglong2 t=wp[q];
          ffma2(acc[0][2*q],v0,t.x); ffma2(acc[0][2*q+1],v0,t.y);
          ffma2(acc[1][2*q],v1,t.x); ffma2(acc[1][2*q+1],v1,t.y);
        }
      }
    }
  }
  float4* op = (float4*)(g_b1 + (size_t)(2*idx)*32);
  #pragma unroll
  for (int p=0;p<2;p++)
  #pragma unroll
  for (int c4=0;c4<8;c4++){
    float2 a=unpack2(acc[p][2*c4]), b2=unpack2(acc[p][2*c4+1]);
    float4 o; o.x=fmaxf(a.x,0.f); o.y=fmaxf(a.y,0.f); o.z=fmaxf(b2.x,0.f); o.w=fmaxf(b2.y,0.f);
    op[p*8+c4]=o;
  }
}

// ---------------- enc2: 32->64, k3 s2 p1, relu; 2 px/thread, co halves (R3) -
__global__ __launch_bounds__(256) void enc2_k(const float* __restrict__ bias){
  __shared__ __align__(16) float ws[9216];
  __shared__ float bs[32];
  int half = blockIdx.y;
  int tid = threadIdx.x;
  for (int i=tid;i<9216;i+=256){
    int c = i & 31; int r = i >> 5;
    ws[i] = g_wr2[r*64 + half*32 + c];
  }
  if (tid<32) bs[tid]=bias[half*32+tid];
  __syncthreads();
  int idx = blockIdx.x*256 + tid;
  int tw = idx & 31, ho = (idx>>5)&63, b = idx>>11;
  u64 acc[2][16];
  #pragma unroll
  for (int c=0;c<16;c++){ acc[0][c]=pack2(bs[2*c],bs[2*c+1]); acc[1][c]=acc[0][c]; }
  for (int kh=0;kh<3;kh++){
    int hi = 2*ho-1+kh; bool inh = (unsigned)hi<128u;
    for (int kw=0;kw<3;kw++){
      int wi0 = 4*tw-1+kw, wi1 = wi0+2;
      bool in0 = inh && (unsigned)wi0<128u;
      bool in1 = inh && (unsigned)wi1<128u;
      const float4* ip0 = (const float4*)(g_b1 + ((size_t)((b*128+hi)*128+wi0))*32);
      const float4* ip1 = ip0 + 16;
      const float* wt = &ws[(kh*3+kw)*1024];
      #pragma unroll 4
      for (int ci4=0;ci4<8;ci4++){
        float4 v0 = in0 ? ip0[ci4] : zero4();
        float4 v1 = in1 ? ip1[ci4] : zero4();
        u64 a0=bcast2(v0.x), a1=bcast2(v0.y), a2=bcast2(v0.z), a3=bcast2(v0.w);
        u64 b0=bcast2(v1.x), b1=bcast2(v1.y), b2=bcast2(v1.z), b3=bcast2(v1.w);
        const ulonglong2* wp = (const ulonglong2*)(wt + ci4*128);
        #pragma unroll
        for (int q=0;q<8;q++){ ulonglong2 t=wp[q];
          ffma2(acc[0][2*q],a0,t.x); ffma2(acc[0][2*q+1],a0,t.y);
          ffma2(acc[1][2*q],b0,t.x); ffma2(acc[1][2*q+1],b0,t.y); }
        #pragma unroll
        for (int q=0;q<8;q++){ ulonglong2 t=wp[8+q];
          ffma2(acc[0][2*q],a1,t.x); ffma2(acc[0][2*q+1],a1,t.y);
          ffma2(acc[1][2*q],b1,t.x); ffma2(acc[1][2*q+1],b1,t.y); }
        #pragma unroll
        for (int q=0;q<8;q++){ ulonglong2 t=wp[16+q];
          ffma2(acc[0][2*q],a2,t.x); ffma2(acc[0][2*q+1],a2,t.y);
          ffma2(acc[1][2*q],b2,t.x); ffma2(acc[1][2*q+1],b2,t.y); }
        #pragma unroll
        for (int q=0;q<8;q++){ ulonglong2 t=wp[24+q];
          ffma2(acc[0][2*q],a3,t.x); ffma2(acc[0][2*q+1],a3,t.y);
          ffma2(acc[1][2*q],b3,t.x); ffma2(acc[1][2*q+1],b3,t.y); }
      }
    }
  }
  #pragma unroll
  for (int p=0;p<2;p++){
    float4* op = (float4*)(g_b2 + (size_t)(2*idx+p)*64 + half*32);
    #pragma unroll
    for (int c4=0;c4<8;c4++){
      float2 a=unpack2(acc[p][2*c4]), b2=unpack2(acc[p][2*c4+1]);
      float4 o; o.x=fmaxf(a.x,0.f); o.y=fmaxf(a.y,0.f); o.z=fmaxf(b2.x,0.f); o.w=fmaxf(b2.y,0.f);
      op[c4]=o;
    }
  }
}

// ------------- enc3 (1x1 64->16) + VQ + quantize + VQ loss (R3) -------------
__global__ __launch_bounds__(256) void vq_k(const float* __restrict__ cb,
                                            const float* __restrict__ w3,
                                            const float* __restrict__ b3){
  __shared__ __align__(16) float cbs[8192];
  __shared__ float nrm[512];
  __shared__ __align__(16) float w3s[1024];
  __shared__ float b3s[16];
  int tid = threadIdx.x;
  for (int i=tid;i<8192;i+=256) cbs[i]=cb[i];
  for (int i=tid;i<1024;i+=256){ int ci=i>>4, d=i&15; w3s[i]=w3[d*64+ci]; }
  if (tid<16) b3s[tid]=b3[tid];
  __syncthreads();
  for (int k=tid;k<512;k+=256){
    float s=0.f;
    #pragma unroll
    for (int d=0;d<16;d++){ float e=cbs[k*16+d]; s=fmaf(e,e,s); }
    nrm[k]=0.5f*s;
  }
  __syncthreads();
  int idx = blockIdx.x*256 + tid;
  u64 z2[2][8];
  #pragma unroll
  for (int q=0;q<8;q++){ z2[0][q]=pack2(b3s[2*q],b3s[2*q+1]); z2[1][q]=z2[0][q]; }
  const float4* ip0 = (const float4*)(g_b2 + (size_t)(2*idx)*64);
  const float4* ip1 = ip0 + 16;
  #pragma unroll 4
  for (int ci4=0;ci4<16;ci4++){
    float4 v0 = ip0[ci4], v1 = ip1[ci4];
    float a[4]={v0.x,v0.y,v0.z,v0.w}, bb[4]={v1.x,v1.y,v1.z,v1.w};
    #pragma unroll
    for (int j=0;j<4;j++){
      u64 vb0 = bcast2(a[j]), vb1 = bcast2(bb[j]);
      const ulonglong2* wp = (const ulonglong2*)&w3s[(ci4*4+j)*16];
      #pragma unroll
      for (int q=0;q<4;q++){ ulonglong2 t=wp[q];
        ffma2(z2[0][2*q],vb0,t.x); ffma2(z2[0][2*q+1],vb0,t.y);
        ffma2(z2[1][2*q],vb1,t.x); ffma2(z2[1][2*q+1],vb1,t.y); }
    }
  }
  int best0=0, best1=0; float bs0=-3.4e38f, bs1=-3.4e38f;
  for (int k=0;k<512;k++){
    const ulonglong2* e2 = (const ulonglong2*)&cbs[k*16];
    ulonglong2 t0=e2[0], t1=e2[1], t2=e2[2], t3=e2[3];
    u64 sa0=0ull, sb0=0ull, sa1=0ull, sb1=0ull;
    ffma2(sa0,z2[0][0],t0.x); ffma2(sb0,z2[0][4],t2.x);
    ffma2(sa1,z2[1][0],t0.x); ffma2(sb1,z2[1][4],t2.x);
    ffma2(sa0,z2[0][1],t0.y); ffma2(sb0,z2[0][5],t2.y);
    ffma2(sa1,z2[1][1],t0.y); ffma2(sb1,z2[1][5],t2.y);
    ffma2(sa0,z2[0][2],t1.x); ffma2(sb0,z2[0][6],t3.x);
    ffma2(sa1,z2[1][2],t1.x); ffma2(sb1,z2[1][6],t3.x);
    ffma2(sa0,z2[0][3],t1.y); ffma2(sb0,z2[0][7],t3.y);
    ffma2(sa1,z2[1][3],t1.y); ffma2(sb1,z2[1][7],t3.y);
    float2 pa0=unpack2(sa0), pb0=unpack2(sb0);
    float2 pa1=unpack2(sa1), pb1=unpack2(sb1);
    float nk = nrm[k];
    float s0 = (pa0.x + pa0.y) + (pb0.x + pb0.y) - nk;
    float s1 = (pa1.x + pa1.y) + (pb1.x + pb1.y) - nk;
    if (s0>bs0){ bs0=s0; best0=k; }
    if (s1>bs1){ bs1=s1; best1=k; }
  }
  float ls=0.f;
  int bests[2]={best0,best1};
  #pragma unroll
  for (int p=0;p<2;p++){
    const float* e = &cbs[bests[p]*16];
    float4* qo = (float4*)(g_q + (size_t)(2*idx+p)*16);
    #pragma unroll
    for (int d4=0;d4<4;d4++){
      float4 o; o.x=e[d4*4+0]; o.y=e[d4*4+1]; o.z=e[d4*4+2]; o.w=e[d4*4+3];
      qo[d4]=o;
      float2 za=unpack2(z2[p][d4*2]), zb=unpack2(z2[p][d4*2+1]);
      float d0=o.x-za.x, d1=o.y-za.y, d2=o.z-zb.x, d3=o.w-zb.y;
      ls = fmaf(d0,d0, fmaf(d1,d1, fmaf(d2,d2, fmaf(d3,d3, ls))));
    }
  }
  float s = blockReduceSum(ls);
  if (tid==0) atomicAdd(&g_acc[0], (double)s);
}

// ------------- dec1 (R3): convT 16->64, parity + halves + 2px; bf16 output --
template<int PH,int PW>
__global__ __launch_bounds__(256) void dec1_k(const float* __restrict__ bias){
  constexpr int NKH = PH?2:1, NKW = PW?2:1;
  __shared__ __align__(16) float ws[NKH*NKW*512];
  __shared__ float bs[32];
  int half = blockIdx.y;
  int tid = threadIdx.x;
  for (int i=tid;i<NKH*NKW*512;i+=256){
    int j = i & 511; int t = i >> 9;
    int a = t / NKW, c = t % NKW;
    int kh = PH ? a*2 : 1;
    int kw = PW ? c*2 : 1;
    ws[i] = g_wrd1[(kh*3+kw)*1024 + (j>>5)*64 + half*32 + (j&31)];
  }
  if (tid<32) bs[tid]=bias[half*32+tid];
  __syncthreads();
  int idx = blockIdx.x*256 + tid;
  int tw = idx & 31, hb = (idx>>5)&63, b = idx>>11;
  int wb0 = 2*tw;
  int ho = 2*hb+PH, wo0 = 2*wb0+PW;
  u64 acc[2][16];
  #pragma unroll
  for (int c=0;c<16;c++){ acc[0][c]=pack2(bs[2*c],bs[2*c+1]); acc[1][c]=acc[0][c]; }
  #pragma unroll
  for (int a=0;a<NKH;a++){
    int hi = PH ? (a==0 ? hb+1 : hb) : hb;
    bool inh = PH ? (hi<64) : true;
    #pragma unroll
    for (int cc=0;cc<NKW;cc++){
      int wi0 = PW ? (cc==0 ? wb0+1 : wb0) : wb0;
      int wi1 = wi0+1;
      bool in0 = inh;
      bool in1 = inh && (wi1<64);
      const float4* ip0 = (const float4*)(g_q + ((size_t)((b*64+hi)*64+wi0))*16);
      const float4* ip1 = ip0 + 4;
      const float* wt = &ws[(a*NKW+cc)*512];
      #pragma unroll
      for (int ci4=0;ci4<4;ci4++){
        float4 v0 = in0 ? ip0[ci4] : zero4();
        float4 v1 = in1 ? ip1[ci4] : zero4();
        float va[4]={v0.x,v0.y,v0.z,v0.w}, vb[4]={v1.x,v1.y,v1.z,v1.w};
        #pragma unroll
        for (int j=0;j<4;j++){
          u64 p0 = bcast2(va[j]), p1 = bcast2(vb[j]);
          const ulonglong2* wp = (const ulonglong2*)(wt + (ci4*4+j)*32);
          #pragma unroll
          for (int q=0;q<8;q++){ ulonglong2 t3=wp[q];
            ffma2(acc[0][2*q],p0,t3.x); ffma2(acc[0][2*q+1],p0,t3.y);
            ffma2(acc[1][2*q],p1,t3.x); ffma2(acc[1][2*q+1],p1,t3.y); }
        }
      }
    }
  }
  #pragma unroll
  for (int p=0;p<2;p++){
    int wo = wo0 + 2*p;
    unsigned short* op = g_d1h + ((size_t)((b*128+ho)*128+wo))*64 + half*32;
    u32 pk[16];
    #pragma unroll
    for (int c=0;c<16;c++){
      float2 f = unpack2(acc[p][c]);
      pk[c] = bfpack(fmaxf(f.x,0.f), fmaxf(f.y,0.f));
    }
    #pragma unroll
    for (int q=0;q<4;q++)
      ((uint4*)op)[q] = make_uint4(pk[4*q],pk[4*q+1],pk[4*q+2],pk[4*q+3]);
  }
}

// ------------- dec2: convT 64->32 via mma.sync bf16 (per parity class) ------
// Block: 128 threads (4 warps). Covers (b, hb, 64 consecutive wb). Each warp:
// 16 output pixels (m) x 32 co (4 n-tiles), K=64 per tap, fp32 accumulate.
template<int PH,int PW>
__global__ __launch_bounds__(128) void dec2_mma_k(const float* __restrict__ bias){
  constexpr int NKH = PH?2:1, NKW = PW?2:1, NROWS = PH?2:1;
  constexpr int ROWB = 65*144;                    // bytes per staged input row
  __shared__ __align__(16) unsigned char As[NROWS*ROWB];
  __shared__ __align__(16) u32 Bs[NKH*NKW*1024];
  __shared__ float bias_s[32];
  int tid = threadIdx.x;
  int bx = blockIdx.x;
  int wchunk = bx & 1, hb = (bx>>1)&127, b = bx>>8;
  int wb0 = wchunk*64;
  // stage B fragments
  for (int i=tid;i<NKH*NKW*1024;i+=128){
    int tl = i>>10, w_ = i & 1023;
    int a = tl/NKW, cc = tl%NKW;
    int kh = PH? a*2 : 1, kw = PW? cc*2 : 1;
    Bs[i] = g_wfrag[(kh*3+kw)*1024 + w_];
  }
  if (tid<32) bias_s[tid]=bias[tid];
  // stage A rows (bf16, padded pixel stride 144B; slot 64 / invalid rows zero)
  for (int i=tid;i<NROWS*65*8;i+=128){
    int r = i/520, rem = i%520, px = rem>>3, ch = rem&7;
    int hi = hb + r;                              // r=0 -> hb, r=1 -> hb+1
    int wi = wb0 + px;
    uint4 v = make_uint4(0,0,0,0);
    if (hi<128 && wi<128)
      v = *(const uint4*)&g_d1h[(((size_t)(b*128+hi))*128+wi)*64 + ch*8];
    *(uint4*)&As[r*ROWB + px*144 + ch*16] = v;
  }
  __syncthreads();

  u32 aSm = smem_u32(As);
  u32 bSm = smem_u32(Bs);
  int lane = tid & 31, wid = tid>>5;
  int g = lane>>2, tig = lane&3;
  float c[4][4];
  #pragma unroll
  for (int ntv=0;ntv<4;ntv++){
    float bA = bias_s[ntv*8+2*tig], bB = bias_s[ntv*8+2*tig+1];
    c[ntv][0]=bA; c[ntv][1]=bB; c[ntv][2]=bA; c[ntv][3]=bB;
  }
  u32 laneRow = (u32)(lane & 15);
  u32 laneCol = (lane & 16) ? 16u : 0u;
  #pragma unroll
  for (int a=0;a<NKH;a++){
    int rtap = PH ? (a==0 ? 1 : 0) : 0;           // kh=0 -> hi=hb+1
    #pragma unroll
    for (int cc=0;cc<NKW;cc++){
      int shift = PW ? (cc==0 ? 1 : 0) : 0;       // kw=0 -> wi=wb+1
      int tl = a*NKW+cc;
      u32 abase = aSm + rtap*ROWB + (wid*16 + shift + laneRow)*144 + laneCol;
      #pragma unroll
      for (int kt=0;kt<4;kt++){
        u32 a0,a1,a2,a3;
        asm volatile("ldmatrix.sync.aligned.m8n8.x4.shared.b16 {%0,%1,%2,%3}, [%4];"
                     : "=r"(a0),"=r"(a1),"=r"(a2),"=r"(a3)
                     : "r"(abase + kt*32));
        #pragma unroll
        for (int ntv=0;ntv<4;ntv++){
          u32 b0,b1;
          asm volatile("ld.shared.v2.u32 {%0,%1}, [%2];"
                       : "=r"(b0),"=r"(b1)
                       : "r"(bSm + (((tl*4+kt)*4+ntv)*64 + lane*2)*4));
          asm volatile("mma.sync.aligned.m16n8k16.row.col.f32.bf16.bf16.f32 "
                       "{%0,%1,%2,%3}, {%4,%5,%6,%7}, {%8,%9}, {%0,%1,%2,%3};"
                       : "+f"(c[ntv][0]),"+f"(c[ntv][1]),"+f"(c[ntv][2]),"+f"(c[ntv][3])
                       : "r"(a0),"r"(a1),"r"(a2),"r"(a3),"r"(b0),"r"(b1));
        }
      }
    }
  }
  // epilogue: relu + store fp32 NHWC
  int ho = 2*hb+PH;
  int wbA = wb0 + wid*16 + g, wbB = wbA + 8;
  float* rowBase = g_d2 + ((size_t)(b*256+ho))*256*32;
  float* pA = rowBase + (size_t)(2*wbA+PW)*32 + 2*tig;
  float* pB = rowBase + (size_t)(2*wbB+PW)*32 + 2*tig;
  #pragma unroll
  for (int ntv=0;ntv<4;ntv++){
    float2 vA; vA.x=fmaxf(c[ntv][0],0.f); vA.y=fmaxf(c[ntv][1],0.f);
    float2 vB; vB.x=fmaxf(c[ntv][2],0.f); vB.y=fmaxf(c[ntv][3],0.f);
    *(float2*)(pA + ntv*8) = vA;
    *(float2*)(pB + ntv*8) = vB;
  }
}

// ------------- dec3: convT 32->3 k3 s1 p1 + recon MSE (fused, no store) -----
#define COMPSEL(v,c) ((c)==0 ? (v).x : (c)==1 ? (v).y : (c)==2 ? (v).z : (v).w)
__global__ __launch_bounds__(256) void dec3_k(const float* __restrict__ x,
                                              const float* __restrict__ bias){
  __shared__ __align__(16) u64 ws2[864];
  __shared__ float bs[3];
  int tid = threadIdx.x;
  for (int i=tid;i<864;i+=256){ float w=g_wrd3[i]; ws2[i]=pack2(w,w); }
  if (tid<3) bs[tid]=bias[tid];
  __syncthreads();
  int idx = blockIdx.x*256 + tid;
  int tw = idx & 63, ho = (idx>>6)&255, b = idx>>14;
  int wo0 = tw*4;
  u64 accp[3][2];
  #pragma unroll
  for (int co=0;co<3;co++){ accp[co][0]=pack2(bs[co],bs[co]); accp[co][1]=accp[co][0]; }
  for (int kh=0;kh<3;kh++){
    int hi = ho-1+kh; if ((unsigned)hi>=256u) continue;
    const float* rowp = g_d2 + ((size_t)(b*256+hi))*256*32;
    #pragma unroll 2
    for (int ci4=0;ci4<8;ci4++){
      float4 v[6];
      #pragma unroll
      for (int j=0;j<6;j++){
        int wi = wo0-1+j;
        if ((unsigned)wi<256u) v[j] = ((const float4*)(rowp + (size_t)wi*32))[ci4];
        else v[j] = zero4();
      }
      #pragma unroll
      for (int kw=0;kw<3;kw++){
        #pragma unroll
        for (int c=0;c<4;c++){
          float f0=COMPSEL(v[kw+0],c), f1=COMPSEL(v[kw+1],c);
          float f2=COMPSEL(v[kw+2],c), f3=COMPSEL(v[kw+3],c);
          u64 a0=pack2(f0,f1), a1=pack2(f2,f3);
          const u64* wd = &ws2[((kh*3+kw)*32 + ci4*4 + c)*3];
          u64 w0=wd[0], w1=wd[1], w2=wd[2];
          ffma2(accp[0][0],a0,w0); ffma2(accp[0][1],a1,w0);
          ffma2(accp[1][0],a0,w1); ffma2(accp[1][1],a1,w1);
          ffma2(accp[2][0],a0,w2); ffma2(accp[2][1],a1,w2);
        }
      }
    }
  }
  float acc[4][3];
  #pragma unroll
  for (int co=0;co<3;co++){
    float2 p0=unpack2(accp[co][0]), p1=unpack2(accp[co][1]);
    acc[0][co]=p0.x; acc[1][co]=p0.y; acc[2][co]=p1.x; acc[3][co]=p1.y;
  }
  float ls=0.f;
  const float* xb = x + (size_t)b*3*65536;
  #pragma unroll
  for (int o=0;o<4;o++){
    #pragma unroll
    for (int c=0;c<3;c++){
      float d = acc[o][c] - xb[(size_t)c*65536 + ho*256 + wo0+o];
      ls = fmaf(d,d,ls);
    }
  }
  float s = blockReduceSum(ls);
  if (tid==0) atomicAdd(&g_acc[1], (double)s);
}

// ------------- finalize -----------------------------------------------------
__global__ void final_k(float* __restrict__ out){
  double vq  = g_acc[0];
  double rec = g_acc[1];
  float e_q  = (float)(1.25 * vq / 4194304.0);
  float mse  = (float)(rec / 12582912.0);
  out[0] = e_q;
  out[1] = mse;
  out[2] = mse;
}

// ---------------- launch ----------------------------------------------------
extern "C" void kernel_launch(void* const* d_in, const int* in_sizes, int n_in,
                              void* d_out, int out_size){
  const float* x   = (const float*)d_in[0];
  const float* ew1 = (const float*)d_in[1];
  const float* eb1 = (const float*)d_in[2];
  const float* ew2 = (const float*)d_in[3];
  const float* eb2 = (const float*)d_in[4];
  const float* ew3 = (const float*)d_in[5];
  const float* eb3 = (const float*)d_in[6];
  const float* cb  = (const float*)d_in[7];
  const float* dw1 = (const float*)d_in[8];
  const float* db1 = (const float*)d_in[9];
  const float* dw2 = (const float*)d_in[10];
  const float* db2 = (const float*)d_in[11];
  const float* dw3 = (const float*)d_in[12];
  const float* db3 = (const float*)d_in[13];
  float* out = (float*)d_out;

  repack_k<<<64,256>>>(ew1, ew2, dw1, dw2, dw3);
  enc1_k<<<2048,256>>>(x, eb1);
  enc2_k<<<dim3(512,2),256>>>(eb2);
  vq_k<<<512,256>>>(cb, ew3, eb3);
  dec1_k<0,0><<<dim3(512,2),256>>>(db1);
  dec1_k<0,1><<<dim3(512,2),256>>>(db1);
  dec1_k<1,0><<<dim3(512,2),256>>>(db1);
  dec1_k<1,1><<<dim3(512,2),256>>>(db1);
  dec2_mma_k<0,0><<<16384,128>>>(db2);
  dec2_mma_k<0,1><<<16384,128>>>(db2);
  dec2_mma_k<1,0><<<16384,128>>>(db2);
  dec2_mma_k<1,1><<<16384,128>>>(db2);
  dec3_k<<<4096,256>>>(x, db3);
  final_k<<<1,1>>>(out);
}

// round 7
// speedup vs baseline: 2.3391x; 1.2475x over previous
#include <cuda_runtime.h>
#include <cuda_bf16.h>
#include <cstdint>

typedef unsigned long long u64;
typedef unsigned int u32;

// ---------------- scratch (device globals; no allocations allowed) ----------
__device__ unsigned short g_b1h[(size_t)64*128*128*32];  // enc1 out NHWC bf16
__device__ float g_b2[(size_t)64*64*64*64];              // enc2 out NHWC fp32 (exact VQ input fmt)
__device__ unsigned short g_qh[(size_t)64*64*64*16];     // quantized NHWC bf16
__device__ unsigned short g_d1h[(size_t)64*128*128*64];  // dec1 out NHWC bf16
__device__ float g_d2[(size_t)64*256*256*32];            // dec2 out NHWC fp32

__device__ float g_wr1 [864];      // enc1 w  [kh][kw][ci=3][co=32]
__device__ u32   g_wfrag2[18432];  // enc2 w  B-frags [tap9][kt2][nt8][lane32][reg2]
__device__ u32   g_wfragd1[4608];  // dec1 w  B-frags [tap9][nt8][lane32][reg2]
__device__ u32   g_wfrag[9216];    // dec2 w  B-frags [tap9][kt4][nt4][lane32][reg2]
__device__ float g_wrd3[864];      // dec3 w  [kh][kw][ci=32][co=3] (pre-flipped)
__device__ double g_acc[2];        // [0]=vq sq-sum, [1]=recon sq-sum

// ---------------- helpers ----------------------------------------------------
__device__ __forceinline__ u64 pack2(float lo, float hi){
  u64 r; asm("mov.b64 %0, {%1, %2};" : "=l"(r)
             : "r"(__float_as_uint(lo)), "r"(__float_as_uint(hi)));
  return r;
}
__device__ __forceinline__ u64 bcast2(float v){
  u64 r; asm("mov.b64 %0, {%1, %1};" : "=l"(r) : "r"(__float_as_uint(v)));
  return r;
}
__device__ __forceinline__ float2 unpack2(u64 p){
  unsigned lo, hi;
  asm("mov.b64 {%0, %1}, %2;" : "=r"(lo), "=r"(hi) : "l"(p));
  return make_float2(__uint_as_float(lo), __uint_as_float(hi));
}
__device__ __forceinline__ void ffma2(u64 &acc, u64 a, u64 b){
  asm("fma.rn.f32x2 %0, %1, %2, %0;" : "+l"(acc) : "l"(a), "l"(b));
}
__device__ __forceinline__ float4 zero4(){ float4 z; z.x=z.y=z.z=z.w=0.f; return z; }
__device__ __forceinline__ u32 bfpack(float lo, float hi){
  u32 r; asm("cvt.rn.bf16x2.f32 %0, %1, %2;" : "=r"(r) : "f"(hi), "f"(lo));
  return r;
}
__device__ __forceinline__ u32 smem_u32(const void* p){
  u32 a; asm("{ .reg .u64 t; cvta.to.shared.u64 t, %1; cvt.u32.u64 %0, t; }"
             : "=r"(a) : "l"(p));
  return a;
}

__device__ __forceinline__ float blockReduceSum(float v){
  __shared__ float red[32];
  #pragma unroll
  for (int o=16;o;o>>=1) v += __shfl_down_sync(0xffffffffu, v, o);
  int lane = threadIdx.x & 31, w = threadIdx.x >> 5;
  if (lane==0) red[w]=v;
  __syncthreads();
  if (w==0){
    v = (lane < ((int)blockDim.x>>5)) ? red[lane] : 0.f;
    #pragma unroll
    for (int o=16;o;o>>=1) v += __shfl_down_sync(0xffffffffu, v, o);
  }
  return v;
}

// ---------------- weight repack + accumulator reset -------------------------
__global__ void repack_k(const float* __restrict__ ew1, const float* __restrict__ ew2,
                         const float* __restrict__ dw1, const float* __restrict__ dw2,
                         const float* __restrict__ dw3){
  int t = blockIdx.x*blockDim.x + threadIdx.x;
  int nt = gridDim.x*blockDim.x;
  if (blockIdx.x==0 && threadIdx.x<2) g_acc[threadIdx.x]=0.0;
  for (int i=t;i<864;i+=nt){ int co=i%32; int r=i/32; int ci=r%3; r/=3; int kw=r%3, kh=r/3;
    g_wr1[i] = ew1[((co*3+ci)*3+kh)*3+kw]; }
  // enc2 bf16 B-frags: i = tap*1024 + kt*512 + nt*64 + lane*2 + reg
  for (int i=t;i<18432;i+=nt){
    int reg=i&1; int lane=(i>>1)&31; int ntv=(i>>6)&7; int kt=(i>>9)&1; int tap=i>>10;
    int kh=tap/3, kw=tap%3;
    int gg=lane>>2, tg=lane&3;
    int co = ntv*8+gg;
    int ci0 = kt*16 + 2*tg + (reg?8:0);
    float w0 = ew2[((co*32+ci0)*3+kh)*3+kw];
    float w1 = ew2[((co*32+ci0+1)*3+kh)*3+kw];
    g_wfrag2[i] = (u32)__bfloat16_as_ushort(__float2bfloat16(w0))
                | ((u32)__bfloat16_as_ushort(__float2bfloat16(w1))<<16);
  }
  // dec1 bf16 B-frags: i = tap*512 + nt*64 + lane*2 + reg
  for (int i=t;i<4608;i+=nt){
    int reg=i&1; int lane=(i>>1)&31; int ntv=(i>>6)&7; int tap=i>>9;
    int kh=tap/3, kw=tap%3;
    int gg=lane>>2, tg=lane&3;
    int co = ntv*8+gg;
    int ci0 = 2*tg + (reg?8:0);
    float w0 = dw1[((ci0*64+co)*3+kh)*3+kw];
    float w1 = dw1[(((ci0+1)*64+co)*3+kh)*3+kw];
    g_wfragd1[i] = (u32)__bfloat16_as_ushort(__float2bfloat16(w0))
                 | ((u32)__bfloat16_as_ushort(__float2bfloat16(w1))<<16);
  }
  // dec2 bf16 B-frags (R6 layout): i = tap*1024 + kt*256 + nt*64 + lane*2 + reg
  for (int i=t;i<9216;i+=nt){
    int tap = i>>10; int w_ = i & 1023;
    int reg = w_ & 1; int lane = (w_>>1)&31; int ntv = (w_>>6)&3; int kt = (w_>>8)&3;
    int kh = tap/3, kw = tap%3;
    int gg = lane>>2, tg = lane&3;
    int co = ntv*8+gg;
    int ci0 = kt*16 + 2*tg + (reg?8:0);
    float w0 = dw2[((ci0*32+co)*3+kh)*3+kw];
    float w1 = dw2[(((ci0+1)*32+co)*3+kh)*3+kw];
    g_wfrag[i] = (u32)__bfloat16_as_ushort(__float2bfloat16(w0))
               | ((u32)__bfloat16_as_ushort(__float2bfloat16(w1))<<16);
  }
  for (int i=t;i<864;i+=nt){ int co=i%3; int r=i/3; int ci=r%32; r/=32; int kw=r%3, kh=r/3;
    g_wrd3[i] = dw3[((ci*3+co)*3+(2-kh))*3+(2-kw)]; }
}

// ---------------- enc1: 3->32, k3 s2 p1, relu; 2 px/thread; bf16 out --------
__global__ __launch_bounds__(256) void enc1_k(const float* __restrict__ x,
                                              const float* __restrict__ bias){
  __shared__ __align__(16) float ws[864];
  __shared__ float bs[32];
  int tid = threadIdx.x;
  for (int i=tid;i<864;i+=256) ws[i]=g_wr1[i];
  if (tid<32) bs[tid]=bias[tid];
  __syncthreads();
  int idx = blockIdx.x*256 + tid;
  int tw = idx & 63, ho = (idx>>6)&127, b = idx>>13;
  u64 acc[2][16];
  #pragma unroll
  for (int c=0;c<16;c++){ acc[0][c]=pack2(bs[2*c],bs[2*c+1]); acc[1][c]=acc[0][c]; }
  const float* xb = x + (size_t)b*3*65536;
  for (int kh=0;kh<3;kh++){
    int hi = 2*ho-1+kh; bool inh = (unsigned)hi<256u;
    for (int kw=0;kw<3;kw++){
      int wi0 = 4*tw-1+kw, wi1 = wi0+2;
      bool in0 = inh && (unsigned)wi0<256u;
      bool in1 = inh && (unsigned)wi1<256u;
      #pragma unroll
      for (int ci=0;ci<3;ci++){
        float f0 = in0 ? xb[(size_t)ci*65536 + hi*256 + wi0] : 0.f;
        float f1 = in1 ? xb[(size_t)ci*65536 + hi*256 + wi1] : 0.f;
        u64 v0=bcast2(f0), v1=bcast2(f1);
        const ulonglong2* wp = (const ulonglong2*)&ws[((kh*3+kw)*3+ci)*32];
        #pragma unroll
        for (int q=0;q<8;q++){
          ulonglong2 t=wp[q];
          ffma2(acc[0][2*q],v0,t.x); ffma2(acc[0][2*q+1],v0,t.y);
          ffma2(acc[1][2*q],v1,t.x); ffma2(acc[1][2*q+1],v1,t.y);
        }
      }
    }
  }
  unsigned short* op = g_b1h + (size_t)(2*idx)*32;
  #pragma unroll
  for (int p=0;p<2;p++){
    u32 pk[16];
    #pragma unroll
    for (int c=0;c<16;c++){
      float2 f = unpack2(acc[p][c]);
      pk[c] = bfpack(fmaxf(f.x,0.f), fmaxf(f.y,0.f));
    }
    #pragma unroll
    for (int q=0;q<4;q++)
      ((uint4*)op)[p*4+q] = make_uint4(pk[4*q],pk[4*q+1],pk[4*q+2],pk[4*q+3]);
  }
}

// ---------------- enc2: 32->64 k3 s2 p1 relu via mma bf16 -------------------
// Block 128 thr (4 warps x 16 px = 64 wo = full output row). fp32 out g_b2.
__global__ __launch_bounds__(128) void enc2_mma_k(const float* __restrict__ bias){
  constexpr int ROWB = 129*80;
  __shared__ __align__(16) unsigned char As[3*ROWB];
  __shared__ float bias_s[64];
  int tid = threadIdx.x, bx = blockIdx.x;
  int ho = bx & 63, b = bx >> 6;
  if (tid<64) bias_s[tid]=bias[tid];
  for (int i=tid;i<3*129*4;i+=128){
    int r=i/516, rem=i%516, px=rem>>2, ch=rem&3;
    int hi=2*ho-1+r, wi=px-1;
    uint4 v=make_uint4(0,0,0,0);
    if ((unsigned)hi<128u && (unsigned)wi<128u)
      v = *(const uint4*)&g_b1h[(((size_t)(b*128+hi))*128+wi)*32 + ch*8];
    *(uint4*)&As[r*ROWB + px*80 + ch*16] = v;
  }
  __syncthreads();
  u32 aSm = smem_u32(As);
  int lane = tid&31, wid = tid>>5;
  int g = lane>>2, tig = lane&3;
  float c[8][4];
  #pragma unroll
  for (int ntv=0;ntv<8;ntv++){
    float bA=bias_s[ntv*8+2*tig], bB=bias_s[ntv*8+2*tig+1];
    c[ntv][0]=bA; c[ntv][1]=bB; c[ntv][2]=bA; c[ntv][3]=bB;
  }
  u32 laneRow = (u32)(lane & 15);
  u32 laneCol = (lane & 16) ? 16u : 0u;
  #pragma unroll
  for (int kh=0;kh<3;kh++){
    #pragma unroll
    for (int kw=0;kw<3;kw++){
      int tap = kh*3+kw;
      #pragma unroll
      for (int kt=0;kt<2;kt++){
        u32 abase = aSm + kh*ROWB + (wid*32 + 2*laneRow + kw)*80 + kt*32 + laneCol;
        u32 a0,a1,a2,a3;
        asm volatile("ldmatrix.sync.aligned.m8n8.x4.shared.b16 {%0,%1,%2,%3}, [%4];"
                     : "=r"(a0),"=r"(a1),"=r"(a2),"=r"(a3) : "r"(abase));
        #pragma unroll
        for (int ntv=0;ntv<8;ntv++){
          uint2 bv = *(const uint2*)&g_wfrag2[tap*1024 + kt*512 + ntv*64 + lane*2];
          asm volatile("mma.sync.aligned.m16n8k16.row.col.f32.bf16.bf16.f32 "
                       "{%0,%1,%2,%3}, {%4,%5,%6,%7}, {%8,%9}, {%0,%1,%2,%3};"
                       : "+f"(c[ntv][0]),"+f"(c[ntv][1]),"+f"(c[ntv][2]),"+f"(c[ntv][3])
                       : "r"(a0),"r"(a1),"r"(a2),"r"(a3),"r"(bv.x),"r"(bv.y));
        }
      }
    }
  }
  int woA = wid*16+g, woB = woA+8;
  float* base = g_b2 + ((size_t)(b*64+ho))*64*64;
  float* pA = base + (size_t)woA*64 + 2*tig;
  float* pB = base + (size_t)woB*64 + 2*tig;
  #pragma unroll
  for (int ntv=0;ntv<8;ntv++){
    float2 vA; vA.x=fmaxf(c[ntv][0],0.f); vA.y=fmaxf(c[ntv][1],0.f);
    float2 vB; vB.x=fmaxf(c[ntv][2],0.f); vB.y=fmaxf(c[ntv][3],0.f);
    *(float2*)(pA + ntv*8) = vA;
    *(float2*)(pB + ntv*8) = vB;
  }
}

// ------------- enc3 (1x1 64->16) + VQ + quantize(bf16) + VQ loss ------------
__global__ __launch_bounds__(256) void vq_k(const float* __restrict__ cb,
                                            const float* __restrict__ w3,
                                            const float* __restrict__ b3){
  __shared__ __align__(16) float cbs[8192];
  __shared__ float nrm[512];
  __shared__ __align__(16) float w3s[1024];
  __shared__ float b3s[16];
  int tid = threadIdx.x;
  for (int i=tid;i<8192;i+=256) cbs[i]=cb[i];
  for (int i=tid;i<1024;i+=256){ int ci=i>>4, d=i&15; w3s[i]=w3[d*64+ci]; }
  if (tid<16) b3s[tid]=b3[tid];
  __syncthreads();
  for (int k=tid;k<512;k+=256){
    float s=0.f;
    #pragma unroll
    for (int d=0;d<16;d++){ float e=cbs[k*16+d]; s=fmaf(e,e,s); }
    nrm[k]=0.5f*s;
  }
  __syncthreads();
  int idx = blockIdx.x*256 + tid;
  u64 z2[2][8];
  #pragma unroll
  for (int q=0;q<8;q++){ z2[0][q]=pack2(b3s[2*q],b3s[2*q+1]); z2[1][q]=z2[0][q]; }
  const float4* ip0 = (const float4*)(g_b2 + (size_t)(2*idx)*64);
  const float4* ip1 = ip0 + 16;
  #pragma unroll 4
  for (int ci4=0;ci4<16;ci4++){
    float4 v0 = ip0[ci4], v1 = ip1[ci4];
    float a[4]={v0.x,v0.y,v0.z,v0.w}, bb[4]={v1.x,v1.y,v1.z,v1.w};
    #pragma unroll
    for (int j=0;j<4;j++){
      u64 vb0 = bcast2(a[j]), vb1 = bcast2(bb[j]);
      const ulonglong2* wp = (const ulonglong2*)&w3s[(ci4*4+j)*16];
      #pragma unroll
      for (int q=0;q<4;q++){ ulonglong2 t=wp[q];
        ffma2(z2[0][2*q],vb0,t.x); ffma2(z2[0][2*q+1],vb0,t.y);
        ffma2(z2[1][2*q],vb1,t.x); ffma2(z2[1][2*q+1],vb1,t.y); }
    }
  }
  int best0=0, best1=0; float bs0=-3.4e38f, bs1=-3.4e38f;
  for (int k=0;k<512;k++){
    const ulonglong2* e2 = (const ulonglong2*)&cbs[k*16];
    ulonglong2 t0=e2[0], t1=e2[1], t2=e2[2], t3=e2[3];
    u64 sa0=0ull, sb0=0ull, sa1=0ull, sb1=0ull;
    ffma2(sa0,z2[0][0],t0.x); ffma2(sb0,z2[0][4],t2.x);
    ffma2(sa1,z2[1][0],t0.x); ffma2(sb1,z2[1][4],t2.x);
    ffma2(sa0,z2[0][1],t0.y); ffma2(sb0,z2[0][5],t2.y);
    ffma2(sa1,z2[1][1],t0.y); ffma2(sb1,z2[1][5],t2.y);
    ffma2(sa0,z2[0][2],t1.x); ffma2(sb0,z2[0][6],t3.x);
    ffma2(sa1,z2[1][2],t1.x); ffma2(sb1,z2[1][6],t3.x);
    ffma2(sa0,z2[0][3],t1.y); ffma2(sb0,z2[0][7],t3.y);
    ffma2(sa1,z2[1][3],t1.y); ffma2(sb1,z2[1][7],t3.y);
    float2 pa0=unpack2(sa0), pb0=unpack2(sb0);
    float2 pa1=unpack2(sa1), pb1=unpack2(sb1);
    float nk = nrm[k];
    float s0 = (pa0.x + pa0.y) + (pb0.x + pb0.y) - nk;
    float s1 = (pa1.x + pa1.y) + (pb1.x + pb1.y) - nk;
    if (s0>bs0){ bs0=s0; best0=k; }
    if (s1>bs1){ bs1=s1; best1=k; }
  }
  float ls=0.f;
  int bests[2]={best0,best1};
  #pragma unroll
  for (int p=0;p<2;p++){
    const float* e = &cbs[bests[p]*16];
    unsigned short* qo = g_qh + (size_t)(2*idx+p)*16;
    u32 pk[8];
    #pragma unroll
    for (int d4=0;d4<4;d4++){
      float e0=e[d4*4+0], e1=e[d4*4+1], e2v=e[d4*4+2], e3v=e[d4*4+3];
      pk[2*d4]   = bfpack(e0,e1);
      pk[2*d4+1] = bfpack(e2v,e3v);
      float2 za=unpack2(z2[p][d4*2]), zb=unpack2(z2[p][d4*2+1]);
      float d0=e0-za.x, d1=e1-za.y, d2=e2v-zb.x, d3=e3v-zb.y;
      ls = fmaf(d0,d0, fmaf(d1,d1, fmaf(d2,d2, fmaf(d3,d3, ls))));
    }
    ((uint4*)qo)[0] = make_uint4(pk[0],pk[1],pk[2],pk[3]);
    ((uint4*)qo)[1] = make_uint4(pk[4],pk[5],pk[6],pk[7]);
  }
  float s = blockReduceSum(ls);
  if (tid==0) atomicAdd(&g_acc[0], (double)s);
}

// ------------- dec1: convT 16->64 via mma bf16 (per parity class) -----------
template<int PH,int PW>
__global__ __launch_bounds__(128) void dec1_mma_k(const float* __restrict__ bias){
  constexpr int NKH = PH?2:1, NKW = PW?2:1, NROWS = PH?2:1;
  constexpr int ROWB = 65*48;
  __shared__ __align__(16) unsigned char As[NROWS*ROWB];
  __shared__ __align__(16) u32 Bs[NKH*NKW*512];
  __shared__ float bias_s[64];
  int tid = threadIdx.x, bx = blockIdx.x;
  int hb = bx & 63, b = bx >> 6;
  for (int i=tid;i<NKH*NKW*512;i+=128){
    int tl=i>>9, w_=i&511;
    int a=tl/NKW, cc=tl%NKW;
    int kh=PH?a*2:1, kw=PW?cc*2:1;
    Bs[i]=g_wfragd1[(kh*3+kw)*512+w_];
  }
  if (tid<64) bias_s[tid]=bias[tid];
  for (int i=tid;i<NROWS*65*2;i+=128){
    int r=i/130, rem=i%130, px=rem>>1, hf=rem&1;
    int hi=hb+r;
    uint4 v=make_uint4(0,0,0,0);
    if (hi<64 && px<64)
      v=*(const uint4*)&g_qh[(((size_t)(b*64+hi))*64+px)*16 + hf*8];
    *(uint4*)&As[r*ROWB+px*48+hf*16]=v;
  }
  __syncthreads();
  u32 aSm = smem_u32(As);
  u32 bSm = smem_u32(Bs);
  int lane = tid&31, wid = tid>>5;
  int g = lane>>2, tig = lane&3;
  float c[8][4];
  #pragma unroll
  for (int ntv=0;ntv<8;ntv++){
    float bA=bias_s[ntv*8+2*tig], bB=bias_s[ntv*8+2*tig+1];
    c[ntv][0]=bA; c[ntv][1]=bB; c[ntv][2]=bA; c[ntv][3]=bB;
  }
  u32 laneRow = (u32)(lane & 15);
  u32 laneCol = (lane & 16) ? 16u : 0u;
  #pragma unroll
  for (int a=0;a<NKH;a++){
    int rtap = PH ? (a==0 ? 1 : 0) : 0;
    #pragma unroll
    for (int cc=0;cc<NKW;cc++){
      int shift = PW ? (cc==0 ? 1 : 0) : 0;
      int tl = a*NKW+cc;
      u32 abase = aSm + rtap*ROWB + (wid*16 + shift + laneRow)*48 + laneCol;
      u32 a0,a1,a2,a3;
      asm volatile("ldmatrix.sync.aligned.m8n8.x4.shared.b16 {%0,%1,%2,%3}, [%4];"
                   : "=r"(a0),"=r"(a1),"=r"(a2),"=r"(a3) : "r"(abase));
      #pragma unroll
      for (int ntv=0;ntv<8;ntv++){
        u32 b0,b1;
        asm volatile("ld.shared.v2.u32 {%0,%1}, [%2];"
                     : "=r"(b0),"=r"(b1)
                     : "r"(bSm + ((tl*8+ntv)*64 + lane*2)*4));
        asm volatile("mma.sync.aligned.m16n8k16.row.col.f32.bf16.bf16.f32 "
                     "{%0,%1,%2,%3}, {%4,%5,%6,%7}, {%8,%9}, {%0,%1,%2,%3};"
                     : "+f"(c[ntv][0]),"+f"(c[ntv][1]),"+f"(c[ntv][2]),"+f"(c[ntv][3])
                     : "r"(a0),"r"(a1),"r"(a2),"r"(a3),"r"(b0),"r"(b1));
      }
    }
  }
  int ho = 2*hb+PH;
  int wbA = wid*16+g, wbB = wbA+8;
  unsigned short* rb = g_d1h + ((size_t)(b*128+ho))*128*64;
  unsigned short* pA = rb + (size_t)(2*wbA+PW)*64 + 2*tig;
  unsigned short* pB = rb + (size_t)(2*wbB+PW)*64 + 2*tig;
  #pragma unroll
  for (int ntv=0;ntv<8;ntv++){
    *(u32*)(pA + ntv*8) = bfpack(fmaxf(c[ntv][0],0.f), fmaxf(c[ntv][1],0.f));
    *(u32*)(pB + ntv*8) = bfpack(fmaxf(c[ntv][2],0.f), fmaxf(c[ntv][3],0.f));
  }
}

// ------------- dec2: convT 64->32 via mma bf16 (R6, unchanged) --------------
template<int PH,int PW>
__global__ __launch_bounds__(128) void dec2_mma_k(const float* __restrict__ bias){
  constexpr int NKH = PH?2:1, NKW = PW?2:1, NROWS = PH?2:1;
  constexpr int ROWB = 65*144;
  __shared__ __align__(16) unsigned char As[NROWS*ROWB];
  __shared__ __align__(16) u32 Bs[NKH*NKW*1024];
  __shared__ float bias_s[32];
  int tid = threadIdx.x;
  int bx = blockIdx.x;
  int wchunk = bx & 1, hb = (bx>>1)&127, b = bx>>8;
  int wb0 = wchunk*64;
  for (int i=tid;i<NKH*NKW*1024;i+=128){
    int tl = i>>10, w_ = i & 1023;
    int a = tl/NKW, cc = tl%NKW;
    int kh = PH? a*2 : 1, kw = PW? cc*2 : 1;
    Bs[i] = g_wfrag[(kh*3+kw)*1024 + w_];
  }
  if (tid<32) bias_s[tid]=bias[tid];
  for (int i=tid;i<NROWS*65*8;i+=128){
    int r = i/520, rem = i%520, px = rem>>3, ch = rem&7;
    int hi = hb + r;
    int wi = wb0 + px;
    uint4 v = make_uint4(0,0,0,0);
    if (hi<128 && wi<128)
      v = *(const uint4*)&g_d1h[(((size_t)(b*128+hi))*128+wi)*64 + ch*8];
    *(uint4*)&As[r*ROWB + px*144 + ch*16] = v;
  }
  __syncthreads();

  u32 aSm = smem_u32(As);
  u32 bSm = smem_u32(Bs);
  int lane = tid & 31, wid = tid>>5;
  int g = lane>>2, tig = lane&3;
  float c[4][4];
  #pragma unroll
  for (int ntv=0;ntv<4;ntv++){
    float bA = bias_s[ntv*8+2*tig], bB = bias_s[ntv*8+2*tig+1];
    c[ntv][0]=bA; c[ntv][1]=bB; c[ntv][2]=bA; c[ntv][3]=bB;
  }
  u32 laneRow = (u32)(lane & 15);
  u32 laneCol = (lane & 16) ? 16u : 0u;
  #pragma unroll
  for (int a=0;a<NKH;a++){
    int rtap = PH ? (a==0 ? 1 : 0) : 0;
    #pragma unroll
    for (int cc=0;cc<NKW;cc++){
      int shift = PW ? (cc==0 ? 1 : 0) : 0;
      int tl = a*NKW+cc;
      u32 abase = aSm + rtap*ROWB + (wid*16 + shift + laneRow)*144 + laneCol;
      #pragma unroll
      for (int kt=0;kt<4;kt++){
        u32 a0,a1,a2,a3;
        asm volatile("ldmatrix.sync.aligned.m8n8.x4.shared.b16 {%0,%1,%2,%3}, [%4];"
                     : "=r"(a0),"=r"(a1),"=r"(a2),"=r"(a3)
                     : "r"(abase + kt*32));
        #pragma unroll
        for (int ntv=0;ntv<4;ntv++){
          u32 b0,b1;
          asm volatile("ld.shared.v2.u32 {%0,%1}, [%2];"
                       : "=r"(b0),"=r"(b1)
                       : "r"(bSm + (((tl*4+kt)*4+ntv)*64 + lane*2)*4));
          asm volatile("mma.sync.aligned.m16n8k16.row.col.f32.bf16.bf16.f32 "
                       "{%0,%1,%2,%3}, {%4,%5,%6,%7}, {%8,%9}, {%0,%1,%2,%3};"
                       : "+f"(c[ntv][0]),"+f"(c[ntv][1]),"+f"(c[ntv][2]),"+f"(c[ntv][3])
                       : "r"(a0),"r"(a1),"r"(a2),"r"(a3),"r"(b0),"r"(b1));
        }
      }
    }
  }
  int ho = 2*hb+PH;
  int wbA = wb0 + wid*16 + g, wbB = wbA + 8;
  float* rowBase = g_d2 + ((size_t)(b*256+ho))*256*32;
  float* pA = rowBase + (size_t)(2*wbA+PW)*32 + 2*tig;
  float* pB = rowBase + (size_t)(2*wbB+PW)*32 + 2*tig;
  #pragma unroll
  for (int ntv=0;ntv<4;ntv++){
    float2 vA; vA.x=fmaxf(c[ntv][0],0.f); vA.y=fmaxf(c[ntv][1],0.f);
    float2 vB; vB.x=fmaxf(c[ntv][2],0.f); vB.y=fmaxf(c[ntv][3],0.f);
    *(float2*)(pA + ntv*8) = vA;
    *(float2*)(pB + ntv*8) = vB;
  }
}

// ------------- dec3: convT 32->3 k3 s1 p1 + recon MSE (fused, no store) -----
#define COMPSEL(v,c) ((c)==0 ? (v).x : (c)==1 ? (v).y : (c)==2 ? (v).z : (v).w)
__global__ __launch_bounds__(256) void dec3_k(const float* __restrict__ x,
                                              const float* __restrict__ bias){
  __shared__ __align__(16) u64 ws2[864];
  __shared__ float bs[3];
  int tid = threadIdx.x;
  for (int i=tid;i<864;i+=256){ float w=g_wrd3[i]; ws2[i]=pack2(w,w); }
  if (tid<3) bs[tid]=bias[tid];
  __syncthreads();
  int idx = blockIdx.x*256 + tid;
  int tw = idx & 63, ho = (idx>>6)&255, b = idx>>14;
  int wo0 = tw*4;
  u64 accp[3][2];
  #pragma unroll
  for (int co=0;co<3;co++){ accp[co][0]=pack2(bs[co],bs[co]); accp[co][1]=accp[co][0]; }
  for (int kh=0;kh<3;kh++){
    int hi = ho-1+kh; if ((unsigned)hi>=256u) continue;
    const float* rowp = g_d2 + ((size_t)(b*256+hi))*256*32;
    #pragma unroll 2
    for (int ci4=0;ci4<8;ci4++){
      float4 v[6];
      #pragma unroll
      for (int j=0;j<6;j++){
        int wi = wo0-1+j;
        if ((unsigned)wi<256u) v[j] = ((const float4*)(rowp + (size_t)wi*32))[ci4];
        else v[j] = zero4();
      }
      #pragma unroll
      for (int kw=0;kw<3;kw++){
        #pragma unroll
        for (int c=0;c<4;c++){
          float f0=COMPSEL(v[kw+0],c), f1=COMPSEL(v[kw+1],c);
          float f2=COMPSEL(v[kw+2],c), f3=COMPSEL(v[kw+3],c);
          u64 a0=pack2(f0,f1), a1=pack2(f2,f3);
          const u64* wd = &ws2[((kh*3+kw)*32 + ci4*4 + c)*3];
          u64 w0=wd[0], w1=wd[1], w2=wd[2];
          ffma2(accp[0][0],a0,w0); ffma2(accp[0][1],a1,w0);
          ffma2(accp[1][0],a0,w1); ffma2(accp[1][1],a1,w1);
          ffma2(accp[2][0],a0,w2); ffma2(accp[2][1],a1,w2);
        }
      }
    }
  }
  float acc[4][3];
  #pragma unroll
  for (int co=0;co<3;co++){
    float2 p0=unpack2(accp[co][0]), p1=unpack2(accp[co][1]);
    acc[0][co]=p0.x; acc[1][co]=p0.y; acc[2][co]=p1.x; acc[3][co]=p1.y;
  }
  float ls=0.f;
  const float* xb = x + (size_t)b*3*65536;
  #pragma unroll
  for (int o=0;o<4;o++){
    #pragma unroll
    for (int c=0;c<3;c++){
      float d = acc[o][c] - xb[(size_t)c*65536 + ho*256 + wo0+o];
      ls = fmaf(d,d,ls);
    }
  }
  float s = blockReduceSum(ls);
  if (tid==0) atomicAdd(&g_acc[1], (double)s);
}

// ------------- finalize -----------------------------------------------------
__global__ void final_k(float* __restrict__ out){
  double vq  = g_acc[0];
  double rec = g_acc[1];
  float e_q  = (float)(1.25 * vq / 4194304.0);
  float mse  = (float)(rec / 12582912.0);
  out[0] = e_q;
  out[1] = mse;
  out[2] = mse;
}

// ---------------- launch ----------------------------------------------------
extern "C" void kernel_launch(void* const* d_in, const int* in_sizes, int n_in,
                              void* d_out, int out_size){
  const float* x   = (const float*)d_in[0];
  const float* ew1 = (const float*)d_in[1];
  const float* eb1 = (const float*)d_in[2];
  const float* ew2 = (const float*)d_in[3];
  const float* eb2 = (const float*)d_in[4];
  const float* ew3 = (const float*)d_in[5];
  const float* eb3 = (const float*)d_in[6];
  const float* cb  = (const float*)d_in[7];
  const float* dw1 = (const float*)d_in[8];
  const float* db1 = (const float*)d_in[9];
  const float* dw2 = (const float*)d_in[10];
  const float* db2 = (const float*)d_in[11];
  const float* dw3 = (const float*)d_in[12];
  const float* db3 = (const float*)d_in[13];
  float* out = (float*)d_out;

  repack_k<<<64,256>>>(ew1, ew2, dw1, dw2, dw3);
  enc1_k<<<2048,256>>>(x, eb1);
  enc2_mma_k<<<4096,128>>>(eb2);
  vq_k<<<512,256>>>(cb, ew3, eb3);
  dec1_mma_k<0,0><<<4096,128>>>(db1);
  dec1_mma_k<0,1><<<4096,128>>>(db1);
  dec1_mma_k<1,0><<<4096,128>>>(db1);
  dec1_mma_k<1,1><<<4096,128>>>(db1);
  dec2_mma_k<0,0><<<16384,128>>>(db2);
  dec2_mma_k<0,1><<<16384,128>>>(db2);
  dec2_mma_k<1,0><<<16384,128>>>(db2);
  dec2_mma_k<1,1><<<16384,128>>>(db2);
  dec3_k<<<4096,256>>>(x, db3);
  final_k<<<1,1>>>(out);
}

// round 8
// speedup vs baseline: 2.9778x; 1.2731x over previous
#include <cuda_runtime.h>
#include <cuda_bf16.h>
#include <cstdint>

typedef unsigned long long u64;
typedef unsigned int u32;

// ---------------- scratch (device globals; no allocations allowed) ----------
__device__ unsigned short g_b1h[(size_t)64*128*128*32];  // enc1 out NHWC bf16
__device__ float g_b2[(size_t)64*64*64*64];              // enc2 out NHWC fp32 (exact VQ input)
__device__ unsigned short g_qh[(size_t)64*64*64*16];     // quantized NHWC bf16
__device__ unsigned short g_d1h[(size_t)64*128*128*64];  // dec1 out NHWC bf16
__device__ unsigned short g_d2h[(size_t)64*256*256*32];  // dec2 out NHWC bf16

__device__ float g_wr1 [864];       // enc1 w  [kh][kw][ci=3][co=32]
__device__ u32   g_wfrag2[18432];   // enc2 w  B-frags
__device__ u32   g_wfragd1[4608];   // dec1 w  B-frags
__device__ u32   g_wfrag[9216];     // dec2 w  B-frags
__device__ u32   g_wfragd3[1152];   // dec3 w  B-frags [tap9][kt2][lane32][reg2] (flip baked)
__device__ double g_acc[2];         // [0]=vq sq-sum, [1]=recon sq-sum

// ---------------- helpers ----------------------------------------------------
__device__ __forceinline__ u64 pack2(float lo, float hi){
  u64 r; asm("mov.b64 %0, {%1, %2};" : "=l"(r)
             : "r"(__float_as_uint(lo)), "r"(__float_as_uint(hi)));
  return r;
}
__device__ __forceinline__ u64 bcast2(float v){
  u64 r; asm("mov.b64 %0, {%1, %1};" : "=l"(r) : "r"(__float_as_uint(v)));
  return r;
}
__device__ __forceinline__ float2 unpack2(u64 p){
  unsigned lo, hi;
  asm("mov.b64 {%0, %1}, %2;" : "=r"(lo), "=r"(hi) : "l"(p));
  return make_float2(__uint_as_float(lo), __uint_as_float(hi));
}
__device__ __forceinline__ void ffma2(u64 &acc, u64 a, u64 b){
  asm("fma.rn.f32x2 %0, %1, %2, %0;" : "+l"(acc) : "l"(a), "l"(b));
}
__device__ __forceinline__ float4 zero4(){ float4 z; z.x=z.y=z.z=z.w=0.f; return z; }
__device__ __forceinline__ u32 bfpack(float lo, float hi){
  u32 r; asm("cvt.rn.bf16x2.f32 %0, %1, %2;" : "=r"(r) : "f"(hi), "f"(lo));
  return r;
}
__device__ __forceinline__ u32 smem_u32(const void* p){
  u32 a; asm("{ .reg .u64 t; cvta.to.shared.u64 t, %1; cvt.u32.u64 %0, t; }"
             : "=r"(a) : "l"(p));
  return a;
}

__device__ __forceinline__ float blockReduceSum(float v){
  __shared__ float red[32];
  #pragma unroll
  for (int o=16;o;o>>=1) v += __shfl_down_sync(0xffffffffu, v, o);
  int lane = threadIdx.x & 31, w = threadIdx.x >> 5;
  if (lane==0) red[w]=v;
  __syncthreads();
  if (w==0){
    v = (lane < ((int)blockDim.x>>5)) ? red[lane] : 0.f;
    #pragma unroll
    for (int o=16;o;o>>=1) v += __shfl_down_sync(0xffffffffu, v, o);
  }
  return v;
}

// ---------------- weight repack + accumulator reset -------------------------
__global__ void repack_k(const float* __restrict__ ew1, const float* __restrict__ ew2,
                         const float* __restrict__ dw1, const float* __restrict__ dw2,
                         const float* __restrict__ dw3){
  int t = blockIdx.x*blockDim.x + threadIdx.x;
  int nt = gridDim.x*blockDim.x;
  if (blockIdx.x==0 && threadIdx.x<2) g_acc[threadIdx.x]=0.0;
  for (int i=t;i<864;i+=nt){ int co=i%32; int r=i/32; int ci=r%3; r/=3; int kw=r%3, kh=r/3;
    g_wr1[i] = ew1[((co*3+ci)*3+kh)*3+kw]; }
  // enc2 B-frags: i = tap*1024 + kt*512 + nt*64 + lane*2 + reg
  for (int i=t;i<18432;i+=nt){
    int reg=i&1; int lane=(i>>1)&31; int ntv=(i>>6)&7; int kt=(i>>9)&1; int tap=i>>10;
    int kh=tap/3, kw=tap%3;
    int gg=lane>>2, tg=lane&3;
    int co = ntv*8+gg;
    int ci0 = kt*16 + 2*tg + (reg?8:0);
    float w0 = ew2[((co*32+ci0)*3+kh)*3+kw];
    float w1 = ew2[((co*32+ci0+1)*3+kh)*3+kw];
    g_wfrag2[i] = (u32)__bfloat16_as_ushort(__float2bfloat16(w0))
                | ((u32)__bfloat16_as_ushort(__float2bfloat16(w1))<<16);
  }
  // dec1 B-frags: i = tap*512 + nt*64 + lane*2 + reg
  for (int i=t;i<4608;i+=nt){
    int reg=i&1; int lane=(i>>1)&31; int ntv=(i>>6)&7; int tap=i>>9;
    int kh=tap/3, kw=tap%3;
    int gg=lane>>2, tg=lane&3;
    int co = ntv*8+gg;
    int ci0 = 2*tg + (reg?8:0);
    float w0 = dw1[((ci0*64+co)*3+kh)*3+kw];
    float w1 = dw1[(((ci0+1)*64+co)*3+kh)*3+kw];
    g_wfragd1[i] = (u32)__bfloat16_as_ushort(__float2bfloat16(w0))
                 | ((u32)__bfloat16_as_ushort(__float2bfloat16(w1))<<16);
  }
  // dec2 B-frags: i = tap*1024 + kt*256 + nt*64 + lane*2 + reg
  for (int i=t;i<9216;i+=nt){
    int tap = i>>10; int w_ = i & 1023;
    int reg = w_ & 1; int lane = (w_>>1)&31; int ntv = (w_>>6)&3; int kt = (w_>>8)&3;
    int kh = tap/3, kw = tap%3;
    int gg = lane>>2, tg = lane&3;
    int co = ntv*8+gg;
    int ci0 = kt*16 + 2*tg + (reg?8:0);
    float w0 = dw2[((ci0*32+co)*3+kh)*3+kw];
    float w1 = dw2[(((ci0+1)*32+co)*3+kh)*3+kw];
    g_wfrag[i] = (u32)__bfloat16_as_ushort(__float2bfloat16(w0))
               | ((u32)__bfloat16_as_ushort(__float2bfloat16(w1))<<16);
  }
  // dec3 B-frags (flip baked): i = tap*128 + kt*64 + lane*2 + reg; co=gg (pad >=3 with 0)
  for (int i=t;i<1152;i+=nt){
    int reg=i&1; int lane=(i>>1)&31; int kt=(i>>6)&1; int tap=i>>7;
    int kh=tap/3, kw=tap%3;
    int gg=lane>>2, tg=lane&3;
    int co=gg;
    int ci0 = kt*16 + 2*tg + (reg?8:0);
    float w0=0.f, w1=0.f;
    if (co<3){
      w0 = dw3[((ci0*3+co)*3+(2-kh))*3+(2-kw)];
      w1 = dw3[(((ci0+1)*3+co)*3+(2-kh))*3+(2-kw)];
    }
    g_wfragd3[i] = (u32)__bfloat16_as_ushort(__float2bfloat16(w0))
                 | ((u32)__bfloat16_as_ushort(__float2bfloat16(w1))<<16);
  }
}

// ---------------- enc1: 3->32, k3 s2 p1, relu; 2 px/thread; bf16 out --------
__global__ __launch_bounds__(256) void enc1_k(const float* __restrict__ x,
                                              const float* __restrict__ bias){
  __shared__ __align__(16) float ws[864];
  __shared__ float bs[32];
  int tid = threadIdx.x;
  for (int i=tid;i<864;i+=256) ws[i]=g_wr1[i];
  if (tid<32) bs[tid]=bias[tid];
  __syncthreads();
  int idx = blockIdx.x*256 + tid;
  int tw = idx & 63, ho = (idx>>6)&127, b = idx>>13;
  u64 acc[2][16];
  #pragma unroll
  for (int c=0;c<16;c++){ acc[0][c]=pack2(bs[2*c],bs[2*c+1]); acc[1][c]=acc[0][c]; }
  const float* xb = x + (size_t)b*3*65536;
  for (int kh=0;kh<3;kh++){
    int hi = 2*ho-1+kh; bool inh = (unsigned)hi<256u;
    for (int kw=0;kw<3;kw++){
      int wi0 = 4*tw-1+kw, wi1 = wi0+2;
      bool in0 = inh && (unsigned)wi0<256u;
      bool in1 = inh && (unsigned)wi1<256u;
      #pragma unroll
      for (int ci=0;ci<3;ci++){
        float f0 = in0 ? xb[(size_t)ci*65536 + hi*256 + wi0] : 0.f;
        float f1 = in1 ? xb[(size_t)ci*65536 + hi*256 + wi1] : 0.f;
        u64 v0=bcast2(f0), v1=bcast2(f1);
        const ulonglong2* wp = (const ulonglong2*)&ws[((kh*3+kw)*3+ci)*32];
        #pragma unroll
        for (int q=0;q<8;q++){
          ulonglong2 t=wp[q];
          ffma2(acc[0][2*q],v0,t.x); ffma2(acc[0][2*q+1],v0,t.y);
          ffma2(acc[1][2*q],v1,t.x); ffma2(acc[1][2*q+1],v1,t.y);
        }
      }
    }
  }
  unsigned short* op = g_b1h + (size_t)(2*idx)*32;
  #pragma unroll
  for (int p=0;p<2;p++){
    u32 pk[16];
    #pragma unroll
    for (int c=0;c<16;c++){
      float2 f = unpack2(acc[p][c]);
      pk[c] = bfpack(fmaxf(f.x,0.f), fmaxf(f.y,0.f));
    }
    #pragma unroll
    for (int q=0;q<4;q++)
      ((uint4*)op)[p*4+q] = make_uint4(pk[4*q],pk[4*q+1],pk[4*q+2],pk[4*q+3]);
  }
}

// ---------------- enc2: 32->64 k3 s2 p1 relu via mma bf16 (R7) --------------
__global__ __launch_bounds__(128) void enc2_mma_k(const float* __restrict__ bias){
  constexpr int ROWB = 129*80;
  __shared__ __align__(16) unsigned char As[3*ROWB];
  __shared__ float bias_s[64];
  int tid = threadIdx.x, bx = blockIdx.x;
  int ho = bx & 63, b = bx >> 6;
  if (tid<64) bias_s[tid]=bias[tid];
  for (int i=tid;i<3*129*4;i+=128){
    int r=i/516, rem=i%516, px=rem>>2, ch=rem&3;
    int hi=2*ho-1+r, wi=px-1;
    uint4 v=make_uint4(0,0,0,0);
    if ((unsigned)hi<128u && (unsigned)wi<128u)
      v = *(const uint4*)&g_b1h[(((size_t)(b*128+hi))*128+wi)*32 + ch*8];
    *(uint4*)&As[r*ROWB + px*80 + ch*16] = v;
  }
  __syncthreads();
  u32 aSm = smem_u32(As);
  int lane = tid&31, wid = tid>>5;
  int g = lane>>2, tig = lane&3;
  float c[8][4];
  #pragma unroll
  for (int ntv=0;ntv<8;ntv++){
    float bA=bias_s[ntv*8+2*tig], bB=bias_s[ntv*8+2*tig+1];
    c[ntv][0]=bA; c[ntv][1]=bB; c[ntv][2]=bA; c[ntv][3]=bB;
  }
  u32 laneRow = (u32)(lane & 15);
  u32 laneCol = (lane & 16) ? 16u : 0u;
  #pragma unroll
  for (int kh=0;kh<3;kh++){
    #pragma unroll
    for (int kw=0;kw<3;kw++){
      int tap = kh*3+kw;
      #pragma unroll
      for (int kt=0;kt<2;kt++){
        u32 abase = aSm + kh*ROWB + (wid*32 + 2*laneRow + kw)*80 + kt*32 + laneCol;
        u32 a0,a1,a2,a3;
        asm volatile("ldmatrix.sync.aligned.m8n8.x4.shared.b16 {%0,%1,%2,%3}, [%4];"
                     : "=r"(a0),"=r"(a1),"=r"(a2),"=r"(a3) : "r"(abase));
        #pragma unroll
        for (int ntv=0;ntv<8;ntv++){
          uint2 bv = *(const uint2*)&g_wfrag2[tap*1024 + kt*512 + ntv*64 + lane*2];
          asm volatile("mma.sync.aligned.m16n8k16.row.col.f32.bf16.bf16.f32 "
                       "{%0,%1,%2,%3}, {%4,%5,%6,%7}, {%8,%9}, {%0,%1,%2,%3};"
                       : "+f"(c[ntv][0]),"+f"(c[ntv][1]),"+f"(c[ntv][2]),"+f"(c[ntv][3])
                       : "r"(a0),"r"(a1),"r"(a2),"r"(a3),"r"(bv.x),"r"(bv.y));
        }
      }
    }
  }
  int woA = wid*16+g, woB = woA+8;
  float* base = g_b2 + ((size_t)(b*64+ho))*64*64;
  float* pA = base + (size_t)woA*64 + 2*tig;
  float* pB = base + (size_t)woB*64 + 2*tig;
  #pragma unroll
  for (int ntv=0;ntv<8;ntv++){
    float2 vA; vA.x=fmaxf(c[ntv][0],0.f); vA.y=fmaxf(c[ntv][1],0.f);
    float2 vB; vB.x=fmaxf(c[ntv][2],0.f); vB.y=fmaxf(c[ntv][3],0.f);
    *(float2*)(pA + ntv*8) = vA;
    *(float2*)(pB + ntv*8) = vB;
  }
}

// ------------- enc3 (1x1 64->16) + VQ + quantize(bf16) + VQ loss (R7) -------
__global__ __launch_bounds__(256) void vq_k(const float* __restrict__ cb,
                                            const float* __restrict__ w3,
                                            const float* __restrict__ b3){
  __shared__ __align__(16) float cbs[8192];
  __shared__ float nrm[512];
  __shared__ __align__(16) float w3s[1024];
  __shared__ float b3s[16];
  int tid = threadIdx.x;
  for (int i=tid;i<8192;i+=256) cbs[i]=cb[i];
  for (int i=tid;i<1024;i+=256){ int ci=i>>4, d=i&15; w3s[i]=w3[d*64+ci]; }
  if (tid<16) b3s[tid]=b3[tid];
  __syncthreads();
  for (int k=tid;k<512;k+=256){
    float s=0.f;
    #pragma unroll
    for (int d=0;d<16;d++){ float e=cbs[k*16+d]; s=fmaf(e,e,s); }
    nrm[k]=0.5f*s;
  }
  __syncthreads();
  int idx = blockIdx.x*256 + tid;
  u64 z2[2][8];
  #pragma unroll
  for (int q=0;q<8;q++){ z2[0][q]=pack2(b3s[2*q],b3s[2*q+1]); z2[1][q]=z2[0][q]; }
  const float4* ip0 = (const float4*)(g_b2 + (size_t)(2*idx)*64);
  const float4* ip1 = ip0 + 16;
  #pragma unroll 4
  for (int ci4=0;ci4<16;ci4++){
    float4 v0 = ip0[ci4], v1 = ip1[ci4];
    float a[4]={v0.x,v0.y,v0.z,v0.w}, bb[4]={v1.x,v1.y,v1.z,v1.w};
    #pragma unroll
    for (int j=0;j<4;j++){
      u64 vb0 = bcast2(a[j]), vb1 = bcast2(bb[j]);
      const ulonglong2* wp = (const ulonglong2*)&w3s[(ci4*4+j)*16];
      #pragma unroll
      for (int q=0;q<4;q++){ ulonglong2 t=wp[q];
        ffma2(z2[0][2*q],vb0,t.x); ffma2(z2[0][2*q+1],vb0,t.y);
        ffma2(z2[1][2*q],vb1,t.x); ffma2(z2[1][2*q+1],vb1,t.y); }
    }
  }
  int best0=0, best1=0; float bs0=-3.4e38f, bs1=-3.4e38f;
  for (int k=0;k<512;k++){
    const ulonglong2* e2 = (const ulonglong2*)&cbs[k*16];
    ulonglong2 t0=e2[0], t1=e2[1], t2=e2[2], t3=e2[3];
    u64 sa0=0ull, sb0=0ull, sa1=0ull, sb1=0ull;
    ffma2(sa0,z2[0][0],t0.x); ffma2(sb0,z2[0][4],t2.x);
    ffma2(sa1,z2[1][0],t0.x); ffma2(sb1,z2[1][4],t2.x);
    ffma2(sa0,z2[0][1],t0.y); ffma2(sb0,z2[0][5],t2.y);
    ffma2(sa1,z2[1][1],t0.y); ffma2(sb1,z2[1][5],t2.y);
    ffma2(sa0,z2[0][2],t1.x); ffma2(sb0,z2[0][6],t3.x);
    ffma2(sa1,z2[1][2],t1.x); ffma2(sb1,z2[1][6],t3.x);
    ffma2(sa0,z2[0][3],t1.y); ffma2(sb0,z2[0][7],t3.y);
    ffma2(sa1,z2[1][3],t1.y); ffma2(sb1,z2[1][7],t3.y);
    float2 pa0=unpack2(sa0), pb0=unpack2(sb0);
    float2 pa1=unpack2(sa1), pb1=unpack2(sb1);
    float nk = nrm[k];
    float s0 = (pa0.x + pa0.y) + (pb0.x + pb0.y) - nk;
    float s1 = (pa1.x + pa1.y) + (pb1.x + pb1.y) - nk;
    if (s0>bs0){ bs0=s0; best0=k; }
    if (s1>bs1){ bs1=s1; best1=k; }
  }
  float ls=0.f;
  int bests[2]={best0,best1};
  #pragma unroll
  for (int p=0;p<2;p++){
    const float* e = &cbs[bests[p]*16];
    unsigned short* qo = g_qh + (size_t)(2*idx+p)*16;
    u32 pk[8];
    #pragma unroll
    for (int d4=0;d4<4;d4++){
      float e0=e[d4*4+0], e1=e[d4*4+1], e2v=e[d4*4+2], e3v=e[d4*4+3];
      pk[2*d4]   = bfpack(e0,e1);
      pk[2*d4+1] = bfpack(e2v,e3v);
      float2 za=unpack2(z2[p][d4*2]), zb=unpack2(z2[p][d4*2+1]);
      float d0=e0-za.x, d1=e1-za.y, d2=e2v-zb.x, d3=e3v-zb.y;
      ls = fmaf(d0,d0, fmaf(d1,d1, fmaf(d2,d2, fmaf(d3,d3, ls))));
    }
    ((uint4*)qo)[0] = make_uint4(pk[0],pk[1],pk[2],pk[3]);
    ((uint4*)qo)[1] = make_uint4(pk[4],pk[5],pk[6],pk[7]);
  }
  float s = blockReduceSum(ls);
  if (tid==0) atomicAdd(&g_acc[0], (double)s);
}

// ------------- dec1: convT 16->64 via mma bf16 (R7) -------------------------
template<int PH,int PW>
__global__ __launch_bounds__(128) void dec1_mma_k(const float* __restrict__ bias){
  constexpr int NKH = PH?2:1, NKW = PW?2:1, NROWS = PH?2:1;
  constexpr int ROWB = 65*48;
  __shared__ __align__(16) unsigned char As[NROWS*ROWB];
  __shared__ __align__(16) u32 Bs[NKH*NKW*512];
  __shared__ float bias_s[64];
  int tid = threadIdx.x, bx = blockIdx.x;
  int hb = bx & 63, b = bx >> 6;
  for (int i=tid;i<NKH*NKW*512;i+=128){
    int tl=i>>9, w_=i&511;
    int a=tl/NKW, cc=tl%NKW;
    int kh=PH?a*2:1, kw=PW?cc*2:1;
    Bs[i]=g_wfragd1[(kh*3+kw)*512+w_];
  }
  if (tid<64) bias_s[tid]=bias[tid];
  for (int i=tid;i<NROWS*65*2;i+=128){
    int r=i/130, rem=i%130, px=rem>>1, hf=rem&1;
    int hi=hb+r;
    uint4 v=make_uint4(0,0,0,0);
    if (hi<64 && px<64)
      v=*(const uint4*)&g_qh[(((size_t)(b*64+hi))*64+px)*16 + hf*8];
    *(uint4*)&As[r*ROWB+px*48+hf*16]=v;
  }
  __syncthreads();
  u32 aSm = smem_u32(As);
  u32 bSm = smem_u32(Bs);
  int lane = tid&31, wid = tid>>5;
  int g = lane>>2, tig = lane&3;
  float c[8][4];
  #pragma unroll
  for (int ntv=0;ntv<8;ntv++){
    float bA=bias_s[ntv*8+2*tig], bB=bias_s[ntv*8+2*tig+1];
    c[ntv][0]=bA; c[ntv][1]=bB; c[ntv][2]=bA; c[ntv][3]=bB;
  }
  u32 laneRow = (u32)(lane & 15);
  u32 laneCol = (lane & 16) ? 16u : 0u;
  #pragma unroll
  for (int a=0;a<NKH;a++){
    int rtap = PH ? (a==0 ? 1 : 0) : 0;
    #pragma unroll
    for (int cc=0;cc<NKW;cc++){
      int shift = PW ? (cc==0 ? 1 : 0) : 0;
      int tl = a*NKW+cc;
      u32 abase = aSm + rtap*ROWB + (wid*16 + shift + laneRow)*48 + laneCol;
      u32 a0,a1,a2,a3;
      asm volatile("ldmatrix.sync.aligned.m8n8.x4.shared.b16 {%0,%1,%2,%3}, [%4];"
                   : "=r"(a0),"=r"(a1),"=r"(a2),"=r"(a3) : "r"(abase));
      #pragma unroll
      for (int ntv=0;ntv<8;ntv++){
        u32 b0,b1;
        asm volatile("ld.shared.v2.u32 {%0,%1}, [%2];"
                     : "=r"(b0),"=r"(b1)
                     : "r"(bSm + ((tl*8+ntv)*64 + lane*2)*4));
        asm volatile("mma.sync.aligned.m16n8k16.row.col.f32.bf16.bf16.f32 "
                     "{%0,%1,%2,%3}, {%4,%5,%6,%7}, {%8,%9}, {%0,%1,%2,%3};"
                     : "+f"(c[ntv][0]),"+f"(c[ntv][1]),"+f"(c[ntv][2]),"+f"(c[ntv][3])
                     : "r"(a0),"r"(a1),"r"(a2),"r"(a3),"r"(b0),"r"(b1));
      }
    }
  }
  int ho = 2*hb+PH;
  int wbA = wid*16+g, wbB = wbA+8;
  unsigned short* rb = g_d1h + ((size_t)(b*128+ho))*128*64;
  unsigned short* pA = rb + (size_t)(2*wbA+PW)*64 + 2*tig;
  unsigned short* pB = rb + (size_t)(2*wbB+PW)*64 + 2*tig;
  #pragma unroll
  for (int ntv=0;ntv<8;ntv++){
    *(u32*)(pA + ntv*8) = bfpack(fmaxf(c[ntv][0],0.f), fmaxf(c[ntv][1],0.f));
    *(u32*)(pB + ntv*8) = bfpack(fmaxf(c[ntv][2],0.f), fmaxf(c[ntv][3],0.f));
  }
}

// ------------- dec2: convT 64->32 via mma bf16; bf16 output -----------------
template<int PH,int PW>
__global__ __launch_bounds__(128) void dec2_mma_k(const float* __restrict__ bias){
  constexpr int NKH = PH?2:1, NKW = PW?2:1, NROWS = PH?2:1;
  constexpr int ROWB = 65*144;
  __shared__ __align__(16) unsigned char As[NROWS*ROWB];
  __shared__ __align__(16) u32 Bs[NKH*NKW*1024];
  __shared__ float bias_s[32];
  int tid = threadIdx.x;
  int bx = blockIdx.x;
  int wchunk = bx & 1, hb = (bx>>1)&127, b = bx>>8;
  int wb0 = wchunk*64;
  for (int i=tid;i<NKH*NKW*1024;i+=128){
    int tl = i>>10, w_ = i & 1023;
    int a = tl/NKW, cc = tl%NKW;
    int kh = PH? a*2 : 1, kw = PW? cc*2 : 1;
    Bs[i] = g_wfrag[(kh*3+kw)*1024 + w_];
  }
  if (tid<32) bias_s[tid]=bias[tid];
  for (int i=tid;i<NROWS*65*8;i+=128){
    int r = i/520, rem = i%520, px = rem>>3, ch = rem&7;
    int hi = hb + r;
    int wi = wb0 + px;
    uint4 v = make_uint4(0,0,0,0);
    if (hi<128 && wi<128)
      v = *(const uint4*)&g_d1h[(((size_t)(b*128+hi))*128+wi)*64 + ch*8];
    *(uint4*)&As[r*ROWB + px*144 + ch*16] = v;
  }
  __syncthreads();

  u32 aSm = smem_u32(As);
  u32 bSm = smem_u32(Bs);
  int lane = tid & 31, wid = tid>>5;
  int g = lane>>2, tig = lane&3;
  float c[4][4];
  #pragma unroll
  for (int ntv=0;ntv<4;ntv++){
    float bA = bias_s[ntv*8+2*tig], bB = bias_s[ntv*8+2*tig+1];
    c[ntv][0]=bA; c[ntv][1]=bB; c[ntv][2]=bA; c[ntv][3]=bB;
  }
  u32 laneRow = (u32)(lane & 15);
  u32 laneCol = (lane & 16) ? 16u : 0u;
  #pragma unroll
  for (int a=0;a<NKH;a++){
    int rtap = PH ? (a==0 ? 1 : 0) : 0;
    #pragma unroll
    for (int cc=0;cc<NKW;cc++){
      int shift = PW ? (cc==0 ? 1 : 0) : 0;
      int tl = a*NKW+cc;
      u32 abase = aSm + rtap*ROWB + (wid*16 + shift + laneRow)*144 + laneCol;
      #pragma unroll
      for (int kt=0;kt<4;kt++){
        u32 a0,a1,a2,a3;
        asm volatile("ldmatrix.sync.aligned.m8n8.x4.shared.b16 {%0,%1,%2,%3}, [%4];"
                     : "=r"(a0),"=r"(a1),"=r"(a2),"=r"(a3)
                     : "r"(abase + kt*32));
        #pragma unroll
        for (int ntv=0;ntv<4;ntv++){
          u32 b0,b1;
          asm volatile("ld.shared.v2.u32 {%0,%1}, [%2];"
                       : "=r"(b0),"=r"(b1)
                       : "r"(bSm + (((tl*4+kt)*4+ntv)*64 + lane*2)*4));
          asm volatile("mma.sync.aligned.m16n8k16.row.col.f32.bf16.bf16.f32 "
                       "{%0,%1,%2,%3}, {%4,%5,%6,%7}, {%8,%9}, {%0,%1,%2,%3};"
                       : "+f"(c[ntv][0]),"+f"(c[ntv][1]),"+f"(c[ntv][2]),"+f"(c[ntv][3])
                       : "r"(a0),"r"(a1),"r"(a2),"r"(a3),"r"(b0),"r"(b1));
        }
      }
    }
  }
  int ho = 2*hb+PH;
  int wbA = wb0 + wid*16 + g, wbB = wbA + 8;
  unsigned short* rowBase = g_d2h + ((size_t)(b*256+ho))*256*32;
  unsigned short* pA = rowBase + (size_t)(2*wbA+PW)*32 + 2*tig;
  unsigned short* pB = rowBase + (size_t)(2*wbB+PW)*32 + 2*tig;
  #pragma unroll
  for (int ntv=0;ntv<4;ntv++){
    *(u32*)(pA + ntv*8) = bfpack(fmaxf(c[ntv][0],0.f), fmaxf(c[ntv][1],0.f));
    *(u32*)(pB + ntv*8) = bfpack(fmaxf(c[ntv][2],0.f), fmaxf(c[ntv][3],0.f));
  }
}

// ------------- dec3: conv 32->3 via mma bf16 + fused recon MSE --------------
// Block 128 thr (4 warps x 16 px). Grid: 64b x 256ho x 4 wchunks.
__global__ __launch_bounds__(128) void dec3_mma_k(const float* __restrict__ x,
                                                  const float* __restrict__ bias){
  constexpr int PXB = 80;
  __shared__ __align__(16) unsigned char As[3*66*PXB];
  __shared__ __align__(16) u32 Bs[1152];
  __shared__ float bias_s[3];
  int tid = threadIdx.x, bx = blockIdx.x;
  int wchunk = bx & 3, ho = (bx>>2)&255, b = bx>>10;
  int wb0 = wchunk*64;
  for (int i=tid;i<1152;i+=128) Bs[i]=g_wfragd3[i];
  if (tid<3) bias_s[tid]=bias[tid];
  for (int i=tid;i<3*66*4;i+=128){
    int r=i/264, rem=i%264, px=rem>>2, q=rem&3;
    int hi=ho-1+r, wi=wb0-1+px;
    uint4 v=make_uint4(0,0,0,0);
    if ((unsigned)hi<256u && (unsigned)wi<256u)
      v=*(const uint4*)&g_d2h[(((size_t)(b*256+hi))*256+wi)*32 + q*8];
    *(uint4*)&As[(r*66+px)*PXB + q*16]=v;
  }
  __syncthreads();
  u32 aSm=smem_u32(As), bSm=smem_u32(Bs);
  int lane=tid&31, wid=tid>>5;
  int g=lane>>2, tig=lane&3;
  float c[4]={0.f,0.f,0.f,0.f};
  u32 laneRow=(u32)(lane&15);
  u32 laneCol=(lane&16)?16u:0u;
  #pragma unroll
  for (int kh=0;kh<3;kh++){
    #pragma unroll
    for (int kw=0;kw<3;kw++){
      int tap=kh*3+kw;
      u32 abase = aSm + (u32)(kh*66 + wid*16 + kw + laneRow)*PXB + laneCol;
      #pragma unroll
      for (int kt=0;kt<2;kt++){
        u32 a0,a1,a2,a3;
        asm volatile("ldmatrix.sync.aligned.m8n8.x4.shared.b16 {%0,%1,%2,%3}, [%4];"
                     : "=r"(a0),"=r"(a1),"=r"(a2),"=r"(a3) : "r"(abase + kt*32));
        u32 b0,b1;
        asm volatile("ld.shared.v2.u32 {%0,%1}, [%2];"
                     : "=r"(b0),"=r"(b1)
                     : "r"(bSm + ((tap*2+kt)*64 + lane*2)*4));
        asm volatile("mma.sync.aligned.m16n8k16.row.col.f32.bf16.bf16.f32 "
                     "{%0,%1,%2,%3}, {%4,%5,%6,%7}, {%8,%9}, {%0,%1,%2,%3};"
                     : "+f"(c[0]),"+f"(c[1]),"+f"(c[2]),"+f"(c[3])
                     : "r"(a0),"r"(a1),"r"(a2),"r"(a3),"r"(b0),"r"(b1));
      }
    }
  }
  // epilogue: px rows g, g+8; co = 2*tig, 2*tig+1 (only co<3 valid)
  int pxA = wb0 + wid*16 + g, pxB = pxA + 8;
  const float* xb = x + (size_t)b*3*65536 + ho*256;
  float ls = 0.f;
  int co0 = 2*tig, co1 = co0+1;
  if (co0 < 3){
    float d0 = c[0] + bias_s[co0] - xb[(size_t)co0*65536 + pxA];
    float d1 = c[2] + bias_s[co0] - xb[(size_t)co0*65536 + pxB];
    ls = fmaf(d0,d0, fmaf(d1,d1, ls));
  }
  if (co1 < 3){
    float d0 = c[1] + bias_s[co1] - xb[(size_t)co1*65536 + pxA];
    float d1 = c[3] + bias_s[co1] - xb[(size_t)co1*65536 + pxB];
    ls = fmaf(d0,d0, fmaf(d1,d1, ls));
  }
  float s = blockReduceSum(ls);
  if (tid==0) atomicAdd(&g_acc[1], (double)s);
}

// ------------- finalize -----------------------------------------------------
__global__ void final_k(float* __restrict__ out){
  double vq  = g_acc[0];
  double rec = g_acc[1];
  float e_q  = (float)(1.25 * vq / 4194304.0);
  float mse  = (float)(rec / 12582912.0);
  out[0] = e_q;
  out[1] = mse;
  out[2] = mse;
}

// ---------------- launch ----------------------------------------------------
extern "C" void kernel_launch(void* const* d_in, const int* in_sizes, int n_in,
                              void* d_out, int out_size){
  const float* x   = (const float*)d_in[0];
  const float* ew1 = (const float*)d_in[1];
  const float* eb1 = (const float*)d_in[2];
  const float* ew2 = (const float*)d_in[3];
  const float* eb2 = (const float*)d_in[4];
  const float* ew3 = (const float*)d_in[5];
  const float* eb3 = (const float*)d_in[6];
  const float* cb  = (const float*)d_in[7];
  const float* dw1 = (const float*)d_in[8];
  const float* db1 = (const float*)d_in[9];
  const float* dw2 = (const float*)d_in[10];
  const float* db2 = (const float*)d_in[11];
  const float* dw3 = (const float*)d_in[12];
  const float* db3 = (const float*)d_in[13];
  float* out = (float*)d_out;

  repack_k<<<64,256>>>(ew1, ew2, dw1, dw2, dw3);
  enc1_k<<<2048,256>>>(x, eb1);
  enc2_mma_k<<<4096,128>>>(eb2);
  vq_k<<<512,256>>>(cb, ew3, eb3);
  dec1_mma_k<0,0><<<4096,128>>>(db1);
  dec1_mma_k<0,1><<<4096,128>>>(db1);
  dec1_mma_k<1,0><<<4096,128>>>(db1);
  dec1_mma_k<1,1><<<4096,128>>>(db1);
  dec2_mma_k<0,0><<<16384,128>>>(db2);
  dec2_mma_k<0,1><<<16384,128>>>(db2);
  dec2_mma_k<1,0><<<16384,128>>>(db2);
  dec2_mma_k<1,1><<<16384,128>>>(db2);
  dec3_mma_k<<<65536,128>>>(x, db3);
  final_k<<<1,1>>>(out);
}

// round 9
// speedup vs baseline: 3.3339x; 1.1196x over previous
#include <cuda_runtime.h>
#include <cuda_bf16.h>
#include <cstdint>

typedef unsigned long long u64;
typedef unsigned int u32;

// ---------------- scratch (device globals; no allocations allowed) ----------
__device__ unsigned short g_b1h[(size_t)64*128*128*32];  // enc1 out NHWC bf16
__device__ unsigned short g_b2h[(size_t)64*64*64*64];    // enc2 out NHWC bf16
__device__ unsigned short g_qh[(size_t)64*64*64*16];     // quantized NHWC bf16
__device__ unsigned short g_d1h[(size_t)64*128*128*64];  // dec1 out NHWC bf16
__device__ unsigned short g_d2h[(size_t)64*256*256*32];  // dec2 out NHWC bf16

__device__ float g_wr1 [864];       // enc1 w  [kh][kw][ci=3][co=32]
__device__ u32   g_wfrag2[18432];   // enc2 w  B-frags
__device__ u32   g_wfragd1[4608];   // dec1 w  B-frags
__device__ u32   g_wfrag[9216];     // dec2 w  B-frags
__device__ u32   g_wfragd3[1152];   // dec3 w  B-frags (flip baked)
__device__ u32   g_wfragw3[512];    // enc3(1x1) w B-frags [kt4][nt2][lane32][reg2]
__device__ u32   g_wfragcb[4096];   // codebook B-frags [chunk64][lane32][reg2]
__device__ float g_nrm[512];        // 0.5*||e_k||^2 (fp32)
__device__ double g_acc[2];         // [0]=vq sq-sum, [1]=recon sq-sum

// ---------------- helpers ----------------------------------------------------
__device__ __forceinline__ u64 pack2(float lo, float hi){
  u64 r; asm("mov.b64 %0, {%1, %2};" : "=l"(r)
             : "r"(__float_as_uint(lo)), "r"(__float_as_uint(hi)));
  return r;
}
__device__ __forceinline__ u64 bcast2(float v){
  u64 r; asm("mov.b64 %0, {%1, %1};" : "=l"(r) : "r"(__float_as_uint(v)));
  return r;
}
__device__ __forceinline__ float2 unpack2(u64 p){
  unsigned lo, hi;
  asm("mov.b64 {%0, %1}, %2;" : "=r"(lo), "=r"(hi) : "l"(p));
  return make_float2(__uint_as_float(lo), __uint_as_float(hi));
}
__device__ __forceinline__ void ffma2(u64 &acc, u64 a, u64 b){
  asm("fma.rn.f32x2 %0, %1, %2, %0;" : "+l"(acc) : "l"(a), "l"(b));
}
__device__ __forceinline__ float4 zero4(){ float4 z; z.x=z.y=z.z=z.w=0.f; return z; }
__device__ __forceinline__ u32 bfpack(float lo, float hi){
  u32 r; asm("cvt.rn.bf16x2.f32 %0, %1, %2;" : "=r"(r) : "f"(hi), "f"(lo));
  return r;
}
__device__ __forceinline__ u32 smem_u32(const void* p){
  u32 a; asm("{ .reg .u64 t; cvta.to.shared.u64 t, %1; cvt.u32.u64 %0, t; }"
             : "=r"(a) : "l"(p));
  return a;
}

__device__ __forceinline__ float blockReduceSum(float v){
  __shared__ float red[32];
  #pragma unroll
  for (int o=16;o;o>>=1) v += __shfl_down_sync(0xffffffffu, v, o);
  int lane = threadIdx.x & 31, w = threadIdx.x >> 5;
  if (lane==0) red[w]=v;
  __syncthreads();
  if (w==0){
    v = (lane < ((int)blockDim.x>>5)) ? red[lane] : 0.f;
    #pragma unroll
    for (int o=16;o;o>>=1) v += __shfl_down_sync(0xffffffffu, v, o);
  }
  return v;
}

// ---------------- weight repack + accumulator reset -------------------------
__global__ void repack_k(const float* __restrict__ ew1, const float* __restrict__ ew2,
                         const float* __restrict__ dw1, const float* __restrict__ dw2,
                         const float* __restrict__ dw3, const float* __restrict__ w3,
                         const float* __restrict__ cb){
  int t = blockIdx.x*blockDim.x + threadIdx.x;
  int nt = gridDim.x*blockDim.x;
  if (blockIdx.x==0 && threadIdx.x<2) g_acc[threadIdx.x]=0.0;
  for (int i=t;i<864;i+=nt){ int co=i%32; int r=i/32; int ci=r%3; r/=3; int kw=r%3, kh=r/3;
    g_wr1[i] = ew1[((co*3+ci)*3+kh)*3+kw]; }
  // enc2 B-frags
  for (int i=t;i<18432;i+=nt){
    int reg=i&1; int lane=(i>>1)&31; int ntv=(i>>6)&7; int kt=(i>>9)&1; int tap=i>>10;
    int kh=tap/3, kw=tap%3;
    int gg=lane>>2, tg=lane&3;
    int co = ntv*8+gg;
    int ci0 = kt*16 + 2*tg + (reg?8:0);
    float w0 = ew2[((co*32+ci0)*3+kh)*3+kw];
    float w1 = ew2[((co*32+ci0+1)*3+kh)*3+kw];
    g_wfrag2[i] = (u32)__bfloat16_as_ushort(__float2bfloat16(w0))
                | ((u32)__bfloat16_as_ushort(__float2bfloat16(w1))<<16);
  }
  // dec1 B-frags
  for (int i=t;i<4608;i+=nt){
    int reg=i&1; int lane=(i>>1)&31; int ntv=(i>>6)&7; int tap=i>>9;
    int kh=tap/3, kw=tap%3;
    int gg=lane>>2, tg=lane&3;
    int co = ntv*8+gg;
    int ci0 = 2*tg + (reg?8:0);
    float w0 = dw1[((ci0*64+co)*3+kh)*3+kw];
    float w1 = dw1[(((ci0+1)*64+co)*3+kh)*3+kw];
    g_wfragd1[i] = (u32)__bfloat16_as_ushort(__float2bfloat16(w0))
                 | ((u32)__bfloat16_as_ushort(__float2bfloat16(w1))<<16);
  }
  // dec2 B-frags
  for (int i=t;i<9216;i+=nt){
    int tap = i>>10; int w_ = i & 1023;
    int reg = w_ & 1; int lane = (w_>>1)&31; int ntv = (w_>>6)&3; int kt = (w_>>8)&3;
    int kh = tap/3, kw = tap%3;
    int gg = lane>>2, tg = lane&3;
    int co = ntv*8+gg;
    int ci0 = kt*16 + 2*tg + (reg?8:0);
    float w0 = dw2[((ci0*32+co)*3+kh)*3+kw];
    float w1 = dw2[(((ci0+1)*32+co)*3+kh)*3+kw];
    g_wfrag[i] = (u32)__bfloat16_as_ushort(__float2bfloat16(w0))
               | ((u32)__bfloat16_as_ushort(__float2bfloat16(w1))<<16);
  }
  // dec3 B-frags (flip baked)
  for (int i=t;i<1152;i+=nt){
    int reg=i&1; int lane=(i>>1)&31; int kt=(i>>6)&1; int tap=i>>7;
    int kh=tap/3, kw=tap%3;
    int gg=lane>>2, tg=lane&3;
    int co=gg;
    int ci0 = kt*16 + 2*tg + (reg?8:0);
    float w0=0.f, w1=0.f;
    if (co<3){
      w0 = dw3[((ci0*3+co)*3+(2-kh))*3+(2-kw)];
      w1 = dw3[(((ci0+1)*3+co)*3+(2-kh))*3+(2-kw)];
    }
    g_wfragd3[i] = (u32)__bfloat16_as_ushort(__float2bfloat16(w0))
                 | ((u32)__bfloat16_as_ushort(__float2bfloat16(w1))<<16);
  }
  // enc3 (1x1) w3 B-frags: i = kt*128 + ntv*64 + lane*2 + reg
  for (int i=t;i<512;i+=nt){
    int reg=i&1; int lane=(i>>1)&31; int ntv=(i>>6)&1; int kt=i>>7;
    int gg=lane>>2, tg=lane&3;
    int d = ntv*8+gg;
    int ci0 = kt*16 + 2*tg + (reg?8:0);
    float w0 = w3[d*64+ci0];
    float w1 = w3[d*64+ci0+1];
    g_wfragw3[i] = (u32)__bfloat16_as_ushort(__float2bfloat16(w0))
                 | ((u32)__bfloat16_as_ushort(__float2bfloat16(w1))<<16);
  }
  // codebook B-frags: i = chunk*64 + lane*2 + reg ; n=cw=chunk*8+gg, k=d
  for (int i=t;i<4096;i+=nt){
    int reg=i&1; int lane=(i>>1)&31; int chunk=i>>6;
    int gg=lane>>2, tg=lane&3;
    int cw = chunk*8+gg;
    int d0 = 2*tg + (reg?8:0);
    float w0 = cb[cw*16+d0];
    float w1 = cb[cw*16+d0+1];
    g_wfragcb[i] = (u32)__bfloat16_as_ushort(__float2bfloat16(w0))
                 | ((u32)__bfloat16_as_ushort(__float2bfloat16(w1))<<16);
  }
  // codebook half-norms (fp32)
  for (int k=t;k<512;k+=nt){
    float s=0.f;
    #pragma unroll
    for (int d=0;d<16;d++){ float e=cb[k*16+d]; s=fmaf(e,e,s); }
    g_nrm[k]=0.5f*s;
  }
}

// ---------------- enc1: 3->32, k3 s2 p1, relu; 2 px/thread; bf16 out --------
__global__ __launch_bounds__(256) void enc1_k(const float* __restrict__ x,
                                              const float* __restrict__ bias){
  __shared__ __align__(16) float ws[864];
  __shared__ float bs[32];
  int tid = threadIdx.x;
  for (int i=tid;i<864;i+=256) ws[i]=g_wr1[i];
  if (tid<32) bs[tid]=bias[tid];
  __syncthreads();
  int idx = blockIdx.x*256 + tid;
  int tw = idx & 63, ho = (idx>>6)&127, b = idx>>13;
  u64 acc[2][16];
  #pragma unroll
  for (int c=0;c<16;c++){ acc[0][c]=pack2(bs[2*c],bs[2*c+1]); acc[1][c]=acc[0][c]; }
  const float* xb = x + (size_t)b*3*65536;
  for (int kh=0;kh<3;kh++){
    int hi = 2*ho-1+kh; bool inh = (unsigned)hi<256u;
    for (int kw=0;kw<3;kw++){
      int wi0 = 4*tw-1+kw, wi1 = wi0+2;
      bool in0 = inh && (unsigned)wi0<256u;
      bool in1 = inh && (unsigned)wi1<256u;
      #pragma unroll
      for (int ci=0;ci<3;ci++){
        float f0 = in0 ? xb[(size_t)ci*65536 + hi*256 + wi0] : 0.f;
        float f1 = in1 ? xb[(size_t)ci*65536 + hi*256 + wi1] : 0.f;
        u64 v0=bcast2(f0), v1=bcast2(f1);
        const ulonglong2* wp = (const ulonglong2*)&ws[((kh*3+kw)*3+ci)*32];
        #pragma unroll
        for (int q=0;q<8;q++){
          ulonglong2 t=wp[q];
          ffma2(acc[0][2*q],v0,t.x); ffma2(acc[0][2*q+1],v0,t.y);
          ffma2(acc[1][2*q],v1,t.x); ffma2(acc[1][2*q+1],v1,t.y);
        }
      }
    }
  }
  unsigned short* op = g_b1h + (size_t)(2*idx)*32;
  #pragma unroll
  for (int p=0;p<2;p++){
    u32 pk[16];
    #pragma unroll
    for (int c=0;c<16;c++){
      float2 f = unpack2(acc[p][c]);
      pk[c] = bfpack(fmaxf(f.x,0.f), fmaxf(f.y,0.f));
    }
    #pragma unroll
    for (int q=0;q<4;q++)
      ((uint4*)op)[p*4+q] = make_uint4(pk[4*q],pk[4*q+1],pk[4*q+2],pk[4*q+3]);
  }
}

// ---------------- enc2: 32->64 k3 s2 p1 relu via mma bf16; bf16 out ---------
__global__ __launch_bounds__(128) void enc2_mma_k(const float* __restrict__ bias){
  constexpr int ROWB = 129*80;
  __shared__ __align__(16) unsigned char As[3*ROWB];
  __shared__ float bias_s[64];
  int tid = threadIdx.x, bx = blockIdx.x;
  int ho = bx & 63, b = bx >> 6;
  if (tid<64) bias_s[tid]=bias[tid];
  for (int i=tid;i<3*129*4;i+=128){
    int r=i/516, rem=i%516, px=rem>>2, ch=rem&3;
    int hi=2*ho-1+r, wi=px-1;
    uint4 v=make_uint4(0,0,0,0);
    if ((unsigned)hi<128u && (unsigned)wi<128u)
      v = *(const uint4*)&g_b1h[(((size_t)(b*128+hi))*128+wi)*32 + ch*8];
    *(uint4*)&As[r*ROWB + px*80 + ch*16] = v;
  }
  __syncthreads();
  u32 aSm = smem_u32(As);
  int lane = tid&31, wid = tid>>5;
  int g = lane>>2, tig = lane&3;
  float c[8][4];
  #pragma unroll
  for (int ntv=0;ntv<8;ntv++){
    float bA=bias_s[ntv*8+2*tig], bB=bias_s[ntv*8+2*tig+1];
    c[ntv][0]=bA; c[ntv][1]=bB; c[ntv][2]=bA; c[ntv][3]=bB;
  }
  u32 laneRow = (u32)(lane & 15);
  u32 laneCol = (lane & 16) ? 16u : 0u;
  #pragma unroll
  for (int kh=0;kh<3;kh++){
    #pragma unroll
    for (int kw=0;kw<3;kw++){
      int tap = kh*3+kw;
      #pragma unroll
      for (int kt=0;kt<2;kt++){
        u32 abase = aSm + kh*ROWB + (wid*32 + 2*laneRow + kw)*80 + kt*32 + laneCol;
        u32 a0,a1,a2,a3;
        asm volatile("ldmatrix.sync.aligned.m8n8.x4.shared.b16 {%0,%1,%2,%3}, [%4];"
                     : "=r"(a0),"=r"(a1),"=r"(a2),"=r"(a3) : "r"(abase));
        #pragma unroll
        for (int ntv=0;ntv<8;ntv++){
          uint2 bv = *(const uint2*)&g_wfrag2[tap*1024 + kt*512 + ntv*64 + lane*2];
          asm volatile("mma.sync.aligned.m16n8k16.row.col.f32.bf16.bf16.f32 "
                       "{%0,%1,%2,%3}, {%4,%5,%6,%7}, {%8,%9}, {%0,%1,%2,%3};"
                       : "+f"(c[ntv][0]),"+f"(c[ntv][1]),"+f"(c[ntv][2]),"+f"(c[ntv][3])
                       : "r"(a0),"r"(a1),"r"(a2),"r"(a3),"r"(bv.x),"r"(bv.y));
        }
      }
    }
  }
  int woA = wid*16+g, woB = woA+8;
  unsigned short* base = g_b2h + ((size_t)(b*64+ho))*64*64;
  unsigned short* pA = base + (size_t)woA*64 + 2*tig;
  unsigned short* pB = base + (size_t)woB*64 + 2*tig;
  #pragma unroll
  for (int ntv=0;ntv<8;ntv++){
    *(u32*)(pA + ntv*8) = bfpack(fmaxf(c[ntv][0],0.f), fmaxf(c[ntv][1],0.f));
    *(u32*)(pB + ntv*8) = bfpack(fmaxf(c[ntv][2],0.f), fmaxf(c[ntv][3],0.f));
  }
}

// ------------- VQ via mma: z-GEMM + scoring GEMM + quantize + loss ----------
// Block 128 thr (4 warps x 16 px = 64 px). Grid 4096.
__global__ __launch_bounds__(128) void vq_mma_k(const float* __restrict__ cb,
                                                const float* __restrict__ b3){
  __shared__ __align__(16) unsigned char As[64*144];   // 64px x 64ch bf16, 144B stride
  __shared__ __align__(16) u32 CBf[4096];
  __shared__ __align__(16) u32 Ws3[512];
  __shared__ __align__(8) float nrm_s[512];
  int tid = threadIdx.x;
  size_t base = (size_t)blockIdx.x*64;
  for (int i=tid;i<4096;i+=128) CBf[i]=g_wfragcb[i];
  for (int i=tid;i<512;i+=128) Ws3[i]=g_wfragw3[i];
  for (int i=tid;i<512;i+=128) nrm_s[i]=g_nrm[i];
  for (int i=tid;i<512;i+=128){
    int px=i>>3, ch=i&7;
    uint4 v = *(const uint4*)&g_b2h[(base+px)*64 + ch*8];
    *(uint4*)&As[px*144 + ch*16] = v;
  }
  __syncthreads();
  u32 aSm=smem_u32(As), cbSm=smem_u32(CBf), wSm=smem_u32(Ws3);
  int lane=tid&31, wid=tid>>5;
  int g=lane>>2, tig=lane&3;
  u32 laneRow=(u32)(lane&15), laneCol=(lane&16)?16u:0u;
  // ---- z GEMM: 16px x 16d, K=64 ----
  float zc[2][4];
  #pragma unroll
  for (int ntv=0;ntv<2;ntv++){
    float bA=b3[ntv*8+2*tig], bB=b3[ntv*8+2*tig+1];
    zc[ntv][0]=bA; zc[ntv][1]=bB; zc[ntv][2]=bA; zc[ntv][3]=bB;
  }
  u32 abase = aSm + (u32)(wid*16+laneRow)*144 + laneCol;
  #pragma unroll
  for (int kt=0;kt<4;kt++){
    u32 a0,a1,a2,a3;
    asm volatile("ldmatrix.sync.aligned.m8n8.x4.shared.b16 {%0,%1,%2,%3}, [%4];"
                 : "=r"(a0),"=r"(a1),"=r"(a2),"=r"(a3) : "r"(abase + kt*32));
    #pragma unroll
    for (int ntv=0;ntv<2;ntv++){
      u32 b0,b1;
      asm volatile("ld.shared.v2.u32 {%0,%1}, [%2];"
                   : "=r"(b0),"=r"(b1)
                   : "r"(wSm + ((kt*2+ntv)*64 + lane*2)*4));
      asm volatile("mma.sync.aligned.m16n8k16.row.col.f32.bf16.bf16.f32 "
                   "{%0,%1,%2,%3}, {%4,%5,%6,%7}, {%8,%9}, {%0,%1,%2,%3};"
                   : "+f"(zc[ntv][0]),"+f"(zc[ntv][1]),"+f"(zc[ntv][2]),"+f"(zc[ntv][3])
                   : "r"(a0),"r"(a1),"r"(a2),"r"(a3),"r"(b0),"r"(b1));
    }
  }
  // ---- pack z into A-frags for scoring (C-frag layout == A-frag layout) ----
  u32 aZ0=bfpack(zc[0][0],zc[0][1]);
  u32 aZ1=bfpack(zc[0][2],zc[0][3]);
  u32 aZ2=bfpack(zc[1][0],zc[1][1]);
  u32 aZ3=bfpack(zc[1][2],zc[1][3]);
  // ---- scoring: 64 chunks of 8 codewords ----
  float best0=-3.4e38f, best1=-3.4e38f; int bi0=0, bi1=0;
  for (int chunk=0;chunk<64;chunk++){
    float2 nk = *(const float2*)&nrm_s[chunk*8+2*tig];
    float s0=-nk.x, s1=-nk.y, s2=-nk.x, s3=-nk.y;
    u32 b0,b1;
    asm volatile("ld.shared.v2.u32 {%0,%1}, [%2];"
                 : "=r"(b0),"=r"(b1)
                 : "r"(cbSm + (chunk*64 + lane*2)*4));
    asm volatile("mma.sync.aligned.m16n8k16.row.col.f32.bf16.bf16.f32 "
                 "{%0,%1,%2,%3}, {%4,%5,%6,%7}, {%8,%9}, {%0,%1,%2,%3};"
                 : "+f"(s0),"+f"(s1),"+f"(s2),"+f"(s3)
                 : "r"(aZ0),"r"(aZ1),"r"(aZ2),"r"(aZ3),"r"(b0),"r"(b1));
    int i0 = chunk*8 + 2*tig;
    float cs; int ci;
    if (s1>s0){cs=s1;ci=i0+1;} else {cs=s0;ci=i0;}
    if (cs>best0){best0=cs;bi0=ci;}
    if (s3>s2){cs=s3;ci=i0+1;} else {cs=s2;ci=i0;}
    if (cs>best1){best1=cs;bi1=ci;}
  }
  // quad reduce (lanes sharing g)
  #pragma unroll
  for (int off=1;off<4;off<<=1){
    float os=__shfl_xor_sync(0xffffffffu,best0,off);
    int   oi=__shfl_xor_sync(0xffffffffu,bi0,off);
    if (os>best0 || (os==best0 && oi<bi0)){best0=os;bi0=oi;}
    os=__shfl_xor_sync(0xffffffffu,best1,off);
    oi=__shfl_xor_sync(0xffffffffu,bi1,off);
    if (os>best1 || (os==best1 && oi<bi1)){best1=os;bi1=oi;}
  }
  // ---- quantize write + VQ loss (fp32) ----
  size_t px0 = base + wid*16 + g, px1 = px0 + 8;
  float ls=0.f;
  {
    const float* e = cb + (size_t)bi0*16;
    float e0=e[tig*4], e1=e[tig*4+1], e2v=e[tig*4+2], e3v=e[tig*4+3];
    *(u32*)&g_qh[px0*16 + tig*4]     = bfpack(e0,e1);
    *(u32*)&g_qh[px0*16 + tig*4 + 2] = bfpack(e2v,e3v);
    float d0=e[2*tig]-zc[0][0],   d1=e[2*tig+1]-zc[0][1];
    float d2=e[8+2*tig]-zc[1][0], d3=e[8+2*tig+1]-zc[1][1];
    ls = fmaf(d0,d0, fmaf(d1,d1, fmaf(d2,d2, fmaf(d3,d3, ls))));
  }
  {
    const float* e = cb + (size_t)bi1*16;
    float e0=e[tig*4], e1=e[tig*4+1], e2v=e[tig*4+2], e3v=e[tig*4+3];
    *(u32*)&g_qh[px1*16 + tig*4]     = bfpack(e0,e1);
    *(u32*)&g_qh[px1*16 + tig*4 + 2] = bfpack(e2v,e3v);
    float d0=e[2*tig]-zc[0][2],   d1=e[2*tig+1]-zc[0][3];
    float d2=e[8+2*tig]-zc[1][2], d3=e[8+2*tig+1]-zc[1][3];
    ls = fmaf(d0,d0, fmaf(d1,d1, fmaf(d2,d2, fmaf(d3,d3, ls))));
  }
  float s = blockReduceSum(ls);
  if (tid==0) atomicAdd(&g_acc[0], (double)s);
}

// ------------- dec1: convT 16->64 via mma bf16 ------------------------------
template<int PH,int PW>
__global__ __launch_bounds__(128) void dec1_mma_k(const float* __restrict__ bias){
  constexpr int NKH = PH?2:1, NKW = PW?2:1, NROWS = PH?2:1;
  constexpr int ROWB = 65*48;
  __shared__ __align__(16) unsigned char As[NROWS*ROWB];
  __shared__ __align__(16) u32 Bs[NKH*NKW*512];
  __shared__ float bias_s[64];
  int tid = threadIdx.x, bx = blockIdx.x;
  int hb = bx & 63, b = bx >> 6;
  for (int i=tid;i<NKH*NKW*512;i+=128){
    int tl=i>>9, w_=i&511;
    int a=tl/NKW, cc=tl%NKW;
    int kh=PH?a*2:1, kw=PW?cc*2:1;
    Bs[i]=g_wfragd1[(kh*3+kw)*512+w_];
  }
  if (tid<64) bias_s[tid]=bias[tid];
  for (int i=tid;i<NROWS*65*2;i+=128){
    int r=i/130, rem=i%130, px=rem>>1, hf=rem&1;
    int hi=hb+r;
    uint4 v=make_uint4(0,0,0,0);
    if (hi<64 && px<64)
      v=*(const uint4*)&g_qh[(((size_t)(b*64+hi))*64+px)*16 + hf*8];
    *(uint4*)&As[r*ROWB+px*48+hf*16]=v;
  }
  __syncthreads();
  u32 aSm = smem_u32(As);
  u32 bSm = smem_u32(Bs);
  int lane = tid&31, wid = tid>>5;
  int g = lane>>2, tig = lane&3;
  float c[8][4];
  #pragma unroll
  for (int ntv=0;ntv<8;ntv++){
    float bA=bias_s[ntv*8+2*tig], bB=bias_s[ntv*8+2*tig+1];
    c[ntv][0]=bA; c[ntv][1]=bB; c[ntv][2]=bA; c[ntv][3]=bB;
  }
  u32 laneRow = (u32)(lane & 15);
  u32 laneCol = (lane & 16) ? 16u : 0u;
  #pragma unroll
  for (int a=0;a<NKH;a++){
    int rtap = PH ? (a==0 ? 1 : 0) : 0;
    #pragma unroll
    for (int cc=0;cc<NKW;cc++){
      int shift = PW ? (cc==0 ? 1 : 0) : 0;
      int tl = a*NKW+cc;
      u32 abase = aSm + rtap*ROWB + (wid*16 + shift + laneRow)*48 + laneCol;
      u32 a0,a1,a2,a3;
      asm volatile("ldmatrix.sync.aligned.m8n8.x4.shared.b16 {%0,%1,%2,%3}, [%4];"
                   : "=r"(a0),"=r"(a1),"=r"(a2),"=r"(a3) : "r"(abase));
      #pragma unroll
      for (int ntv=0;ntv<8;ntv++){
        u32 b0,b1;
        asm volatile("ld.shared.v2.u32 {%0,%1}, [%2];"
                     : "=r"(b0),"=r"(b1)
                     : "r"(bSm + ((tl*8+ntv)*64 + lane*2)*4));
        asm volatile("mma.sync.aligned.m16n8k16.row.col.f32.bf16.bf16.f32 "
                     "{%0,%1,%2,%3}, {%4,%5,%6,%7}, {%8,%9}, {%0,%1,%2,%3};"
                     : "+f"(c[ntv][0]),"+f"(c[ntv][1]),"+f"(c[ntv][2]),"+f"(c[ntv][3])
                     : "r"(a0),"r"(a1),"r"(a2),"r"(a3),"r"(b0),"r"(b1));
      }
    }
  }
  int ho = 2*hb+PH;
  int wbA = wid*16+g, wbB = wbA+8;
  unsigned short* rb = g_d1h + ((size_t)(b*128+ho))*128*64;
  unsigned short* pA = rb + (size_t)(2*wbA+PW)*64 + 2*tig;
  unsigned short* pB = rb + (size_t)(2*wbB+PW)*64 + 2*tig;
  #pragma unroll
  for (int ntv=0;ntv<8;ntv++){
    *(u32*)(pA + ntv*8) = bfpack(fmaxf(c[ntv][0],0.f), fmaxf(c[ntv][1],0.f));
    *(u32*)(pB + ntv*8) = bfpack(fmaxf(c[ntv][2],0.f), fmaxf(c[ntv][3],0.f));
  }
}

// ------------- dec2: convT 64->32 via mma bf16; bf16 output -----------------
template<int PH,int PW>
__global__ __launch_bounds__(128) void dec2_mma_k(const float* __restrict__ bias){
  constexpr int NKH = PH?2:1, NKW = PW?2:1, NROWS = PH?2:1;
  constexpr int ROWB = 65*144;
  __shared__ __align__(16) unsigned char As[NROWS*ROWB];
  __shared__ __align__(16) u32 Bs[NKH*NKW*1024];
  __shared__ float bias_s[32];
  int tid = threadIdx.x;
  int bx = blockIdx.x;
  int wchunk = bx & 1, hb = (bx>>1)&127, b = bx>>8;
  int wb0 = wchunk*64;
  for (int i=tid;i<NKH*NKW*1024;i+=128){
    int tl = i>>10, w_ = i & 1023;
    int a = tl/NKW, cc = tl%NKW;
    int kh = PH? a*2 : 1, kw = PW? cc*2 : 1;
    Bs[i] = g_wfrag[(kh*3+kw)*1024 + w_];
  }
  if (tid<32) bias_s[tid]=bias[tid];
  for (int i=tid;i<NROWS*65*8;i+=128){
    int r = i/520, rem = i%520, px = rem>>3, ch = rem&7;
    int hi = hb + r;
    int wi = wb0 + px;
    uint4 v = make_uint4(0,0,0,0);
    if (hi<128 && wi<128)
      v = *(const uint4*)&g_d1h[(((size_t)(b*128+hi))*128+wi)*64 + ch*8];
    *(uint4*)&As[r*ROWB + px*144 + ch*16] = v;
  }
  __syncthreads();

  u32 aSm = smem_u32(As);
  u32 bSm = smem_u32(Bs);
  int lane = tid & 31, wid = tid>>5;
  int g = lane>>2, tig = lane&3;
  float c[4][4];
  #pragma unroll
  for (int ntv=0;ntv<4;ntv++){
    float bA = bias_s[ntv*8+2*tig], bB = bias_s[ntv*8+2*tig+1];
    c[ntv][0]=bA; c[ntv][1]=bB; c[ntv][2]=bA; c[ntv][3]=bB;
  }
  u32 laneRow = (u32)(lane & 15);
  u32 laneCol = (lane & 16) ? 16u : 0u;
  #pragma unroll
  for (int a=0;a<NKH;a++){
    int rtap = PH ? (a==0 ? 1 : 0) : 0;
    #pragma unroll
    for (int cc=0;cc<NKW;cc++){
      int shift = PW ? (cc==0 ? 1 : 0) : 0;
      int tl = a*NKW+cc;
      u32 abase = aSm + rtap*ROWB + (wid*16 + shift + laneRow)*144 + laneCol;
      #pragma unroll
      for (int kt=0;kt<4;kt++){
        u32 a0,a1,a2,a3;
        asm volatile("ldmatrix.sync.aligned.m8n8.x4.shared.b16 {%0,%1,%2,%3}, [%4];"
                     : "=r"(a0),"=r"(a1),"=r"(a2),"=r"(a3)
                     : "r"(abase + kt*32));
        #pragma unroll
        for (int ntv=0;ntv<4;ntv++){
          u32 b0,b1;
          asm volatile("ld.shared.v2.u32 {%0,%1}, [%2];"
                       : "=r"(b0),"=r"(b1)
                       : "r"(bSm + (((tl*4+kt)*4+ntv)*64 + lane*2)*4));
          asm volatile("mma.sync.aligned.m16n8k16.row.col.f32.bf16.bf16.f32 "
                       "{%0,%1,%2,%3}, {%4,%5,%6,%7}, {%8,%9}, {%0,%1,%2,%3};"
                       : "+f"(c[ntv][0]),"+f"(c[ntv][1]),"+f"(c[ntv][2]),"+f"(c[ntv][3])
                       : "r"(a0),"r"(a1),"r"(a2),"r"(a3),"r"(b0),"r"(b1));
        }
      }
    }
  }
  int ho = 2*hb+PH;
  int wbA = wb0 + wid*16 + g, wbB = wbA + 8;
  unsigned short* rowBase = g_d2h + ((size_t)(b*256+ho))*256*32;
  unsigned short* pA = rowBase + (size_t)(2*wbA+PW)*32 + 2*tig;
  unsigned short* pB = rowBase + (size_t)(2*wbB+PW)*32 + 2*tig;
  #pragma unroll
  for (int ntv=0;ntv<4;ntv++){
    *(u32*)(pA + ntv*8) = bfpack(fmaxf(c[ntv][0],0.f), fmaxf(c[ntv][1],0.f));
    *(u32*)(pB + ntv*8) = bfpack(fmaxf(c[ntv][2],0.f), fmaxf(c[ntv][3],0.f));
  }
}

// ------------- dec3: conv 32->3 via mma bf16 + fused recon MSE --------------
__global__ __launch_bounds__(128) void dec3_mma_k(const float* __restrict__ x,
                                                  const float* __restrict__ bias){
  constexpr int PXB = 80;
  __shared__ __align__(16) unsigned char As[3*66*PXB];
  __shared__ __align__(16) u32 Bs[1152];
  __shared__ float bias_s[3];
  int tid = threadIdx.x, bx = blockIdx.x;
  int wchunk = bx & 3, ho = (bx>>2)&255, b = bx>>10;
  int wb0 = wchunk*64;
  for (int i=tid;i<1152;i+=128) Bs[i]=g_wfragd3[i];
  if (tid<3) bias_s[tid]=bias[tid];
  for (int i=tid;i<3*66*4;i+=128){
    int r=i/264, rem=i%264, px=rem>>2, q=rem&3;
    int hi=ho-1+r, wi=wb0-1+px;
    uint4 v=make_uint4(0,0,0,0);
    if ((unsigned)hi<256u && (unsigned)wi<256u)
      v=*(const uint4*)&g_d2h[(((size_t)(b*256+hi))*256+wi)*32 + q*8];
    *(uint4*)&As[(r*66+px)*PXB + q*16]=v;
  }
  __syncthreads();
  u32 aSm=smem_u32(As), bSm=smem_u32(Bs);
  int lane=tid&31, wid=tid>>5;
  int g=lane>>2, tig=lane&3;
  float c[4]={0.f,0.f,0.f,0.f};
  u32 laneRow=(u32)(lane&15);
  u32 laneCol=(lane&16)?16u:0u;
  #pragma unroll
  for (int kh=0;kh<3;kh++){
    #pragma unroll
    for (int kw=0;kw<3;kw++){
      int tap=kh*3+kw;
      u32 abase = aSm + (u32)(kh*66 + wid*16 + kw + laneRow)*PXB + laneCol;
      #pragma unroll
      for (int kt=0;kt<2;kt++){
        u32 a0,a1,a2,a3;
        asm volatile("ldmatrix.sync.aligned.m8n8.x4.shared.b16 {%0,%1,%2,%3}, [%4];"
                     : "=r"(a0),"=r"(a1),"=r"(a2),"=r"(a3) : "r"(abase + kt*32));
        u32 b0,b1;
        asm volatile("ld.shared.v2.u32 {%0,%1}, [%2];"
                     : "=r"(b0),"=r"(b1)
                     : "r"(bSm + ((tap*2+kt)*64 + lane*2)*4));
        asm volatile("mma.sync.aligned.m16n8k16.row.col.f32.bf16.bf16.f32 "
                     "{%0,%1,%2,%3}, {%4,%5,%6,%7}, {%8,%9}, {%0,%1,%2,%3};"
                     : "+f"(c[0]),"+f"(c[1]),"+f"(c[2]),"+f"(c[3])
                     : "r"(a0),"r"(a1),"r"(a2),"r"(a3),"r"(b0),"r"(b1));
      }
    }
  }
  int pxA = wb0 + wid*16 + g, pxB = pxA + 8;
  const float* xb = x + (size_t)b*3*65536 + ho*256;
  float ls = 0.f;
  int co0 = 2*tig, co1 = co0+1;
  if (co0 < 3){
    float d0 = c[0] + bias_s[co0] - xb[(size_t)co0*65536 + pxA];
    float d1 = c[2] + bias_s[co0] - xb[(size_t)co0*65536 + pxB];
    ls = fmaf(d0,d0, fmaf(d1,d1, ls));
  }
  if (co1 < 3){
    float d0 = c[1] + bias_s[co1] - xb[(size_t)co1*65536 + pxA];
    float d1 = c[3] + bias_s[co1] - xb[(size_t)co1*65536 + pxB];
    ls = fmaf(d0,d0, fmaf(d1,d1, ls));
  }
  float s = blockReduceSum(ls);
  if (tid==0) atomicAdd(&g_acc[1], (double)s);
}

// ------------- finalize -----------------------------------------------------
__global__ void final_k(float* __restrict__ out){
  double vq  = g_acc[0];
  double rec = g_acc[1];
  float e_q  = (float)(1.25 * vq / 4194304.0);
  float mse  = (float)(rec / 12582912.0);
  out[0] = e_q;
  out[1] = mse;
  out[2] = mse;
}

// ---------------- launch ----------------------------------------------------
extern "C" void kernel_launch(void* const* d_in, const int* in_sizes, int n_in,
                              void* d_out, int out_size){
  const float* x   = (const float*)d_in[0];
  const float* ew1 = (const float*)d_in[1];
  const float* eb1 = (const float*)d_in[2];
  const float* ew2 = (const float*)d_in[3];
  const float* eb2 = (const float*)d_in[4];
  const float* ew3 = (const float*)d_in[5];
  const float* eb3 = (const float*)d_in[6];
  const float* cb  = (const float*)d_in[7];
  const float* dw1 = (const float*)d_in[8];
  const float* db1 = (const float*)d_in[9];
  const float* dw2 = (const float*)d_in[10];
  const float* db2 = (const float*)d_in[11];
  const float* dw3 = (const float*)d_in[12];
  const float* db3 = (const float*)d_in[13];
  float* out = (float*)d_out;

  repack_k<<<64,256>>>(ew1, ew2, dw1, dw2, dw3, ew3, cb);
  enc1_k<<<2048,256>>>(x, eb1);
  enc2_mma_k<<<4096,128>>>(eb2);
  vq_mma_k<<<4096,128>>>(cb, eb3);
  dec1_mma_k<0,0><<<4096,128>>>(db1);
  dec1_mma_k<0,1><<<4096,128>>>(db1);
  dec1_mma_k<1,0><<<4096,128>>>(db1);
  dec1_mma_k<1,1><<<4096,128>>>(db1);
  dec2_mma_k<0,0><<<16384,128>>>(db2);
  dec2_mma_k<0,1><<<16384,128>>>(db2);
  dec2_mma_k<1,0><<<16384,128>>>(db2);
  dec2_mma_k<1,1><<<16384,128>>>(db2);
  dec3_mma_k<<<65536,128>>>(x, db3);
  final_k<<<1,1>>>(out);
}

// round 10
// speedup vs baseline: 3.8302x; 1.1488x over previous
#include <cuda_runtime.h>
#include <cuda_bf16.h>
#include <cstdint>

typedef unsigned long long u64;
typedef unsigned int u32;

// ---------------- scratch (device globals; no allocations allowed) ----------
__device__ unsigned short g_b1h[(size_t)64*128*128*32];  // enc1 out NHWC bf16
__device__ unsigned short g_b2h[(size_t)64*64*64*64];    // enc2 out NHWC bf16
__device__ unsigned short g_qh[(size_t)64*64*64*16];     // quantized NHWC bf16
__device__ unsigned short g_d1h[(size_t)64*128*128*64];  // dec1 out NHWC bf16
__device__ unsigned short g_d2h[(size_t)64*256*256*32];  // dec2 out NHWC bf16

__device__ u32   g_wfrag1[512];     // enc1 w  B-frags [kt2][nt4][lane32][reg2] (k=(kh,kw,ci), pad>=27)
__device__ u32   g_wfrag2[18432];   // enc2 w  B-frags
__device__ u32   g_wfragd1[4608];   // dec1 w  B-frags
__device__ u32   g_wfrag[9216];     // dec2 w  B-frags
__device__ u32   g_wfragd3[1152];   // dec3 w  B-frags (flip baked)
__device__ u32   g_wfragw3[512];    // enc3(1x1) w B-frags [kt4][nt2][lane32][reg2]
__device__ u32   g_wfragcb[4096];   // codebook B-frags [chunk64][lane32][reg2]
__device__ float g_nrm[512];        // 0.5*||e_k||^2 (fp32)
__device__ double g_acc[2];         // [0]=vq sq-sum, [1]=recon sq-sum

// ---------------- helpers ----------------------------------------------------
__device__ __forceinline__ u64 pack2(float lo, float hi){
  u64 r; asm("mov.b64 %0, {%1, %2};" : "=l"(r)
             : "r"(__float_as_uint(lo)), "r"(__float_as_uint(hi)));
  return r;
}
__device__ __forceinline__ float2 unpack2(u64 p){
  unsigned lo, hi;
  asm("mov.b64 {%0, %1}, %2;" : "=r"(lo), "=r"(hi) : "l"(p));
  return make_float2(__uint_as_float(lo), __uint_as_float(hi));
}
__device__ __forceinline__ u32 bfpack(float lo, float hi){
  u32 r; asm("cvt.rn.bf16x2.f32 %0, %1, %2;" : "=r"(r) : "f"(hi), "f"(lo));
  return r;
}
__device__ __forceinline__ u32 smem_u32(const void* p){
  u32 a; asm("{ .reg .u64 t; cvta.to.shared.u64 t, %1; cvt.u32.u64 %0, t; }"
             : "=r"(a) : "l"(p));
  return a;
}

__device__ __forceinline__ float blockReduceSum(float v){
  __shared__ float red[32];
  #pragma unroll
  for (int o=16;o;o>>=1) v += __shfl_down_sync(0xffffffffu, v, o);
  int lane = threadIdx.x & 31, w = threadIdx.x >> 5;
  if (lane==0) red[w]=v;
  __syncthreads();
  if (w==0){
    v = (lane < ((int)blockDim.x>>5)) ? red[lane] : 0.f;
    #pragma unroll
    for (int o=16;o;o>>=1) v += __shfl_down_sync(0xffffffffu, v, o);
  }
  return v;
}

__device__ __forceinline__ unsigned short f2bf(float v){
  return __bfloat16_as_ushort(__float2bfloat16(v));
}

// ---------------- weight repack + accumulator reset -------------------------
__global__ void repack_k(const float* __restrict__ ew1, const float* __restrict__ ew2,
                         const float* __restrict__ dw1, const float* __restrict__ dw2,
                         const float* __restrict__ dw3, const float* __restrict__ w3,
                         const float* __restrict__ cb){
  int t = blockIdx.x*blockDim.x + threadIdx.x;
  int nt = gridDim.x*blockDim.x;
  if (blockIdx.x==0 && threadIdx.x<2) g_acc[threadIdx.x]=0.0;
  // enc1 B-frags: i = kt*256 + ntv*64 + lane*2 + reg ; k=(kh*3+kw)*3+ci, pad>=27
  for (int i=t;i<512;i+=nt){
    int reg=i&1; int lane=(i>>1)&31; int ntv=(i>>6)&3; int kt=i>>8;
    int gg=lane>>2, tg=lane&3;
    int co = ntv*8+gg;
    int k0 = kt*16 + 2*tg + (reg?8:0);
    float w0=0.f, w1=0.f;
    if (k0<27){ int kh=k0/9, r=k0%9, kw=r/3, ci=r%3;
      w0 = ew1[((co*3+ci)*3+kh)*3+kw]; }
    if (k0+1<27){ int k1=k0+1; int kh=k1/9, r=k1%9, kw=r/3, ci=r%3;
      w1 = ew1[((co*3+ci)*3+kh)*3+kw]; }
    g_wfrag1[i] = (u32)f2bf(w0) | ((u32)f2bf(w1)<<16);
  }
  // enc2 B-frags
  for (int i=t;i<18432;i+=nt){
    int reg=i&1; int lane=(i>>1)&31; int ntv=(i>>6)&7; int kt=(i>>9)&1; int tap=i>>10;
    int kh=tap/3, kw=tap%3;
    int gg=lane>>2, tg=lane&3;
    int co = ntv*8+gg;
    int ci0 = kt*16 + 2*tg + (reg?8:0);
    g_wfrag2[i] = (u32)f2bf(ew2[((co*32+ci0)*3+kh)*3+kw])
                | ((u32)f2bf(ew2[((co*32+ci0+1)*3+kh)*3+kw])<<16);
  }
  // dec1 B-frags
  for (int i=t;i<4608;i+=nt){
    int reg=i&1; int lane=(i>>1)&31; int ntv=(i>>6)&7; int tap=i>>9;
    int kh=tap/3, kw=tap%3;
    int gg=lane>>2, tg=lane&3;
    int co = ntv*8+gg;
    int ci0 = 2*tg + (reg?8:0);
    g_wfragd1[i] = (u32)f2bf(dw1[((ci0*64+co)*3+kh)*3+kw])
                 | ((u32)f2bf(dw1[(((ci0+1)*64+co)*3+kh)*3+kw])<<16);
  }
  // dec2 B-frags
  for (int i=t;i<9216;i+=nt){
    int tap = i>>10; int w_ = i & 1023;
    int reg = w_ & 1; int lane = (w_>>1)&31; int ntv = (w_>>6)&3; int kt = (w_>>8)&3;
    int kh = tap/3, kw = tap%3;
    int gg = lane>>2, tg = lane&3;
    int co = ntv*8+gg;
    int ci0 = kt*16 + 2*tg + (reg?8:0);
    g_wfrag[i] = (u32)f2bf(dw2[((ci0*32+co)*3+kh)*3+kw])
               | ((u32)f2bf(dw2[(((ci0+1)*32+co)*3+kh)*3+kw])<<16);
  }
  // dec3 B-frags (flip baked)
  for (int i=t;i<1152;i+=nt){
    int reg=i&1; int lane=(i>>1)&31; int kt=(i>>6)&1; int tap=i>>7;
    int kh=tap/3, kw=tap%3;
    int gg=lane>>2, tg=lane&3;
    int co=gg;
    int ci0 = kt*16 + 2*tg + (reg?8:0);
    float w0=0.f, w1=0.f;
    if (co<3){
      w0 = dw3[((ci0*3+co)*3+(2-kh))*3+(2-kw)];
      w1 = dw3[(((ci0+1)*3+co)*3+(2-kh))*3+(2-kw)];
    }
    g_wfragd3[i] = (u32)f2bf(w0) | ((u32)f2bf(w1)<<16);
  }
  // enc3 (1x1) w3 B-frags
  for (int i=t;i<512;i+=nt){
    int reg=i&1; int lane=(i>>1)&31; int ntv=(i>>6)&1; int kt=i>>7;
    int gg=lane>>2, tg=lane&3;
    int d = ntv*8+gg;
    int ci0 = kt*16 + 2*tg + (reg?8:0);
    g_wfragw3[i] = (u32)f2bf(w3[d*64+ci0]) | ((u32)f2bf(w3[d*64+ci0+1])<<16);
  }
  // codebook B-frags
  for (int i=t;i<4096;i+=nt){
    int reg=i&1; int lane=(i>>1)&31; int chunk=i>>6;
    int gg=lane>>2, tg=lane&3;
    int cw = chunk*8+gg;
    int d0 = 2*tg + (reg?8:0);
    g_wfragcb[i] = (u32)f2bf(cb[cw*16+d0]) | ((u32)f2bf(cb[cw*16+d0+1])<<16);
  }
  // codebook half-norms
  for (int k=t;k<512;k+=nt){
    float s=0.f;
    #pragma unroll
    for (int d=0;d<16;d++){ float e=cb[k*16+d]; s=fmaf(e,e,s); }
    g_nrm[k]=0.5f*s;
  }
}

// ---------------- enc1: 3->32 k3 s2 p1 relu via mma (smem im2col) -----------
// Block 128 thr (4 warps x 16 px = 64 px of one output row). Grid 64*128*2.
__global__ __launch_bounds__(128) void enc1_mma_k(const float* __restrict__ x,
                                                  const float* __restrict__ bias){
  constexpr int PXB = 80;                           // 32 k * 2B + 16 pad
  __shared__ __align__(16) unsigned char As[64*PXB];
  __shared__ __align__(16) u32 Bs[512];
  __shared__ float bias_s[32];
  int tid = threadIdx.x, bx = blockIdx.x;
  int wchunk = bx & 1, ho = (bx>>1)&127, b = bx>>8;
  int wb0 = wchunk*64;
  for (int i=tid;i<512;i+=128) Bs[i]=g_wfrag1[i];
  if (tid<32) bias_s[tid]=bias[tid];
  const float* xb = x + (size_t)b*3*65536;
  for (int i=tid;i<2048;i+=128){
    int k=i>>6, px=i&63;
    unsigned short h=0;
    if (k<27){
      int kh=k/9, r=k%9, kw=r/3, ci=r%3;
      int hi=2*ho-1+kh, wi=2*(wb0+px)-1+kw;
      if ((unsigned)hi<256u && (unsigned)wi<256u)
        h = f2bf(xb[(size_t)ci*65536 + hi*256 + wi]);
    }
    *(unsigned short*)&As[px*PXB + k*2] = h;
  }
  __syncthreads();
  u32 aSm = smem_u32(As), bSm = smem_u32(Bs);
  int lane=tid&31, wid=tid>>5;
  int g=lane>>2, tig=lane&3;
  u32 laneRow=(u32)(lane&15), laneCol=(lane&16)?16u:0u;
  float c[4][4];
  #pragma unroll
  for (int ntv=0;ntv<4;ntv++){
    float bA=bias_s[ntv*8+2*tig], bB=bias_s[ntv*8+2*tig+1];
    c[ntv][0]=bA; c[ntv][1]=bB; c[ntv][2]=bA; c[ntv][3]=bB;
  }
  u32 abase = aSm + (u32)(wid*16+laneRow)*PXB + laneCol;
  #pragma unroll
  for (int kt=0;kt<2;kt++){
    u32 a0,a1,a2,a3;
    asm volatile("ldmatrix.sync.aligned.m8n8.x4.shared.b16 {%0,%1,%2,%3}, [%4];"
                 : "=r"(a0),"=r"(a1),"=r"(a2),"=r"(a3) : "r"(abase + kt*32));
    #pragma unroll
    for (int ntv=0;ntv<4;ntv++){
      u32 b0,b1;
      asm volatile("ld.shared.v2.u32 {%0,%1}, [%2];"
                   : "=r"(b0),"=r"(b1)
                   : "r"(bSm + ((kt*4+ntv)*64 + lane*2)*4));
      asm volatile("mma.sync.aligned.m16n8k16.row.col.f32.bf16.bf16.f32 "
                   "{%0,%1,%2,%3}, {%4,%5,%6,%7}, {%8,%9}, {%0,%1,%2,%3};"
                   : "+f"(c[ntv][0]),"+f"(c[ntv][1]),"+f"(c[ntv][2]),"+f"(c[ntv][3])
                   : "r"(a0),"r"(a1),"r"(a2),"r"(a3),"r"(b0),"r"(b1));
    }
  }
  int woA = wb0 + wid*16 + g, woB = woA + 8;
  unsigned short* rb = g_b1h + ((size_t)(b*128+ho))*128*32;
  unsigned short* pA = rb + (size_t)woA*32 + 2*tig;
  unsigned short* pB = rb + (size_t)woB*32 + 2*tig;
  #pragma unroll
  for (int ntv=0;ntv<4;ntv++){
    *(u32*)(pA + ntv*8) = bfpack(fmaxf(c[ntv][0],0.f), fmaxf(c[ntv][1],0.f));
    *(u32*)(pB + ntv*8) = bfpack(fmaxf(c[ntv][2],0.f), fmaxf(c[ntv][3],0.f));
  }
}

// ---------------- enc2: 32->64 k3 s2 p1 relu via mma bf16; bf16 out ---------
__global__ __launch_bounds__(128) void enc2_mma_k(const float* __restrict__ bias){
  constexpr int ROWB = 129*80;
  __shared__ __align__(16) unsigned char As[3*ROWB];
  __shared__ float bias_s[64];
  int tid = threadIdx.x, bx = blockIdx.x;
  int ho = bx & 63, b = bx >> 6;
  if (tid<64) bias_s[tid]=bias[tid];
  for (int i=tid;i<3*129*4;i+=128){
    int r=i/516, rem=i%516, px=rem>>2, ch=rem&3;
    int hi=2*ho-1+r, wi=px-1;
    uint4 v=make_uint4(0,0,0,0);
    if ((unsigned)hi<128u && (unsigned)wi<128u)
      v = *(const uint4*)&g_b1h[(((size_t)(b*128+hi))*128+wi)*32 + ch*8];
    *(uint4*)&As[r*ROWB + px*80 + ch*16] = v;
  }
  __syncthreads();
  u32 aSm = smem_u32(As);
  int lane = tid&31, wid = tid>>5;
  int g = lane>>2, tig = lane&3;
  float c[8][4];
  #pragma unroll
  for (int ntv=0;ntv<8;ntv++){
    float bA=bias_s[ntv*8+2*tig], bB=bias_s[ntv*8+2*tig+1];
    c[ntv][0]=bA; c[ntv][1]=bB; c[ntv][2]=bA; c[ntv][3]=bB;
  }
  u32 laneRow = (u32)(lane & 15);
  u32 laneCol = (lane & 16) ? 16u : 0u;
  #pragma unroll
  for (int kh=0;kh<3;kh++){
    #pragma unroll
    for (int kw=0;kw<3;kw++){
      int tap = kh*3+kw;
      #pragma unroll
      for (int kt=0;kt<2;kt++){
        u32 abase = aSm + kh*ROWB + (wid*32 + 2*laneRow + kw)*80 + kt*32 + laneCol;
        u32 a0,a1,a2,a3;
        asm volatile("ldmatrix.sync.aligned.m8n8.x4.shared.b16 {%0,%1,%2,%3}, [%4];"
                     : "=r"(a0),"=r"(a1),"=r"(a2),"=r"(a3) : "r"(abase));
        #pragma unroll
        for (int ntv=0;ntv<8;ntv++){
          uint2 bv = *(const uint2*)&g_wfrag2[tap*1024 + kt*512 + ntv*64 + lane*2];
          asm volatile("mma.sync.aligned.m16n8k16.row.col.f32.bf16.bf16.f32 "
                       "{%0,%1,%2,%3}, {%4,%5,%6,%7}, {%8,%9}, {%0,%1,%2,%3};"
                       : "+f"(c[ntv][0]),"+f"(c[ntv][1]),"+f"(c[ntv][2]),"+f"(c[ntv][3])
                       : "r"(a0),"r"(a1),"r"(a2),"r"(a3),"r"(bv.x),"r"(bv.y));
        }
      }
    }
  }
  int woA = wid*16+g, woB = woA+8;
  unsigned short* base = g_b2h + ((size_t)(b*64+ho))*64*64;
  unsigned short* pA = base + (size_t)woA*64 + 2*tig;
  unsigned short* pB = base + (size_t)woB*64 + 2*tig;
  #pragma unroll
  for (int ntv=0;ntv<8;ntv++){
    *(u32*)(pA + ntv*8) = bfpack(fmaxf(c[ntv][0],0.f), fmaxf(c[ntv][1],0.f));
    *(u32*)(pB + ntv*8) = bfpack(fmaxf(c[ntv][2],0.f), fmaxf(c[ntv][3],0.f));
  }
}

// ------------- VQ via mma: z-GEMM + scoring GEMM + quantize + loss ----------
__global__ __launch_bounds__(128) void vq_mma_k(const float* __restrict__ cb,
                                                const float* __restrict__ b3){
  __shared__ __align__(16) unsigned char As[64*144];
  __shared__ __align__(16) u32 CBf[4096];
  __shared__ __align__(16) u32 Ws3[512];
  __shared__ __align__(8) float nrm_s[512];
  int tid = threadIdx.x;
  size_t base = (size_t)blockIdx.x*64;
  for (int i=tid;i<4096;i+=128) CBf[i]=g_wfragcb[i];
  for (int i=tid;i<512;i+=128) Ws3[i]=g_wfragw3[i];
  for (int i=tid;i<512;i+=128) nrm_s[i]=g_nrm[i];
  for (int i=tid;i<512;i+=128){
    int px=i>>3, ch=i&7;
    uint4 v = *(const uint4*)&g_b2h[(base+px)*64 + ch*8];
    *(uint4*)&As[px*144 + ch*16] = v;
  }
  __syncthreads();
  u32 aSm=smem_u32(As), cbSm=smem_u32(CBf), wSm=smem_u32(Ws3);
  int lane=tid&31, wid=tid>>5;
  int g=lane>>2, tig=lane&3;
  u32 laneRow=(u32)(lane&15), laneCol=(lane&16)?16u:0u;
  float zc[2][4];
  #pragma unroll
  for (int ntv=0;ntv<2;ntv++){
    float bA=b3[ntv*8+2*tig], bB=b3[ntv*8+2*tig+1];
    zc[ntv][0]=bA; zc[ntv][1]=bB; zc[ntv][2]=bA; zc[ntv][3]=bB;
  }
  u32 abase = aSm + (u32)(wid*16+laneRow)*144 + laneCol;
  #pragma unroll
  for (int kt=0;kt<4;kt++){
    u32 a0,a1,a2,a3;
    asm volatile("ldmatrix.sync.aligned.m8n8.x4.shared.b16 {%0,%1,%2,%3}, [%4];"
                 : "=r"(a0),"=r"(a1),"=r"(a2),"=r"(a3) : "r"(abase + kt*32));
    #pragma unroll
    for (int ntv=0;ntv<2;ntv++){
      u32 b0,b1;
      asm volatile("ld.shared.v2.u32 {%0,%1}, [%2];"
                   : "=r"(b0),"=r"(b1)
                   : "r"(wSm + ((kt*2+ntv)*64 + lane*2)*4));
      asm volatile("mma.sync.aligned.m16n8k16.row.col.f32.bf16.bf16.f32 "
                   "{%0,%1,%2,%3}, {%4,%5,%6,%7}, {%8,%9}, {%0,%1,%2,%3};"
                   : "+f"(zc[ntv][0]),"+f"(zc[ntv][1]),"+f"(zc[ntv][2]),"+f"(zc[ntv][3])
                   : "r"(a0),"r"(a1),"r"(a2),"r"(a3),"r"(b0),"r"(b1));
    }
  }
  u32 aZ0=bfpack(zc[0][0],zc[0][1]);
  u32 aZ1=bfpack(zc[0][2],zc[0][3]);
  u32 aZ2=bfpack(zc[1][0],zc[1][1]);
  u32 aZ3=bfpack(zc[1][2],zc[1][3]);
  float best0=-3.4e38f, best1=-3.4e38f; int bi0=0, bi1=0;
  for (int chunk=0;chunk<64;chunk++){
    float2 nk = *(const float2*)&nrm_s[chunk*8+2*tig];
    float s0=-nk.x, s1=-nk.y, s2=-nk.x, s3=-nk.y;
    u32 b0,b1;
    asm volatile("ld.shared.v2.u32 {%0,%1}, [%2];"
                 : "=r"(b0),"=r"(b1)
                 : "r"(cbSm + (chunk*64 + lane*2)*4));
    asm volatile("mma.sync.aligned.m16n8k16.row.col.f32.bf16.bf16.f32 "
                 "{%0,%1,%2,%3}, {%4,%5,%6,%7}, {%8,%9}, {%0,%1,%2,%3};"
                 : "+f"(s0),"+f"(s1),"+f"(s2),"+f"(s3)
                 : "r"(aZ0),"r"(aZ1),"r"(aZ2),"r"(aZ3),"r"(b0),"r"(b1));
    int i0 = chunk*8 + 2*tig;
    float cs; int ci;
    if (s1>s0){cs=s1;ci=i0+1;} else {cs=s0;ci=i0;}
    if (cs>best0){best0=cs;bi0=ci;}
    if (s3>s2){cs=s3;ci=i0+1;} else {cs=s2;ci=i0;}
    if (cs>best1){best1=cs;bi1=ci;}
  }
  #pragma unroll
  for (int off=1;off<4;off<<=1){
    float os=__shfl_xor_sync(0xffffffffu,best0,off);
    int   oi=__shfl_xor_sync(0xffffffffu,bi0,off);
    if (os>best0 || (os==best0 && oi<bi0)){best0=os;bi0=oi;}
    os=__shfl_xor_sync(0xffffffffu,best1,off);
    oi=__shfl_xor_sync(0xffffffffu,bi1,off);
    if (os>best1 || (os==best1 && oi<bi1)){best1=os;bi1=oi;}
  }
  size_t px0 = base + wid*16 + g, px1 = px0 + 8;
  float ls=0.f;
  {
    const float* e = cb + (size_t)bi0*16;
    *(u32*)&g_qh[px0*16 + tig*4]     = bfpack(e[tig*4],e[tig*4+1]);
    *(u32*)&g_qh[px0*16 + tig*4 + 2] = bfpack(e[tig*4+2],e[tig*4+3]);
    float d0=e[2*tig]-zc[0][0],   d1=e[2*tig+1]-zc[0][1];
    float d2=e[8+2*tig]-zc[1][0], d3=e[8+2*tig+1]-zc[1][1];
    ls = fmaf(d0,d0, fmaf(d1,d1, fmaf(d2,d2, fmaf(d3,d3, ls))));
  }
  {
    const float* e = cb + (size_t)bi1*16;
    *(u32*)&g_qh[px1*16 + tig*4]     = bfpack(e[tig*4],e[tig*4+1]);
    *(u32*)&g_qh[px1*16 + tig*4 + 2] = bfpack(e[tig*4+2],e[tig*4+3]);
    float d0=e[2*tig]-zc[0][2],   d1=e[2*tig+1]-zc[0][3];
    float d2=e[8+2*tig]-zc[1][2], d3=e[8+2*tig+1]-zc[1][3];
    ls = fmaf(d0,d0, fmaf(d1,d1, fmaf(d2,d2, fmaf(d3,d3, ls))));
  }
  float s = blockReduceSum(ls);
  if (tid==0) atomicAdd(&g_acc[0], (double)s);
}

// ------------- dec1: convT 16->64 via mma, ALL 4 parity classes merged ------
__global__ __launch_bounds__(128) void dec1m_k(const float* __restrict__ bias){
  constexpr int ROWB = 65*48;
  __shared__ __align__(16) unsigned char As[2*ROWB];
  __shared__ __align__(16) u32 Bs[4608];
  __shared__ float bias_s[64];
  int tid = threadIdx.x, bx = blockIdx.x;
  int hb = bx & 63, b = bx >> 6;
  for (int i=tid;i<4608;i+=128) Bs[i]=g_wfragd1[i];
  if (tid<64) bias_s[tid]=bias[tid];
  for (int i=tid;i<2*65*2;i+=128){
    int r=i/130, rem=i%130, px=rem>>1, hf=rem&1;
    int hi=hb+r;
    uint4 v=make_uint4(0,0,0,0);
    if (hi<64 && px<64)
      v=*(const uint4*)&g_qh[(((size_t)(b*64+hi))*64+px)*16 + hf*8];
    *(uint4*)&As[r*ROWB+px*48+hf*16]=v;
  }
  __syncthreads();
  u32 aSm = smem_u32(As), bSm = smem_u32(Bs);
  int lane = tid&31, wid = tid>>5;
  int g = lane>>2, tig = lane&3;
  u32 laneRow = (u32)(lane & 15);
  u32 laneCol = (lane & 16) ? 16u : 0u;
  for (int ph=0; ph<2; ph++){
    for (int pw=0; pw<2; pw++){
      float c[8][4];
      #pragma unroll
      for (int ntv=0;ntv<8;ntv++){
        float bA=bias_s[ntv*8+2*tig], bB=bias_s[ntv*8+2*tig+1];
        c[ntv][0]=bA; c[ntv][1]=bB; c[ntv][2]=bA; c[ntv][3]=bB;
      }
      int nkh = ph?2:1, nkw = pw?2:1;
      for (int a=0;a<nkh;a++){
        int kh = ph ? a*2 : 1;
        int rtap = (ph && a==0) ? 1 : 0;
        for (int cc=0;cc<nkw;cc++){
          int kw = pw ? cc*2 : 1;
          int shift = (pw && cc==0) ? 1 : 0;
          int tap = kh*3+kw;
          u32 abase = aSm + rtap*ROWB + (wid*16 + shift + laneRow)*48 + laneCol;
          u32 a0,a1,a2,a3;
          asm volatile("ldmatrix.sync.aligned.m8n8.x4.shared.b16 {%0,%1,%2,%3}, [%4];"
                       : "=r"(a0),"=r"(a1),"=r"(a2),"=r"(a3) : "r"(abase));
          #pragma unroll
          for (int ntv=0;ntv<8;ntv++){
            u32 b0,b1;
            asm volatile("ld.shared.v2.u32 {%0,%1}, [%2];"
                         : "=r"(b0),"=r"(b1)
                         : "r"(bSm + ((tap*8+ntv)*64 + lane*2)*4));
            asm volatile("mma.sync.aligned.m16n8k16.row.col.f32.bf16.bf16.f32 "
                         "{%0,%1,%2,%3}, {%4,%5,%6,%7}, {%8,%9}, {%0,%1,%2,%3};"
                         : "+f"(c[ntv][0]),"+f"(c[ntv][1]),"+f"(c[ntv][2]),"+f"(c[ntv][3])
                         : "r"(a0),"r"(a1),"r"(a2),"r"(a3),"r"(b0),"r"(b1));
          }
        }
      }
      int ho = 2*hb+ph;
      int wbA = wid*16+g, wbB = wbA+8;
      unsigned short* rb = g_d1h + ((size_t)(b*128+ho))*128*64;
      unsigned short* pA = rb + (size_t)(2*wbA+pw)*64 + 2*tig;
      unsigned short* pB = rb + (size_t)(2*wbB+pw)*64 + 2*tig;
      #pragma unroll
      for (int ntv=0;ntv<8;ntv++){
        *(u32*)(pA + ntv*8) = bfpack(fmaxf(c[ntv][0],0.f), fmaxf(c[ntv][1],0.f));
        *(u32*)(pB + ntv*8) = bfpack(fmaxf(c[ntv][2],0.f), fmaxf(c[ntv][3],0.f));
      }
    }
  }
}

// ------------- dec2: convT 64->32 via mma, ALL 4 parity classes merged ------
__global__ __launch_bounds__(128) void dec2m_k(const float* __restrict__ bias){
  constexpr int ROWB = 65*144;
  __shared__ __align__(16) unsigned char As[2*ROWB];
  __shared__ __align__(16) u32 Bs[9216];
  __shared__ float bias_s[32];
  int tid = threadIdx.x, bx = blockIdx.x;
  int wchunk = bx & 1, hb = (bx>>1)&127, b = bx>>8;
  int wb0 = wchunk*64;
  for (int i=tid;i<9216;i+=128) Bs[i]=g_wfrag[i];
  if (tid<32) bias_s[tid]=bias[tid];
  for (int i=tid;i<2*65*8;i+=128){
    int r = i/520, rem = i%520, px = rem>>3, ch = rem&7;
    int hi = hb + r;
    int wi = wb0 + px;
    uint4 v = make_uint4(0,0,0,0);
    if (hi<128 && wi<128)
      v = *(const uint4*)&g_d1h[(((size_t)(b*128+hi))*128+wi)*64 + ch*8];
    *(uint4*)&As[r*ROWB + px*144 + ch*16] = v;
  }
  __syncthreads();
  u32 aSm = smem_u32(As), bSm = smem_u32(Bs);
  int lane = tid & 31, wid = tid>>5;
  int g = lane>>2, tig = lane&3;
  u32 laneRow = (u32)(lane & 15);
  u32 laneCol = (lane & 16) ? 16u : 0u;
  for (int ph=0; ph<2; ph++){
    for (int pw=0; pw<2; pw++){
      float c[4][4];
      #pragma unroll
      for (int ntv=0;ntv<4;ntv++){
        float bA = bias_s[ntv*8+2*tig], bB = bias_s[ntv*8+2*tig+1];
        c[ntv][0]=bA; c[ntv][1]=bB; c[ntv][2]=bA; c[ntv][3]=bB;
      }
      int nkh = ph?2:1, nkw = pw?2:1;
      for (int a=0;a<nkh;a++){
        int kh = ph ? a*2 : 1;
        int rtap = (ph && a==0) ? 1 : 0;
        for (int cc=0;cc<nkw;cc++){
          int kw = pw ? cc*2 : 1;
          int shift = (pw && cc==0) ? 1 : 0;
          int tap = kh*3+kw;
          u32 abase = aSm + rtap*ROWB + (wid*16 + shift + laneRow)*144 + laneCol;
          #pragma unroll
          for (int kt=0;kt<4;kt++){
            u32 a0,a1,a2,a3;
            asm volatile("ldmatrix.sync.aligned.m8n8.x4.shared.b16 {%0,%1,%2,%3}, [%4];"
                         : "=r"(a0),"=r"(a1),"=r"(a2),"=r"(a3)
                         : "r"(abase + kt*32));
            #pragma unroll
            for (int ntv=0;ntv<4;ntv++){
              u32 b0,b1;
              asm volatile("ld.shared.v2.u32 {%0,%1}, [%2];"
                           : "=r"(b0),"=r"(b1)
                           : "r"(bSm + (((tap*4+kt)*4+ntv)*64 + lane*2)*4));
              asm volatile("mma.sync.aligned.m16n8k16.row.col.f32.bf16.bf16.f32 "
                           "{%0,%1,%2,%3}, {%4,%5,%6,%7}, {%8,%9}, {%0,%1,%2,%3};"
                           : "+f"(c[ntv][0]),"+f"(c[ntv][1]),"+f"(c[ntv][2]),"+f"(c[ntv][3])
                           : "r"(a0),"r"(a1),"r"(a2),"r"(a3),"r"(b0),"r"(b1));
            }
          }
        }
      }
      int ho = 2*hb+ph;
      int wbA = wb0 + wid*16 + g, wbB = wbA + 8;
      unsigned short* rowBase = g_d2h + ((size_t)(b*256+ho))*256*32;
      unsigned short* pA = rowBase + (size_t)(2*wbA+pw)*32 + 2*tig;
      unsigned short* pB = rowBase + (size_t)(2*wbB+pw)*32 + 2*tig;
      #pragma unroll
      for (int ntv=0;ntv<4;ntv++){
        *(u32*)(pA + ntv*8) = bfpack(fmaxf(c[ntv][0],0.f), fmaxf(c[ntv][1],0.f));
        *(u32*)(pB + ntv*8) = bfpack(fmaxf(c[ntv][2],0.f), fmaxf(c[ntv][3],0.f));
      }
    }
  }
}

// ------------- dec3: conv 32->3 via mma bf16 + fused recon MSE --------------
__global__ __launch_bounds__(128) void dec3_mma_k(const float* __restrict__ x,
                                                  const float* __restrict__ bias){
  constexpr int PXB = 80;
  __shared__ __align__(16) unsigned char As[3*66*PXB];
  __shared__ __align__(16) u32 Bs[1152];
  __shared__ float bias_s[3];
  int tid = threadIdx.x, bx = blockIdx.x;
  int wchunk = bx & 3, ho = (bx>>2)&255, b = bx>>10;
  int wb0 = wchunk*64;
  for (int i=tid;i<1152;i+=128) Bs[i]=g_wfragd3[i];
  if (tid<3) bias_s[tid]=bias[tid];
  for (int i=tid;i<3*66*4;i+=128){
    int r=i/264, rem=i%264, px=rem>>2, q=rem&3;
    int hi=ho-1+r, wi=wb0-1+px;
    uint4 v=make_uint4(0,0,0,0);
    if ((unsigned)hi<256u && (unsigned)wi<256u)
      v=*(const uint4*)&g_d2h[(((size_t)(b*256+hi))*256+wi)*32 + q*8];
    *(uint4*)&As[(r*66+px)*PXB + q*16]=v;
  }
  __syncthreads();
  u32 aSm=smem_u32(As), bSm=smem_u32(Bs);
  int lane=tid&31, wid=tid>>5;
  int g=lane>>2, tig=lane&3;
  float c[4]={0.f,0.f,0.f,0.f};
  u32 laneRow=(u32)(lane&15);
  u32 laneCol=(lane&16)?16u:0u;
  #pragma unroll
  for (int kh=0;kh<3;kh++){
    #pragma unroll
    for (int kw=0;kw<3;kw++){
      int tap=kh*3+kw;
      u32 abase = aSm + (u32)(kh*66 + wid*16 + kw + laneRow)*PXB + laneCol;
      #pragma unroll
      for (int kt=0;kt<2;kt++){
        u32 a0,a1,a2,a3;
        asm volatile("ldmatrix.sync.aligned.m8n8.x4.shared.b16 {%0,%1,%2,%3}, [%4];"
                     : "=r"(a0),"=r"(a1),"=r"(a2),"=r"(a3) : "r"(abase + kt*32));
        u32 b0,b1;
        asm volatile("ld.shared.v2.u32 {%0,%1}, [%2];"
                     : "=r"(b0),"=r"(b1)
                     : "r"(bSm + ((tap*2+kt)*64 + lane*2)*4));
        asm volatile("mma.sync.aligned.m16n8k16.row.col.f32.bf16.bf16.f32 "
                     "{%0,%1,%2,%3}, {%4,%5,%6,%7}, {%8,%9}, {%0,%1,%2,%3};"
                     : "+f"(c[0]),"+f"(c[1]),"+f"(c[2]),"+f"(c[3])
                     : "r"(a0),"r"(a1),"r"(a2),"r"(a3),"r"(b0),"r"(b1));
      }
    }
  }
  int pxA = wb0 + wid*16 + g, pxB = pxA + 8;
  const float* xb = x + (size_t)b*3*65536 + ho*256;
  float ls = 0.f;
  int co0 = 2*tig, co1 = co0+1;
  if (co0 < 3){
    float d0 = c[0] + bias_s[co0] - xb[(size_t)co0*65536 + pxA];
    float d1 = c[2] + bias_s[co0] - xb[(size_t)co0*65536 + pxB];
    ls = fmaf(d0,d0, fmaf(d1,d1, ls));
  }
  if (co1 < 3){
    float d0 = c[1] + bias_s[co1] - xb[(size_t)co1*65536 + pxA];
    float d1 = c[3] + bias_s[co1] - xb[(size_t)co1*65536 + pxB];
    ls = fmaf(d0,d0, fmaf(d1,d1, ls));
  }
  float s = blockReduceSum(ls);
  if (tid==0) atomicAdd(&g_acc[1], (double)s);
}

// ------------- finalize -----------------------------------------------------
__global__ void final_k(float* __restrict__ out){
  double vq  = g_acc[0];
  double rec = g_acc[1];
  float e_q  = (float)(1.25 * vq / 4194304.0);
  float mse  = (float)(rec / 12582912.0);
  out[0] = e_q;
  out[1] = mse;
  out[2] = mse;
}

// ---------------- launch ----------------------------------------------------
extern "C" void kernel_launch(void* const* d_in, const int* in_sizes, int n_in,
                              void* d_out, int out_size){
  const float* x   = (const float*)d_in[0];
  const float* ew1 = (const float*)d_in[1];
  const float* eb1 = (const float*)d_in[2];
  const float* ew2 = (const float*)d_in[3];
  const float* eb2 = (const float*)d_in[4];
  const float* ew3 = (const float*)d_in[5];
  const float* eb3 = (const float*)d_in[6];
  const float* cb  = (const float*)d_in[7];
  const float* dw1 = (const float*)d_in[8];
  const float* db1 = (const float*)d_in[9];
  const float* dw2 = (const float*)d_in[10];
  const float* db2 = (const float*)d_in[11];
  const float* dw3 = (const float*)d_in[12];
  const float* db3 = (const float*)d_in[13];
  float* out = (float*)d_out;

  repack_k<<<64,256>>>(ew1, ew2, dw1, dw2, dw3, ew3, cb);
  enc1_mma_k<<<16384,128>>>(x, eb1);
  enc2_mma_k<<<4096,128>>>(eb2);
  vq_mma_k<<<4096,128>>>(cb, eb3);
  dec1m_k<<<4096,128>>>(db1);
  dec2m_k<<<16384,128>>>(db2);
  dec3_mma_k<<<65536,128>>>(x, db3);
  final_k<<<1,1>>>(out);
}

// round 11
// speedup vs baseline: 5.2834x; 1.3794x over previous
#include <cuda_runtime.h>
#include <cuda_bf16.h>
#include <cstdint>

typedef unsigned long long u64;
typedef unsigned int u32;

// ---------------- scratch (device globals; no allocations allowed) ----------
__device__ unsigned short g_b1h[(size_t)64*128*128*32];  // enc1 out NHWC bf16
__device__ unsigned short g_b2h[(size_t)64*64*64*64];    // enc2 out NHWC bf16
__device__ unsigned short g_qh[(size_t)64*64*64*16];     // quantized NHWC bf16
__device__ unsigned short g_d1h[(size_t)64*128*128*64];  // dec1 out NHWC bf16
__device__ unsigned short g_d2h[(size_t)64*256*256*32];  // dec2 out NHWC bf16

__device__ u32   g_wfrag1[512];     // enc1 w  B-frags
__device__ u32   g_wfrag2[18432];   // enc2 w  B-frags
__device__ u32   g_wfragd1[4608];   // dec1 w  B-frags
__device__ u32   g_wfrag[9216];     // dec2 w  B-frags
__device__ u32   g_wfragd3[1152];   // dec3 w  B-frags (flip baked)
__device__ u32   g_wfragw3[512];    // enc3(1x1) w B-frags
__device__ u32   g_wfragcb[4096];   // codebook B-frags
__device__ float g_nrm[512];        // 0.5*||e_k||^2 (fp32)
__device__ double g_acc[2];         // [0]=vq sq-sum, [1]=recon sq-sum

// ---------------- helpers ----------------------------------------------------
__device__ __forceinline__ u32 bfpack(float lo, float hi){
  u32 r; asm("cvt.rn.bf16x2.f32 %0, %1, %2;" : "=r"(r) : "f"(hi), "f"(lo));
  return r;
}
__device__ __forceinline__ u32 smem_u32(const void* p){
  u32 a; asm("{ .reg .u64 t; cvta.to.shared.u64 t, %1; cvt.u32.u64 %0, t; }"
             : "=r"(a) : "l"(p));
  return a;
}
__device__ __forceinline__ float blockReduceSum(float v){
  __shared__ float red[32];
  #pragma unroll
  for (int o=16;o;o>>=1) v += __shfl_down_sync(0xffffffffu, v, o);
  int lane = threadIdx.x & 31, w = threadIdx.x >> 5;
  if (lane==0) red[w]=v;
  __syncthreads();
  if (w==0){
    v = (lane < ((int)blockDim.x>>5)) ? red[lane] : 0.f;
    #pragma unroll
    for (int o=16;o;o>>=1) v += __shfl_down_sync(0xffffffffu, v, o);
  }
  return v;
}
__device__ __forceinline__ unsigned short f2bf(float v){
  return __bfloat16_as_ushort(__float2bfloat16(v));
}

// ---------------- weight repack + accumulator reset -------------------------
__global__ void repack_k(const float* __restrict__ ew1, const float* __restrict__ ew2,
                         const float* __restrict__ dw1, const float* __restrict__ dw2,
                         const float* __restrict__ dw3, const float* __restrict__ w3,
                         const float* __restrict__ cb){
  int t = blockIdx.x*blockDim.x + threadIdx.x;
  int nt = gridDim.x*blockDim.x;
  if (blockIdx.x==0 && threadIdx.x<2) g_acc[threadIdx.x]=0.0;
  for (int i=t;i<512;i+=nt){
    int reg=i&1; int lane=(i>>1)&31; int ntv=(i>>6)&3; int kt=i>>8;
    int gg=lane>>2, tg=lane&3;
    int co = ntv*8+gg;
    int k0 = kt*16 + 2*tg + (reg?8:0);
    float w0=0.f, w1=0.f;
    if (k0<27){ int kh=k0/9, r=k0%9, kw=r/3, ci=r%3;
      w0 = ew1[((co*3+ci)*3+kh)*3+kw]; }
    if (k0+1<27){ int k1=k0+1; int kh=k1/9, r=k1%9, kw=r/3, ci=r%3;
      w1 = ew1[((co*3+ci)*3+kh)*3+kw]; }
    g_wfrag1[i] = (u32)f2bf(w0) | ((u32)f2bf(w1)<<16);
  }
  for (int i=t;i<18432;i+=nt){
    int reg=i&1; int lane=(i>>1)&31; int ntv=(i>>6)&7; int kt=(i>>9)&1; int tap=i>>10;
    int kh=tap/3, kw=tap%3;
    int gg=lane>>2, tg=lane&3;
    int co = ntv*8+gg;
    int ci0 = kt*16 + 2*tg + (reg?8:0);
    g_wfrag2[i] = (u32)f2bf(ew2[((co*32+ci0)*3+kh)*3+kw])
                | ((u32)f2bf(ew2[((co*32+ci0+1)*3+kh)*3+kw])<<16);
  }
  for (int i=t;i<4608;i+=nt){
    int reg=i&1; int lane=(i>>1)&31; int ntv=(i>>6)&7; int tap=i>>9;
    int kh=tap/3, kw=tap%3;
    int gg=lane>>2, tg=lane&3;
    int co = ntv*8+gg;
    int ci0 = 2*tg + (reg?8:0);
    g_wfragd1[i] = (u32)f2bf(dw1[((ci0*64+co)*3+kh)*3+kw])
                 | ((u32)f2bf(dw1[(((ci0+1)*64+co)*3+kh)*3+kw])<<16);
  }
  for (int i=t;i<9216;i+=nt){
    int tap = i>>10; int w_ = i & 1023;
    int reg = w_ & 1; int lane = (w_>>1)&31; int ntv = (w_>>6)&3; int kt = (w_>>8)&3;
    int kh = tap/3, kw = tap%3;
    int gg = lane>>2, tg = lane&3;
    int co = ntv*8+gg;
    int ci0 = kt*16 + 2*tg + (reg?8:0);
    g_wfrag[i] = (u32)f2bf(dw2[((ci0*32+co)*3+kh)*3+kw])
               | ((u32)f2bf(dw2[(((ci0+1)*32+co)*3+kh)*3+kw])<<16);
  }
  for (int i=t;i<1152;i+=nt){
    int reg=i&1; int lane=(i>>1)&31; int kt=(i>>6)&1; int tap=i>>7;
    int kh=tap/3, kw=tap%3;
    int gg=lane>>2, tg=lane&3;
    int co=gg;
    int ci0 = kt*16 + 2*tg + (reg?8:0);
    float w0=0.f, w1=0.f;
    if (co<3){
      w0 = dw3[((ci0*3+co)*3+(2-kh))*3+(2-kw)];
      w1 = dw3[(((ci0+1)*3+co)*3+(2-kh))*3+(2-kw)];
    }
    g_wfragd3[i] = (u32)f2bf(w0) | ((u32)f2bf(w1)<<16);
  }
  for (int i=t;i<512;i+=nt){
    int reg=i&1; int lane=(i>>1)&31; int ntv=(i>>6)&1; int kt=i>>7;
    int gg=lane>>2, tg=lane&3;
    int d = ntv*8+gg;
    int ci0 = kt*16 + 2*tg + (reg?8:0);
    g_wfragw3[i] = (u32)f2bf(w3[d*64+ci0]) | ((u32)f2bf(w3[d*64+ci0+1])<<16);
  }
  for (int i=t;i<4096;i+=nt){
    int reg=i&1; int lane=(i>>1)&31; int chunk=i>>6;
    int gg=lane>>2, tg=lane&3;
    int cw = chunk*8+gg;
    int d0 = 2*tg + (reg?8:0);
    g_wfragcb[i] = (u32)f2bf(cb[cw*16+d0]) | ((u32)f2bf(cb[cw*16+d0+1])<<16);
  }
  for (int k=t;k<512;k+=nt){
    float s=0.f;
    #pragma unroll
    for (int d=0;d<16;d++){ float e=cb[k*16+d]; s=fmaf(e,e,s); }
    g_nrm[k]=0.5f*s;
  }
}

// ---------------- enc1: 3->32 k3 s2 p1 relu via mma (smem im2col) -----------
__global__ __launch_bounds__(128) void enc1_mma_k(const float* __restrict__ x,
                                                  const float* __restrict__ bias){
  constexpr int PXB = 80;
  __shared__ __align__(16) unsigned char As[64*PXB];
  __shared__ float bias_s[32];
  int tid = threadIdx.x, bx = blockIdx.x;
  int wchunk = bx & 1, ho = (bx>>1)&127, b = bx>>8;
  int wb0 = wchunk*64;
  if (tid<32) bias_s[tid]=bias[tid];
  const float* xb = x + (size_t)b*3*65536;
  for (int i=tid;i<2048;i+=128){
    int k=i>>6, px=i&63;
    unsigned short h=0;
    if (k<27){
      int kh=k/9, r=k%9, kw=r/3, ci=r%3;
      int hi=2*ho-1+kh, wi=2*(wb0+px)-1+kw;
      if ((unsigned)hi<256u && (unsigned)wi<256u)
        h = f2bf(xb[(size_t)ci*65536 + hi*256 + wi]);
    }
    *(unsigned short*)&As[px*PXB + k*2] = h;
  }
  __syncthreads();
  u32 aSm = smem_u32(As);
  int lane=tid&31, wid=tid>>5;
  int g=lane>>2, tig=lane&3;
  u32 laneRow=(u32)(lane&15), laneCol=(lane&16)?16u:0u;
  float c[4][4];
  #pragma unroll
  for (int ntv=0;ntv<4;ntv++){
    float bA=bias_s[ntv*8+2*tig], bB=bias_s[ntv*8+2*tig+1];
    c[ntv][0]=bA; c[ntv][1]=bB; c[ntv][2]=bA; c[ntv][3]=bB;
  }
  u32 abase = aSm + (u32)(wid*16+laneRow)*PXB + laneCol;
  #pragma unroll
  for (int kt=0;kt<2;kt++){
    u32 a0,a1,a2,a3;
    asm volatile("ldmatrix.sync.aligned.m8n8.x4.shared.b16 {%0,%1,%2,%3}, [%4];"
                 : "=r"(a0),"=r"(a1),"=r"(a2),"=r"(a3) : "r"(abase + kt*32));
    #pragma unroll
    for (int ntv=0;ntv<4;ntv++){
      uint2 bv = *(const uint2*)&g_wfrag1[(kt*4+ntv)*64 + lane*2];
      asm volatile("mma.sync.aligned.m16n8k16.row.col.f32.bf16.bf16.f32 "
                   "{%0,%1,%2,%3}, {%4,%5,%6,%7}, {%8,%9}, {%0,%1,%2,%3};"
                   : "+f"(c[ntv][0]),"+f"(c[ntv][1]),"+f"(c[ntv][2]),"+f"(c[ntv][3])
                   : "r"(a0),"r"(a1),"r"(a2),"r"(a3),"r"(bv.x),"r"(bv.y));
    }
  }
  int woA = wb0 + wid*16 + g, woB = woA + 8;
  unsigned short* rb = g_b1h + ((size_t)(b*128+ho))*128*32;
  unsigned short* pA = rb + (size_t)woA*32 + 2*tig;
  unsigned short* pB = rb + (size_t)woB*32 + 2*tig;
  #pragma unroll
  for (int ntv=0;ntv<4;ntv++){
    *(u32*)(pA + ntv*8) = bfpack(fmaxf(c[ntv][0],0.f), fmaxf(c[ntv][1],0.f));
    *(u32*)(pB + ntv*8) = bfpack(fmaxf(c[ntv][2],0.f), fmaxf(c[ntv][3],0.f));
  }
}

// ---------------- enc2: 32->64 k3 s2 p1 relu via mma bf16; bf16 out ---------
__global__ __launch_bounds__(128) void enc2_mma_k(const float* __restrict__ bias){
  constexpr int ROWB = 129*80;
  __shared__ __align__(16) unsigned char As[3*ROWB];
  __shared__ float bias_s[64];
  int tid = threadIdx.x, bx = blockIdx.x;
  int ho = bx & 63, b = bx >> 6;
  if (tid<64) bias_s[tid]=bias[tid];
  for (int i=tid;i<3*129*4;i+=128){
    int r=i/516, rem=i%516, px=rem>>2, ch=rem&3;
    int hi=2*ho-1+r, wi=px-1;
    uint4 v=make_uint4(0,0,0,0);
    if ((unsigned)hi<128u && (unsigned)wi<128u)
      v = *(const uint4*)&g_b1h[(((size_t)(b*128+hi))*128+wi)*32 + ch*8];
    *(uint4*)&As[r*ROWB + px*80 + ch*16] = v;
  }
  __syncthreads();
  u32 aSm = smem_u32(As);
  int lane = tid&31, wid = tid>>5;
  int g = lane>>2, tig = lane&3;
  float c[8][4];
  #pragma unroll
  for (int ntv=0;ntv<8;ntv++){
    float bA=bias_s[ntv*8+2*tig], bB=bias_s[ntv*8+2*tig+1];
    c[ntv][0]=bA; c[ntv][1]=bB; c[ntv][2]=bA; c[ntv][3]=bB;
  }
  u32 laneRow = (u32)(lane & 15);
  u32 laneCol = (lane & 16) ? 16u : 0u;
  #pragma unroll
  for (int kh=0;kh<3;kh++){
    #pragma unroll
    for (int kw=0;kw<3;kw++){
      int tap = kh*3+kw;
      #pragma unroll
      for (int kt=0;kt<2;kt++){
        u32 abase = aSm + kh*ROWB + (wid*32 + 2*laneRow + kw)*80 + kt*32 + laneCol;
        u32 a0,a1,a2,a3;
        asm volatile("ldmatrix.sync.aligned.m8n8.x4.shared.b16 {%0,%1,%2,%3}, [%4];"
                     : "=r"(a0),"=r"(a1),"=r"(a2),"=r"(a3) : "r"(abase));
        #pragma unroll
        for (int ntv=0;ntv<8;ntv++){
          uint2 bv = *(const uint2*)&g_wfrag2[tap*1024 + kt*512 + ntv*64 + lane*2];
          asm volatile("mma.sync.aligned.m16n8k16.row.col.f32.bf16.bf16.f32 "
                       "{%0,%1,%2,%3}, {%4,%5,%6,%7}, {%8,%9}, {%0,%1,%2,%3};"
                       : "+f"(c[ntv][0]),"+f"(c[ntv][1]),"+f"(c[ntv][2]),"+f"(c[ntv][3])
                       : "r"(a0),"r"(a1),"r"(a2),"r"(a3),"r"(bv.x),"r"(bv.y));
        }
      }
    }
  }
  int woA = wid*16+g, woB = woA+8;
  unsigned short* base = g_b2h + ((size_t)(b*64+ho))*64*64;
  unsigned short* pA = base + (size_t)woA*64 + 2*tig;
  unsigned short* pB = base + (size_t)woB*64 + 2*tig;
  #pragma unroll
  for (int ntv=0;ntv<8;ntv++){
    *(u32*)(pA + ntv*8) = bfpack(fmaxf(c[ntv][0],0.f), fmaxf(c[ntv][1],0.f));
    *(u32*)(pB + ntv*8) = bfpack(fmaxf(c[ntv][2],0.f), fmaxf(c[ntv][3],0.f));
  }
}

// ------------- VQ via mma: z-GEMM + scoring GEMM + quantize + loss ----------
__global__ __launch_bounds__(128) void vq_mma_k(const float* __restrict__ cb,
                                                const float* __restrict__ b3){
  __shared__ __align__(16) unsigned char As[64*144];
  __shared__ __align__(16) u32 CBf[4096];
  __shared__ __align__(8) float nrm_s[512];
  int tid = threadIdx.x;
  size_t base = (size_t)blockIdx.x*64;
  for (int i=tid;i<4096;i+=128) CBf[i]=g_wfragcb[i];
  for (int i=tid;i<512;i+=128) nrm_s[i]=g_nrm[i];
  for (int i=tid;i<512;i+=128){
    int px=i>>3, ch=i&7;
    uint4 v = *(const uint4*)&g_b2h[(base+px)*64 + ch*8];
    *(uint4*)&As[px*144 + ch*16] = v;
  }
  __syncthreads();
  u32 aSm=smem_u32(As), cbSm=smem_u32(CBf);
  int lane=tid&31, wid=tid>>5;
  int g=lane>>2, tig=lane&3;
  u32 laneRow=(u32)(lane&15), laneCol=(lane&16)?16u:0u;
  float zc[2][4];
  #pragma unroll
  for (int ntv=0;ntv<2;ntv++){
    float bA=b3[ntv*8+2*tig], bB=b3[ntv*8+2*tig+1];
    zc[ntv][0]=bA; zc[ntv][1]=bB; zc[ntv][2]=bA; zc[ntv][3]=bB;
  }
  u32 abase = aSm + (u32)(wid*16+laneRow)*144 + laneCol;
  #pragma unroll
  for (int kt=0;kt<4;kt++){
    u32 a0,a1,a2,a3;
    asm volatile("ldmatrix.sync.aligned.m8n8.x4.shared.b16 {%0,%1,%2,%3}, [%4];"
                 : "=r"(a0),"=r"(a1),"=r"(a2),"=r"(a3) : "r"(abase + kt*32));
    #pragma unroll
    for (int ntv=0;ntv<2;ntv++){
      uint2 bv = *(const uint2*)&g_wfragw3[(kt*2+ntv)*64 + lane*2];
      asm volatile("mma.sync.aligned.m16n8k16.row.col.f32.bf16.bf16.f32 "
                   "{%0,%1,%2,%3}, {%4,%5,%6,%7}, {%8,%9}, {%0,%1,%2,%3};"
                   : "+f"(zc[ntv][0]),"+f"(zc[ntv][1]),"+f"(zc[ntv][2]),"+f"(zc[ntv][3])
                   : "r"(a0),"r"(a1),"r"(a2),"r"(a3),"r"(bv.x),"r"(bv.y));
    }
  }
  u32 aZ0=bfpack(zc[0][0],zc[0][1]);
  u32 aZ1=bfpack(zc[0][2],zc[0][3]);
  u32 aZ2=bfpack(zc[1][0],zc[1][1]);
  u32 aZ3=bfpack(zc[1][2],zc[1][3]);
  float best0=-3.4e38f, best1=-3.4e38f; int bi0=0, bi1=0;
  for (int chunk=0;chunk<64;chunk++){
    float2 nk = *(const float2*)&nrm_s[chunk*8+2*tig];
    float s0=-nk.x, s1=-nk.y, s2=-nk.x, s3=-nk.y;
    u32 b0,b1;
    asm volatile("ld.shared.v2.u32 {%0,%1}, [%2];"
                 : "=r"(b0),"=r"(b1)
                 : "r"(cbSm + (chunk*64 + lane*2)*4));
    asm volatile("mma.sync.aligned.m16n8k16.row.col.f32.bf16.bf16.f32 "
                 "{%0,%1,%2,%3}, {%4,%5,%6,%7}, {%8,%9}, {%0,%1,%2,%3};"
                 : "+f"(s0),"+f"(s1),"+f"(s2),"+f"(s3)
                 : "r"(aZ0),"r"(aZ1),"r"(aZ2),"r"(aZ3),"r"(b0),"r"(b1));
    int i0 = chunk*8 + 2*tig;
    float cs; int ci;
    if (s1>s0){cs=s1;ci=i0+1;} else {cs=s0;ci=i0;}
    if (cs>best0){best0=cs;bi0=ci;}
    if (s3>s2){cs=s3;ci=i0+1;} else {cs=s2;ci=i0;}
    if (cs>best1){best1=cs;bi1=ci;}
  }
  #pragma unroll
  for (int off=1;off<4;off<<=1){
    float os=__shfl_xor_sync(0xffffffffu,best0,off);
    int   oi=__shfl_xor_sync(0xffffffffu,bi0,off);
    if (os>best0 || (os==best0 && oi<bi0)){best0=os;bi0=oi;}
    os=__shfl_xor_sync(0xffffffffu,best1,off);
    oi=__shfl_xor_sync(0xffffffffu,bi1,off);
    if (os>best1 || (os==best1 && oi<bi1)){best1=os;bi1=oi;}
  }
  size_t px0 = base + wid*16 + g, px1 = px0 + 8;
  float ls=0.f;
  {
    const float* e = cb + (size_t)bi0*16;
    *(u32*)&g_qh[px0*16 + tig*4]     = bfpack(e[tig*4],e[tig*4+1]);
    *(u32*)&g_qh[px0*16 + tig*4 + 2] = bfpack(e[tig*4+2],e[tig*4+3]);
    float d0=e[2*tig]-zc[0][0],   d1=e[2*tig+1]-zc[0][1];
    float d2=e[8+2*tig]-zc[1][0], d3=e[8+2*tig+1]-zc[1][1];
    ls = fmaf(d0,d0, fmaf(d1,d1, fmaf(d2,d2, fmaf(d3,d3, ls))));
  }
  {
    const float* e = cb + (size_t)bi1*16;
    *(u32*)&g_qh[px1*16 + tig*4]     = bfpack(e[tig*4],e[tig*4+1]);
    *(u32*)&g_qh[px1*16 + tig*4 + 2] = bfpack(e[tig*4+2],e[tig*4+3]);
    float d0=e[2*tig]-zc[0][2],   d1=e[2*tig+1]-zc[0][3];
    float d2=e[8+2*tig]-zc[1][2], d3=e[8+2*tig+1]-zc[1][3];
    ls = fmaf(d0,d0, fmaf(d1,d1, fmaf(d2,d2, fmaf(d3,d3, ls))));
  }
  float s = blockReduceSum(ls);
  if (tid==0) atomicAdd(&g_acc[0], (double)s);
}

// ------------- dec1: convT 16->64 via mma, 4 parities merged, B from global -
__global__ __launch_bounds__(128) void dec1m_k(const float* __restrict__ bias){
  constexpr int ROWB = 65*48;
  __shared__ __align__(16) unsigned char As[2*ROWB];
  __shared__ float bias_s[64];
  int tid = threadIdx.x, bx = blockIdx.x;
  int hb = bx & 63, b = bx >> 6;
  if (tid<64) bias_s[tid]=bias[tid];
  for (int i=tid;i<2*65*2;i+=128){
    int r=i/130, rem=i%130, px=rem>>1, hf=rem&1;
    int hi=hb+r;
    uint4 v=make_uint4(0,0,0,0);
    if (hi<64 && px<64)
      v=*(const uint4*)&g_qh[(((size_t)(b*64+hi))*64+px)*16 + hf*8];
    *(uint4*)&As[r*ROWB+px*48+hf*16]=v;
  }
  __syncthreads();
  u32 aSm = smem_u32(As);
  int lane = tid&31, wid = tid>>5;
  int g = lane>>2, tig = lane&3;
  u32 laneRow = (u32)(lane & 15);
  u32 laneCol = (lane & 16) ? 16u : 0u;
  for (int ph=0; ph<2; ph++){
    for (int pw=0; pw<2; pw++){
      float c[8][4];
      #pragma unroll
      for (int ntv=0;ntv<8;ntv++){
        float bA=bias_s[ntv*8+2*tig], bB=bias_s[ntv*8+2*tig+1];
        c[ntv][0]=bA; c[ntv][1]=bB; c[ntv][2]=bA; c[ntv][3]=bB;
      }
      int nkh = ph?2:1, nkw = pw?2:1;
      for (int a=0;a<nkh;a++){
        int kh = ph ? a*2 : 1;
        int rtap = (ph && a==0) ? 1 : 0;
        for (int cc=0;cc<nkw;cc++){
          int kw = pw ? cc*2 : 1;
          int shift = (pw && cc==0) ? 1 : 0;
          int tap = kh*3+kw;
          u32 abase = aSm + rtap*ROWB + (wid*16 + shift + laneRow)*48 + laneCol;
          u32 a0,a1,a2,a3;
          asm volatile("ldmatrix.sync.aligned.m8n8.x4.shared.b16 {%0,%1,%2,%3}, [%4];"
                       : "=r"(a0),"=r"(a1),"=r"(a2),"=r"(a3) : "r"(abase));
          #pragma unroll
          for (int ntv=0;ntv<8;ntv++){
            uint2 bv = *(const uint2*)&g_wfragd1[(tap*8+ntv)*64 + lane*2];
            asm volatile("mma.sync.aligned.m16n8k16.row.col.f32.bf16.bf16.f32 "
                         "{%0,%1,%2,%3}, {%4,%5,%6,%7}, {%8,%9}, {%0,%1,%2,%3};"
                         : "+f"(c[ntv][0]),"+f"(c[ntv][1]),"+f"(c[ntv][2]),"+f"(c[ntv][3])
                         : "r"(a0),"r"(a1),"r"(a2),"r"(a3),"r"(bv.x),"r"(bv.y));
          }
        }
      }
      int ho = 2*hb+ph;
      int wbA = wid*16+g, wbB = wbA+8;
      unsigned short* rb = g_d1h + ((size_t)(b*128+ho))*128*64;
      unsigned short* pA = rb + (size_t)(2*wbA+pw)*64 + 2*tig;
      unsigned short* pB = rb + (size_t)(2*wbB+pw)*64 + 2*tig;
      #pragma unroll
      for (int ntv=0;ntv<8;ntv++){
        *(u32*)(pA + ntv*8) = bfpack(fmaxf(c[ntv][0],0.f), fmaxf(c[ntv][1],0.f));
        *(u32*)(pB + ntv*8) = bfpack(fmaxf(c[ntv][2],0.f), fmaxf(c[ntv][3],0.f));
      }
    }
  }
}

// ------------- dec2: convT 64->32 via mma, 4 parities merged, B from global -
__global__ __launch_bounds__(128) void dec2m_k(const float* __restrict__ bias){
  constexpr int ROWB = 65*144;
  __shared__ __align__(16) unsigned char As[2*ROWB];
  __shared__ float bias_s[32];
  int tid = threadIdx.x, bx = blockIdx.x;
  int wchunk = bx & 1, hb = (bx>>1)&127, b = bx>>8;
  int wb0 = wchunk*64;
  if (tid<32) bias_s[tid]=bias[tid];
  for (int i=tid;i<2*65*8;i+=128){
    int r = i/520, rem = i%520, px = rem>>3, ch = rem&7;
    int hi = hb + r;
    int wi = wb0 + px;
    uint4 v = make_uint4(0,0,0,0);
    if (hi<128 && wi<128)
      v = *(const uint4*)&g_d1h[(((size_t)(b*128+hi))*128+wi)*64 + ch*8];
    *(uint4*)&As[r*ROWB + px*144 + ch*16] = v;
  }
  __syncthreads();
  u32 aSm = smem_u32(As);
  int lane = tid & 31, wid = tid>>5;
  int g = lane>>2, tig = lane&3;
  u32 laneRow = (u32)(lane & 15);
  u32 laneCol = (lane & 16) ? 16u : 0u;
  for (int ph=0; ph<2; ph++){
    for (int pw=0; pw<2; pw++){
      float c[4][4];
      #pragma unroll
      for (int ntv=0;ntv<4;ntv++){
        float bA = bias_s[ntv*8+2*tig], bB = bias_s[ntv*8+2*tig+1];
        c[ntv][0]=bA; c[ntv][1]=bB; c[ntv][2]=bA; c[ntv][3]=bB;
      }
      int nkh = ph?2:1, nkw = pw?2:1;
      for (int a=0;a<nkh;a++){
        int kh = ph ? a*2 : 1;
        int rtap = (ph && a==0) ? 1 : 0;
        for (int cc=0;cc<nkw;cc++){
          int kw = pw ? cc*2 : 1;
          int shift = (pw && cc==0) ? 1 : 0;
          int tap = kh*3+kw;
          u32 abase = aSm + rtap*ROWB + (wid*16 + shift + laneRow)*144 + laneCol;
          #pragma unroll
          for (int kt=0;kt<4;kt++){
            u32 a0,a1,a2,a3;
            asm volatile("ldmatrix.sync.aligned.m8n8.x4.shared.b16 {%0,%1,%2,%3}, [%4];"
                         : "=r"(a0),"=r"(a1),"=r"(a2),"=r"(a3)
                         : "r"(abase + kt*32));
            #pragma unroll
            for (int ntv=0;ntv<4;ntv++){
              uint2 bv = *(const uint2*)&g_wfrag[((tap*4+kt)*4+ntv)*64 + lane*2];
              asm volatile("mma.sync.aligned.m16n8k16.row.col.f32.bf16.bf16.f32 "
                           "{%0,%1,%2,%3}, {%4,%5,%6,%7}, {%8,%9}, {%0,%1,%2,%3};"
                           : "+f"(c[ntv][0]),"+f"(c[ntv][1]),"+f"(c[ntv][2]),"+f"(c[ntv][3])
                           : "r"(a0),"r"(a1),"r"(a2),"r"(a3),"r"(bv.x),"r"(bv.y));
            }
          }
        }
      }
      int ho = 2*hb+ph;
      int wbA = wb0 + wid*16 + g, wbB = wbA + 8;
      unsigned short* rowBase = g_d2h + ((size_t)(b*256+ho))*256*32;
      unsigned short* pA = rowBase + (size_t)(2*wbA+pw)*32 + 2*tig;
      unsigned short* pB = rowBase + (size_t)(2*wbB+pw)*32 + 2*tig;
      #pragma unroll
      for (int ntv=0;ntv<4;ntv++){
        *(u32*)(pA + ntv*8) = bfpack(fmaxf(c[ntv][0],0.f), fmaxf(c[ntv][1],0.f));
        *(u32*)(pB + ntv*8) = bfpack(fmaxf(c[ntv][2],0.f), fmaxf(c[ntv][3],0.f));
      }
    }
  }
}

// ------------- dec3: conv 32->3 via mma, 4 output rows/block + fused MSE ----
__global__ __launch_bounds__(128) void dec3_mma_k(const float* __restrict__ x,
                                                  const float* __restrict__ bias){
  constexpr int PXB = 80;
  __shared__ __align__(16) unsigned char As[6*66*PXB];   // 6 rows x 66 px
  __shared__ float bias_s[3];
  int tid = threadIdx.x, bx = blockIdx.x;
  int wchunk = bx & 3, hrow = (bx>>2)&63, b = bx>>8;
  int wb0 = wchunk*64;
  int ho0 = hrow*4;
  if (tid<3) bias_s[tid]=bias[tid];
  for (int i=tid;i<6*66*4;i+=128){
    int r=i/264, rem=i%264, px=rem>>2, q=rem&3;
    int hi=ho0-1+r, wi=wb0-1+px;
    uint4 v=make_uint4(0,0,0,0);
    if ((unsigned)hi<256u && (unsigned)wi<256u)
      v=*(const uint4*)&g_d2h[(((size_t)(b*256+hi))*256+wi)*32 + q*8];
    *(uint4*)&As[(r*66+px)*PXB + q*16]=v;
  }
  __syncthreads();
  u32 aSm=smem_u32(As);
  int lane=tid&31, wid=tid>>5;
  int g=lane>>2, tig=lane&3;
  u32 laneRow=(u32)(lane&15);
  u32 laneCol=(lane&16)?16u:0u;
  int co0 = 2*tig, co1 = co0+1;
  float ls = 0.f;
  for (int r=0;r<4;r++){
    float c[4]={0.f,0.f,0.f,0.f};
    #pragma unroll
    for (int kh=0;kh<3;kh++){
      #pragma unroll
      for (int kw=0;kw<3;kw++){
        int tap=kh*3+kw;
        u32 abase = aSm + (u32)((r+kh)*66 + wid*16 + kw + laneRow)*PXB + laneCol;
        #pragma unroll
        for (int kt=0;kt<2;kt++){
          u32 a0,a1,a2,a3;
          asm volatile("ldmatrix.sync.aligned.m8n8.x4.shared.b16 {%0,%1,%2,%3}, [%4];"
                       : "=r"(a0),"=r"(a1),"=r"(a2),"=r"(a3) : "r"(abase + kt*32));
          uint2 bv = *(const uint2*)&g_wfragd3[(tap*2+kt)*64 + lane*2];
          asm volatile("mma.sync.aligned.m16n8k16.row.col.f32.bf16.bf16.f32 "
                       "{%0,%1,%2,%3}, {%4,%5,%6,%7}, {%8,%9}, {%0,%1,%2,%3};"
                       : "+f"(c[0]),"+f"(c[1]),"+f"(c[2]),"+f"(c[3])
                       : "r"(a0),"r"(a1),"r"(a2),"r"(a3),"r"(bv.x),"r"(bv.y));
        }
      }
    }
    int ho = ho0 + r;
    int pxA = wb0 + wid*16 + g, pxB = pxA + 8;
    const float* xb = x + (size_t)b*3*65536 + ho*256;
    if (co0 < 3){
      float d0 = c[0] + bias_s[co0] - xb[(size_t)co0*65536 + pxA];
      float d1 = c[2] + bias_s[co0] - xb[(size_t)co0*65536 + pxB];
      ls = fmaf(d0,d0, fmaf(d1,d1, ls));
    }
    if (co1 < 3){
      float d0 = c[1] + bias_s[co1] - xb[(size_t)co1*65536 + pxA];
      float d1 = c[3] + bias_s[co1] - xb[(size_t)co1*65536 + pxB];
      ls = fmaf(d0,d0, fmaf(d1,d1, ls));
    }
  }
  float s = blockReduceSum(ls);
  if (tid==0) atomicAdd(&g_acc[1], (double)s);
}

// ------------- finalize -----------------------------------------------------
__global__ void final_k(float* __restrict__ out){
  double vq  = g_acc[0];
  double rec = g_acc[1];
  float e_q  = (float)(1.25 * vq / 4194304.0);
  float mse  = (float)(rec / 12582912.0);
  out[0] = e_q;
  out[1] = mse;
  out[2] = mse;
}

// ---------------- launch ----------------------------------------------------
extern "C" void kernel_launch(void* const* d_in, const int* in_sizes, int n_in,
                              void* d_out, int out_size){
  const float* x   = (const float*)d_in[0];
  const float* ew1 = (const float*)d_in[1];
  const float* eb1 = (const float*)d_in[2];
  const float* ew2 = (const float*)d_in[3];
  const float* eb2 = (const float*)d_in[4];
  const float* ew3 = (const float*)d_in[5];
  const float* eb3 = (const float*)d_in[6];
  const float* cb  = (const float*)d_in[7];
  const float* dw1 = (const float*)d_in[8];
  const float* db1 = (const float*)d_in[9];
  const float* dw2 = (const float*)d_in[10];
  const float* db2 = (const float*)d_in[11];
  const float* dw3 = (const float*)d_in[12];
  const float* db3 = (const float*)d_in[13];
  float* out = (float*)d_out;

  repack_k<<<64,256>>>(ew1, ew2, dw1, dw2, dw3, ew3, cb);
  enc1_mma_k<<<16384,128>>>(x, eb1);
  enc2_mma_k<<<4096,128>>>(eb2);
  vq_mma_k<<<4096,128>>>(cb, eb3);
  dec1m_k<<<4096,128>>>(db1);
  dec2m_k<<<16384,128>>>(db2);
  dec3_mma_k<<<16384,128>>>(x, db3);
  final_k<<<1,1>>>(out);
}